// round 1
// baseline (speedup 1.0000x reference)
#include <cuda_runtime.h>
#include <math.h>

#define N0 4096
#define EDG 131072

// ---------------- device scratch (static, no allocation) ----------------
__device__ float dA0[(size_t)N0 * N0];     // original dense adjacency (preserved)
__device__ float dCbuf[(size_t)N0 * N0];   // augment result scratch
__device__ float dA1[2048 * 2048];
__device__ float dA2[1024 * 1024];
__device__ float dA3[512 * 512];
__device__ float dA4[256 * 256];
__device__ float dxs0[4096 * 32];
__device__ float dxs1[2048 * 64];
__device__ float dxs2[1024 * 128];
__device__ float dxs3[512 * 256];
__device__ float dxa[4096 * 512];
__device__ float dxb[4096 * 512];
__device__ float dybuf[4096 * 512];
__device__ float dzbuf[4096 * 512];
__device__ float ddinv[4096];
__device__ float dselfc[4096];
__device__ float dscorev[4096];
__device__ float dvalsv[2048];
__device__ int dperm0[2048];
__device__ int dperm1[1024];
__device__ int dperm2[512];
__device__ int dperm3[256];

// ---------------- kernels ----------------

__global__ void k_edges(const int* __restrict__ ei, float* __restrict__ A) {
    int e = blockIdx.x * blockDim.x + threadIdx.x;
    if (e < EDG) {
        int s = ei[e];
        int d = ei[EDG + e];
        atomicAdd(&A[(size_t)d * N0 + s], 1.0f);
    }
}

// deg_i = rowsum(A) + fill_i, fill_i = 2 if diag==0 else 0
// dinv = 1/sqrt(deg); selfc = dinv^2 * fill
__global__ void k_deg(const float* __restrict__ A, int n,
                      float* __restrict__ dinv, float* __restrict__ selfc) {
    int row = blockIdx.x;
    __shared__ float sh[256];
    const float* ar = A + (size_t)row * n;
    float s = 0.f;
    for (int j = threadIdx.x; j < n; j += 256) s += ar[j];
    sh[threadIdx.x] = s;
    __syncthreads();
    for (int o = 128; o > 0; o >>= 1) {
        if (threadIdx.x < o) sh[threadIdx.x] += sh[threadIdx.x + o];
        __syncthreads();
    }
    if (threadIdx.x == 0) {
        float diag = ar[row];
        float fill = (diag == 0.0f) ? 2.0f : 0.0f;
        float deg = sh[0] + fill;
        float di = (deg > 0.f) ? (1.0f / sqrtf(deg)) : 0.f;
        dinv[row] = di;
        selfc[row] = di * di * fill;
    }
}

// Y = X @ W ; Z = dinv_row * Y
__global__ void k_xw(const float* __restrict__ X, const float* __restrict__ W,
                     const float* __restrict__ dinv,
                     float* __restrict__ Y, float* __restrict__ Z,
                     int n, int cin, int cout) {
    int j = blockIdx.x * 32 + threadIdx.x;
    int i = blockIdx.y * 8 + threadIdx.y;
    if (i >= n || j >= cout) return;
    const float* xr = X + (size_t)i * cin;
    float acc = 0.f;
    for (int k = 0; k < cin; k++) acc = fmaf(xr[k], W[(size_t)k * cout + j], acc);
    Y[(size_t)i * cout + j] = acc;
    Z[(size_t)i * cout + j] = acc * dinv[i];
}

// O = relu?( dinv_i * (A@Z)_ij + selfc_i * Y_ij + b_j )
// BM=64, BN=32, BK=32, 256 threads, 8 rows per thread
__global__ __launch_bounds__(256) void k_gcnmm(
    const float* __restrict__ A, const float* __restrict__ Z,
    const float* __restrict__ Y, const float* __restrict__ dinv,
    const float* __restrict__ selfc, const float* __restrict__ bias,
    float* __restrict__ O, int n, int c, int dorelu) {
    __shared__ float As[32][65];
    __shared__ float Zs[32][32];
    int tid = threadIdx.x;
    int m0 = blockIdx.y * 64;
    int n0c = blockIdx.x * 32;
    int r0 = tid >> 5;      // 0..7
    int colt = tid & 31;    // 0..31
    float acc[8] = {0, 0, 0, 0, 0, 0, 0, 0};

    for (int k0 = 0; k0 < n; k0 += 32) {
        // A tile 64x32 (transposed store)
#pragma unroll
        for (int l = 0; l < 2; l++) {
            int e = tid + 256 * l;
            int row = e >> 3;
            int qc = (e & 7) * 4;
            float4 v = *reinterpret_cast<const float4*>(A + (size_t)(m0 + row) * n + k0 + qc);
            As[qc + 0][row] = v.x;
            As[qc + 1][row] = v.y;
            As[qc + 2][row] = v.z;
            As[qc + 3][row] = v.w;
        }
        // Z tile 32x32 (col-guarded)
        {
            int row = tid >> 3;
            int qc = (tid & 7) * 4;
            int gk = k0 + row;
#pragma unroll
            for (int u = 0; u < 4; u++) {
                int gc = n0c + qc + u;
                Zs[row][qc + u] = (gc < c) ? Z[(size_t)gk * c + gc] : 0.f;
            }
        }
        __syncthreads();
#pragma unroll
        for (int k = 0; k < 32; k++) {
            float zv = Zs[k][colt];
#pragma unroll
            for (int u = 0; u < 8; u++) acc[u] = fmaf(As[k][r0 + 8 * u], zv, acc[u]);
        }
        __syncthreads();
    }
    int gc = n0c + colt;
    if (gc < c) {
        float b = bias[gc];
#pragma unroll
        for (int u = 0; u < 8; u++) {
            int gi = m0 + r0 + 8 * u;
            float o = dinv[gi] * acc[u] + selfc[gi] * Y[(size_t)gi * c + gc] + b;
            if (dorelu) o = fmaxf(o, 0.f);
            O[(size_t)gi * c + gc] = o;
        }
    }
}

// C = B@B where B = A with diag forced to 1.  n multiple of 128.
// 128x128x8 tiling, 256 threads, 8x8 microtile.
__global__ __launch_bounds__(256) void k_auggemm(const float* __restrict__ A,
                                                 float* __restrict__ C, int n) {
    __shared__ float As[8][128];
    __shared__ float Bs[8][128];
    int tid = threadIdx.x;
    int m0 = blockIdx.y * 128;
    int n0c = blockIdx.x * 128;
    int tr = (tid >> 4) * 8;
    int tc = (tid & 15) * 8;
    float acc[8][8] = {};

    for (int k0 = 0; k0 < n; k0 += 8) {
        // A tile: 128 rows x 8 k, transposed store
        {
            int m = tid >> 1;
            int kq = (tid & 1) * 4;
            int gm = m0 + m;
            int gk0 = k0 + kq;
            float4 v = *reinterpret_cast<const float4*>(A + (size_t)gm * n + gk0);
            float vv[4] = {v.x, v.y, v.z, v.w};
#pragma unroll
            for (int u = 0; u < 4; u++) {
                if (gm == gk0 + u) vv[u] = 1.0f;
                As[kq + u][m] = vv[u];
            }
        }
        // B tile: 8 k-rows x 128 cols
        {
            int kk = tid >> 5;
            int cq = (tid & 31) * 4;
            int gk = k0 + kk;
            int gc0 = n0c + cq;
            float4 v = *reinterpret_cast<const float4*>(A + (size_t)gk * n + gc0);
            if (gk >= gc0 && gk < gc0 + 4) {
                float vv[4] = {v.x, v.y, v.z, v.w};
                vv[gk - gc0] = 1.0f;
                v.x = vv[0]; v.y = vv[1]; v.z = vv[2]; v.w = vv[3];
            }
            *reinterpret_cast<float4*>(&Bs[kk][cq]) = v;
        }
        __syncthreads();
#pragma unroll
        for (int k = 0; k < 8; k++) {
            float ra[8], rb[8];
            *reinterpret_cast<float4*>(ra)     = *reinterpret_cast<const float4*>(&As[k][tr]);
            *reinterpret_cast<float4*>(ra + 4) = *reinterpret_cast<const float4*>(&As[k][tr + 4]);
            *reinterpret_cast<float4*>(rb)     = *reinterpret_cast<const float4*>(&Bs[k][tc]);
            *reinterpret_cast<float4*>(rb + 4) = *reinterpret_cast<const float4*>(&Bs[k][tc + 4]);
#pragma unroll
            for (int i = 0; i < 8; i++)
#pragma unroll
                for (int j = 0; j < 8; j++) acc[i][j] = fmaf(ra[i], rb[j], acc[i][j]);
        }
        __syncthreads();
    }
#pragma unroll
    for (int i = 0; i < 8; i++) {
        int gm = m0 + tr + i;
#pragma unroll
        for (int j = 0; j < 8; j += 4) {
            float4 v = {acc[i][j], acc[i][j + 1], acc[i][j + 2], acc[i][j + 3]};
            *reinterpret_cast<float4*>(C + (size_t)gm * n + n0c + tc + j) = v;
        }
    }
}

// score_i = tanh( (x_i . w) / ||w|| )
__global__ void k_score(const float* __restrict__ X, const float* __restrict__ w,
                        int n, int c, float* __restrict__ score) {
    int row = blockIdx.x;
    __shared__ float sh[128];
    const float* xr = X + (size_t)row * c;
    float wsq = 0.f, dot = 0.f;
    for (int k = threadIdx.x; k < c; k += 128) {
        float wv = w[k];
        wsq += wv * wv;
        dot += xr[k] * wv;
    }
    sh[threadIdx.x] = wsq;
    __syncthreads();
    for (int o = 64; o > 0; o >>= 1) {
        if (threadIdx.x < o) sh[threadIdx.x] += sh[threadIdx.x + o];
        __syncthreads();
    }
    float wn = sh[0];
    __syncthreads();
    sh[threadIdx.x] = dot;
    __syncthreads();
    for (int o = 64; o > 0; o >>= 1) {
        if (threadIdx.x < o) sh[threadIdx.x] += sh[threadIdx.x + o];
        __syncthreads();
    }
    if (threadIdx.x == 0) score[row] = tanhf(sh[0] / sqrtf(wn));
}

// stable descending rank selection (== jax.lax.top_k ordering)
__global__ void k_rank(const float* __restrict__ score, int n, int k,
                       int* __restrict__ perm, float* __restrict__ vals) {
    int i = blockIdx.x * 256 + threadIdx.x;
    if (i >= n) return;
    float si = score[i];
    int rank = 0;
    for (int j = 0; j < n; j++) {
        float sj = score[j];
        rank += (sj > si) || (sj == si && j < i);
    }
    if (rank < k) {
        perm[rank] = i;
        vals[rank] = si;
    }
}

__global__ void k_gatherx(const float* __restrict__ X, int c,
                          const int* __restrict__ perm, const float* __restrict__ vals,
                          int k, float* __restrict__ O) {
    int t = blockIdx.x * 256 + threadIdx.x;
    if (t >= k * c) return;
    int r = t / c, j = t % c;
    O[t] = X[(size_t)perm[r] * c + j] * vals[r];
}

// O[r,cc] = (r==cc)?0 : C[perm_r, perm_cc]  (folds augment's diag-zeroing)
__global__ void k_gathera(const float* __restrict__ C, int n,
                          const int* __restrict__ perm, int k, float* __restrict__ O) {
    int cc = blockIdx.x * 256 + threadIdx.x;
    int r = blockIdx.y;
    if (cc >= k) return;
    O[(size_t)r * k + cc] = (r == cc) ? 0.f : C[(size_t)perm[r] * n + perm[cc]];
}

__global__ void k_concat(const float* __restrict__ R, int n, int c, float* __restrict__ O) {
    int t = blockIdx.x * 256 + threadIdx.x;
    int tot = n * 2 * c;
    if (t >= tot) return;
    int i = t / (2 * c), j = t % (2 * c);
    O[t] = (j < c) ? R[(size_t)i * c + j] : 0.f;
}

__global__ void k_scatter(float* __restrict__ O, int ostride, int off,
                          const int* __restrict__ perm, int k,
                          const float* __restrict__ S, int sstride, int nc) {
    int t = blockIdx.x * 256 + threadIdx.x;
    if (t >= k * nc) return;
    int r = t / nc, j = t % nc;
    O[(size_t)perm[r] * ostride + off + j] = S[(size_t)r * sstride + j];
}

__global__ void k_softmax(const float* __restrict__ X, float* __restrict__ O, int n, int c) {
    int i = blockIdx.x * 256 + threadIdx.x;
    if (i >= n) return;
    const float* xr = X + (size_t)i * c;
    float m = -1e30f;
    for (int j = 0; j < c; j++) m = fmaxf(m, xr[j]);
    float s = 0.f;
    for (int j = 0; j < c; j++) s += expf(xr[j] - m);
    float inv = 1.0f / s;
    for (int j = 0; j < c; j++) O[(size_t)i * c + j] = expf(xr[j] - m) * inv;
}

// ---------------- host orchestration ----------------

static void gcn_call(const float* A, int n, const float* xin, int cin,
                     const float* W, const float* b, int cout, bool relu, float* out,
                     float* dinv, float* selfc, float* y, float* z) {
    k_deg<<<n, 256>>>(A, n, dinv, selfc);
    dim3 bx(32, 8);
    dim3 gx((cout + 31) / 32, (n + 7) / 8);
    k_xw<<<gx, bx>>>(xin, W, dinv, y, z, n, cin, cout);
    dim3 g2((cout + 31) / 32, n / 64);
    k_gcnmm<<<g2, 256>>>(A, z, y, dinv, selfc, b, out, n, cout, relu ? 1 : 0);
}

extern "C" void kernel_launch(void* const* d_in, const int* in_sizes, int n_in,
                              void* d_out, int out_size) {
    const float* x = (const float*)d_in[0];
    const int* ei = (const int*)d_in[1];
    const float *Wd[5], *bd[5], *p[4], *Wu[4], *bu[4];
    for (int i = 0; i < 5; i++) { Wd[i] = (const float*)d_in[2 + 2 * i]; bd[i] = (const float*)d_in[3 + 2 * i]; }
    for (int i = 0; i < 4; i++) p[i] = (const float*)d_in[12 + i];
    for (int i = 0; i < 4; i++) { Wu[i] = (const float*)d_in[16 + 2 * i]; bu[i] = (const float*)d_in[17 + 2 * i]; }
    const float* Wo = (const float*)d_in[24];
    const float* bo = (const float*)d_in[25];

    float *A0, *C, *A1, *A2, *A3, *A4, *xs0, *xs1, *xs2, *xs3, *xa, *xb, *y, *z;
    float *dinv, *selfc, *score, *vals;
    int *pm0, *pm1, *pm2, *pm3;
    cudaGetSymbolAddress((void**)&A0, dA0);
    cudaGetSymbolAddress((void**)&C, dCbuf);
    cudaGetSymbolAddress((void**)&A1, dA1);
    cudaGetSymbolAddress((void**)&A2, dA2);
    cudaGetSymbolAddress((void**)&A3, dA3);
    cudaGetSymbolAddress((void**)&A4, dA4);
    cudaGetSymbolAddress((void**)&xs0, dxs0);
    cudaGetSymbolAddress((void**)&xs1, dxs1);
    cudaGetSymbolAddress((void**)&xs2, dxs2);
    cudaGetSymbolAddress((void**)&xs3, dxs3);
    cudaGetSymbolAddress((void**)&xa, dxa);
    cudaGetSymbolAddress((void**)&xb, dxb);
    cudaGetSymbolAddress((void**)&y, dybuf);
    cudaGetSymbolAddress((void**)&z, dzbuf);
    cudaGetSymbolAddress((void**)&dinv, ddinv);
    cudaGetSymbolAddress((void**)&selfc, dselfc);
    cudaGetSymbolAddress((void**)&score, dscorev);
    cudaGetSymbolAddress((void**)&vals, dvalsv);
    cudaGetSymbolAddress((void**)&pm0, dperm0);
    cudaGetSymbolAddress((void**)&pm1, dperm1);
    cudaGetSymbolAddress((void**)&pm2, dperm2);
    cudaGetSymbolAddress((void**)&pm3, dperm3);

    // build adjacency
    cudaMemsetAsync(A0, 0, (size_t)N0 * N0 * sizeof(float));
    k_edges<<<EDG / 256, 256>>>(ei, A0);

    // GCN0: [4096,128] -> [4096,32], relu  (xs[0])
    gcn_call(A0, 4096, x, 128, Wd[0], bd[0], 32, true, xs0, dinv, selfc, y, z);

    // ---- level 1 ----
    k_auggemm<<<dim3(32, 32), 256>>>(A0, C, 4096);
    k_score<<<4096, 128>>>(xs0, p[0], 4096, 32, score);
    k_rank<<<16, 256>>>(score, 4096, 2048, pm0, vals);
    k_gatherx<<<(2048 * 32 + 255) / 256, 256>>>(xs0, 32, pm0, vals, 2048, xa);
    k_gathera<<<dim3(8, 2048), 256>>>(C, 4096, pm0, 2048, A1);
    gcn_call(A1, 2048, xa, 32, Wd[1], bd[1], 64, true, xs1, dinv, selfc, y, z);

    // ---- level 2 ----
    k_auggemm<<<dim3(16, 16), 256>>>(A1, C, 2048);
    k_score<<<2048, 128>>>(xs1, p[1], 2048, 64, score);
    k_rank<<<8, 256>>>(score, 2048, 1024, pm1, vals);
    k_gatherx<<<(1024 * 64 + 255) / 256, 256>>>(xs1, 64, pm1, vals, 1024, xa);
    k_gathera<<<dim3(4, 1024), 256>>>(C, 2048, pm1, 1024, A2);
    gcn_call(A2, 1024, xa, 64, Wd[2], bd[2], 128, true, xs2, dinv, selfc, y, z);

    // ---- level 3 ----
    k_auggemm<<<dim3(8, 8), 256>>>(A2, C, 1024);
    k_score<<<1024, 128>>>(xs2, p[2], 1024, 128, score);
    k_rank<<<4, 256>>>(score, 1024, 512, pm2, vals);
    k_gatherx<<<(512 * 128 + 255) / 256, 256>>>(xs2, 128, pm2, vals, 512, xa);
    k_gathera<<<dim3(2, 512), 256>>>(C, 1024, pm2, 512, A3);
    gcn_call(A3, 512, xa, 128, Wd[3], bd[3], 256, true, xs3, dinv, selfc, y, z);

    // ---- level 4 ----
    k_auggemm<<<dim3(4, 4), 256>>>(A3, C, 512);
    k_score<<<512, 128>>>(xs3, p[3], 512, 256, score);
    k_rank<<<2, 256>>>(score, 512, 256, pm3, vals);
    k_gatherx<<<(256 * 256 + 255) / 256, 256>>>(xs3, 256, pm3, vals, 256, xa);
    k_gathera<<<dim3(1, 256), 256>>>(C, 512, pm3, 256, A4);
    gcn_call(A4, 256, xa, 256, Wd[4], bd[4], 512, true, xb, dinv, selfc, y, z);
    // xcur = xb [256,512]

    // ---- up 0 : res = xs3 [512,256], perm3 ----
    k_concat<<<(512 * 512 + 255) / 256, 256>>>(xs3, 512, 256, xa);
    k_scatter<<<(256 * 256 + 255) / 256, 256>>>(xa, 512, 256, pm3, 256, xb, 512, 256);
    gcn_call(A3, 512, xa, 512, Wu[0], bu[0], 256, true, xb, dinv, selfc, y, z);

    // ---- up 1 : res = xs2 [1024,128], perm2 ----
    k_concat<<<(1024 * 256 + 255) / 256, 256>>>(xs2, 1024, 128, xa);
    k_scatter<<<(512 * 128 + 255) / 256, 256>>>(xa, 256, 128, pm2, 512, xb, 256, 128);
    gcn_call(A2, 1024, xa, 256, Wu[1], bu[1], 128, true, xb, dinv, selfc, y, z);

    // ---- up 2 : res = xs1 [2048,64], perm1 ----
    k_concat<<<(2048 * 128 + 255) / 256, 256>>>(xs1, 2048, 64, xa);
    k_scatter<<<(1024 * 64 + 255) / 256, 256>>>(xa, 128, 64, pm1, 1024, xb, 128, 64);
    gcn_call(A1, 2048, xa, 128, Wu[2], bu[2], 64, true, xb, dinv, selfc, y, z);

    // ---- up 3 : res = xs0 [4096,32], perm0, NO relu ----
    k_concat<<<(4096 * 64 + 255) / 256, 256>>>(xs0, 4096, 32, xa);
    k_scatter<<<(2048 * 32 + 255) / 256, 256>>>(xa, 64, 32, pm0, 2048, xb, 64, 32);
    gcn_call(A0, 4096, xa, 64, Wu[3], bu[3], 32, false, xb, dinv, selfc, y, z);

    // ---- final GCN + softmax ----
    gcn_call(A0, 4096, xb, 32, Wo, bo, 37, false, xa, dinv, selfc, y, z);
    k_softmax<<<16, 256>>>(xa, (float*)d_out, 4096, 37);
}

// round 2
// speedup vs baseline: 4.4649x; 4.4649x over previous
#include <cuda_runtime.h>
#include <cuda_bf16.h>
#include <mma.h>
#include <math.h>

using namespace nvcuda;

#define N0 4096
#define EDG 131072

// ---------------- device scratch (static, no allocation) ----------------
__device__ float dA0[(size_t)N0 * N0];
__device__ float dA1[2048 * 2048];
__device__ float dA2[1024 * 1024];
__device__ float dA3[512 * 512];
__device__ float dA4[256 * 256];
__device__ __nv_bfloat16 dBr[2048 * 4096];
__device__ __nv_bfloat16 dBc[4096 * 2048];
__device__ float dBrf[512 * 1024];
__device__ float dBcf[1024 * 512];
__device__ float dP[8 * 4096 * 64];
__device__ float dxs0[4096 * 32];
__device__ float dxs1[2048 * 64];
__device__ float dxs2[1024 * 128];
__device__ float dxs3[512 * 256];
__device__ float dxa[4096 * 512];
__device__ float dxb[4096 * 512];
__device__ float dybuf[4096 * 512];
__device__ float dzbuf[4096 * 512];
__device__ float ddinv[4096];
__device__ float dselfc[4096];
__device__ float dscorev[4096];
__device__ float dvalsv[2048];
__device__ int dperm0[2048];
__device__ int dperm1[1024];
__device__ int dperm2[512];
__device__ int dperm3[256];

// ---------------- kernels ----------------

__global__ void k_edges(const int* __restrict__ ei, float* __restrict__ A) {
    int e = blockIdx.x * blockDim.x + threadIdx.x;
    if (e < EDG) {
        int s = ei[e];
        int d = ei[EDG + e];
        atomicAdd(&A[(size_t)d * N0 + s], 1.0f);
    }
}

__global__ void k_deg(const float* __restrict__ A, int n,
                      float* __restrict__ dinv, float* __restrict__ selfc) {
    int row = blockIdx.x;
    __shared__ float sh[256];
    const float* ar = A + (size_t)row * n;
    float s = 0.f;
    for (int j = threadIdx.x; j < n; j += 256) s += ar[j];
    sh[threadIdx.x] = s;
    __syncthreads();
    for (int o = 128; o > 0; o >>= 1) {
        if (threadIdx.x < o) sh[threadIdx.x] += sh[threadIdx.x + o];
        __syncthreads();
    }
    if (threadIdx.x == 0) {
        float diag = ar[row];
        float fill = (diag == 0.0f) ? 2.0f : 0.0f;
        float deg = sh[0] + fill;
        float di = (deg > 0.f) ? (1.0f / sqrtf(deg)) : 0.f;
        dinv[row] = di;
        selfc[row] = di * di * fill;
    }
}

// Y = X @ W ; Z = dinv_row * Y
__global__ void k_xw(const float* __restrict__ X, const float* __restrict__ W,
                     const float* __restrict__ dinv,
                     float* __restrict__ Y, float* __restrict__ Z,
                     int n, int cin, int cout) {
    int j = blockIdx.x * 32 + threadIdx.x;
    int i = blockIdx.y * 8 + threadIdx.y;
    if (i >= n || j >= cout) return;
    const float* xr = X + (size_t)i * cin;
    float acc = 0.f;
    for (int k = 0; k < cin; k++) acc = fmaf(xr[k], W[(size_t)k * cout + j], acc);
    Y[(size_t)i * cout + j] = acc;
    Z[(size_t)i * cout + j] = acc * dinv[i];
}

// split-K partial: P[ks][i][c] = (A[:, kchunk] @ Z[kchunk, :])
__global__ __launch_bounds__(256) void k_gcnmm_sp(
    const float* __restrict__ A, const float* __restrict__ Z,
    float* __restrict__ P, int n, int c, int KS) {
    __shared__ float As[32][65];
    __shared__ float Zs[32][32];
    int tid = threadIdx.x;
    int m0 = blockIdx.y * 64;
    int n0c = blockIdx.x * 32;
    int ks = blockIdx.z;
    int chunk = n / KS;
    int kbeg = ks * chunk;
    int kend = kbeg + chunk;
    int r0 = tid >> 5;
    int colt = tid & 31;
    float acc[8] = {0, 0, 0, 0, 0, 0, 0, 0};

    for (int k0 = kbeg; k0 < kend; k0 += 32) {
#pragma unroll
        for (int l = 0; l < 2; l++) {
            int e = tid + 256 * l;
            int row = e >> 3;
            int qc = (e & 7) * 4;
            float4 v = *reinterpret_cast<const float4*>(A + (size_t)(m0 + row) * n + k0 + qc);
            As[qc + 0][row] = v.x;
            As[qc + 1][row] = v.y;
            As[qc + 2][row] = v.z;
            As[qc + 3][row] = v.w;
        }
        {
            int row = tid >> 3;
            int qc = (tid & 7) * 4;
            int gk = k0 + row;
#pragma unroll
            for (int u = 0; u < 4; u++) {
                int gc = n0c + qc + u;
                Zs[row][qc + u] = (gc < c) ? Z[(size_t)gk * c + gc] : 0.f;
            }
        }
        __syncthreads();
#pragma unroll
        for (int k = 0; k < 32; k++) {
            float zv = Zs[k][colt];
#pragma unroll
            for (int u = 0; u < 8; u++) acc[u] = fmaf(As[k][r0 + 8 * u], zv, acc[u]);
        }
        __syncthreads();
    }
    int gc = n0c + colt;
    if (gc < c) {
#pragma unroll
        for (int u = 0; u < 8; u++) {
            int gi = m0 + r0 + 8 * u;
            P[((size_t)ks * n + gi) * c + gc] = acc[u];
        }
    }
}

// out = relu?( dinv_i * sum_ks P + selfc_i * Y + b )
__global__ void k_gcn_epi(const float* __restrict__ P, const float* __restrict__ Y,
                          const float* __restrict__ dinv, const float* __restrict__ selfc,
                          const float* __restrict__ bias, float* __restrict__ O,
                          int n, int c, int KS, int dorelu) {
    int t = blockIdx.x * 256 + threadIdx.x;
    if (t >= n * c) return;
    int i = t / c, j = t % c;
    float s = 0.f;
    size_t stride = (size_t)n * c;
    for (int ks = 0; ks < KS; ks++) s += P[ks * stride + t];
    float o = dinv[i] * s + selfc[i] * Y[t] + bias[j];
    if (dorelu) o = fmaxf(o, 0.f);
    O[t] = o;
}

// Br[r][k] = (perm_r==k) ? 1 : A[perm_r][k]   (bf16, row gather, coalesced)
__global__ void k_grow_bf16(const float* __restrict__ A, int n,
                            const int* __restrict__ perm, int ksel,
                            __nv_bfloat16* __restrict__ Br) {
    size_t t = (size_t)blockIdx.x * 256 + threadIdx.x;
    size_t tot = (size_t)ksel * (n / 4);
    if (t >= tot) return;
    int r = t / (n / 4);
    int k4 = (t % (n / 4)) * 4;
    int pr = perm[r];
    float4 v = *reinterpret_cast<const float4*>(A + (size_t)pr * n + k4);
    float vv[4] = {v.x, v.y, v.z, v.w};
#pragma unroll
    for (int u = 0; u < 4; u++)
        if (k4 + u == pr) vv[u] = 1.0f;
    __nv_bfloat162* dst = reinterpret_cast<__nv_bfloat162*>(Br + (size_t)r * n + k4);
    dst[0] = __floats2bfloat162_rn(vv[0], vv[1]);
    dst[1] = __floats2bfloat162_rn(vv[2], vv[3]);
}

// Bc[k][c] = (k==perm_c) ? 1 : A[k][perm_c]   (bf16, col gather)
__global__ void k_gcol_bf16(const float* __restrict__ A, int n,
                            const int* __restrict__ perm, int ksel,
                            __nv_bfloat16* __restrict__ Bc) {
    size_t t = (size_t)blockIdx.x * 256 + threadIdx.x;
    if (t >= (size_t)n * ksel) return;
    int k = t / ksel;
    int c = t % ksel;
    int pc = perm[c];
    float v = (k == pc) ? 1.0f : A[(size_t)k * n + pc];
    Bc[t] = __float2bfloat16(v);
}

__global__ void k_grow_f32(const float* __restrict__ A, int n,
                           const int* __restrict__ perm, int ksel,
                           float* __restrict__ Br) {
    size_t t = (size_t)blockIdx.x * 256 + threadIdx.x;
    if (t >= (size_t)ksel * n) return;
    int r = t / n;
    int k = t % n;
    int pr = perm[r];
    Br[t] = (k == pr) ? 1.0f : A[(size_t)pr * n + k];
}

__global__ void k_gcol_f32(const float* __restrict__ A, int n,
                           const int* __restrict__ perm, int ksel,
                           float* __restrict__ Bc) {
    size_t t = (size_t)blockIdx.x * 256 + threadIdx.x;
    if (t >= (size_t)n * ksel) return;
    int k = t / ksel;
    int c = t % ksel;
    int pc = perm[c];
    Bc[t] = (k == pc) ? 1.0f : A[(size_t)k * n + pc];
}

// C[M][Nn] = Br[M][K] @ Bc[K][Nn], bf16 inputs fp32 accum (exact for ints<=256)
// 128x128x32 tile, 8 warps (4x2), wmma 16x16x16
__global__ __launch_bounds__(256) void k_wmma(const __nv_bfloat16* __restrict__ Br,
                                              const __nv_bfloat16* __restrict__ Bc,
                                              float* __restrict__ C, int K, int Nn) {
    __shared__ __nv_bfloat16 As[128][48];
    __shared__ __nv_bfloat16 Bs[32][144];
    int tid = threadIdx.x;
    int warp = tid >> 5;
    int wm = warp >> 1;   // 0..3
    int wn = warp & 1;    // 0..1
    int m0 = blockIdx.y * 128;
    int n0 = blockIdx.x * 128;

    wmma::fragment<wmma::accumulator, 16, 16, 16, float> acc[2][4];
#pragma unroll
    for (int i = 0; i < 2; i++)
#pragma unroll
        for (int j = 0; j < 4; j++) wmma::fill_fragment(acc[i][j], 0.0f);

    for (int k0 = 0; k0 < K; k0 += 32) {
#pragma unroll
        for (int l = 0; l < 2; l++) {
            int idx = tid + 256 * l;
            int row = idx >> 2;
            int cg = (idx & 3) * 8;
            *reinterpret_cast<uint4*>(&As[row][cg]) =
                *reinterpret_cast<const uint4*>(Br + (size_t)(m0 + row) * K + k0 + cg);
        }
#pragma unroll
        for (int l = 0; l < 2; l++) {
            int idx = tid + 256 * l;
            int row = idx >> 4;
            int cg = (idx & 15) * 8;
            *reinterpret_cast<uint4*>(&Bs[row][cg]) =
                *reinterpret_cast<const uint4*>(Bc + (size_t)(k0 + row) * Nn + n0 + cg);
        }
        __syncthreads();
#pragma unroll
        for (int kk = 0; kk < 32; kk += 16) {
            wmma::fragment<wmma::matrix_a, 16, 16, 16, __nv_bfloat16, wmma::row_major> af[2];
            wmma::fragment<wmma::matrix_b, 16, 16, 16, __nv_bfloat16, wmma::row_major> bf[4];
#pragma unroll
            for (int i = 0; i < 2; i++)
                wmma::load_matrix_sync(af[i], &As[wm * 32 + 16 * i][kk], 48);
#pragma unroll
            for (int j = 0; j < 4; j++)
                wmma::load_matrix_sync(bf[j], &Bs[kk][wn * 64 + 16 * j], 144);
#pragma unroll
            for (int i = 0; i < 2; i++)
#pragma unroll
                for (int j = 0; j < 4; j++)
                    wmma::mma_sync(acc[i][j], af[i], bf[j], acc[i][j]);
        }
        __syncthreads();
    }
#pragma unroll
    for (int i = 0; i < 2; i++)
#pragma unroll
        for (int j = 0; j < 4; j++)
            wmma::store_matrix_sync(C + (size_t)(m0 + wm * 32 + 16 * i) * Nn + n0 + wn * 64 + 16 * j,
                                    acc[i][j], Nn, wmma::mem_row_major);
}

// fp32 SGEMM, 64x64x16 tile, for small levels
__global__ __launch_bounds__(256) void k_gemm64(const float* __restrict__ Br,
                                                const float* __restrict__ Bc,
                                                float* __restrict__ C, int K, int Nn) {
    __shared__ float As[16][65];
    __shared__ float Bs[16][65];
    int tid = threadIdx.x;
    int m0 = blockIdx.y * 64;
    int n0 = blockIdx.x * 64;
    int ty = tid >> 4, tx = tid & 15;
    float acc[4][4] = {};

    for (int k0 = 0; k0 < K; k0 += 16) {
#pragma unroll
        for (int l = 0; l < 4; l++) {
            int e = tid + 256 * l;
            int row = e >> 4;
            int kk = e & 15;
            As[kk][row] = Br[(size_t)(m0 + row) * K + k0 + kk];
        }
#pragma unroll
        for (int l = 0; l < 4; l++) {
            int e = tid + 256 * l;
            int row = e >> 6;
            int col = e & 63;
            Bs[row][col] = Bc[(size_t)(k0 + row) * Nn + n0 + col];
        }
        __syncthreads();
#pragma unroll
        for (int kk = 0; kk < 16; kk++) {
            float a[4], b[4];
#pragma unroll
            for (int i = 0; i < 4; i++) a[i] = As[kk][ty * 4 + i];
#pragma unroll
            for (int j = 0; j < 4; j++) b[j] = Bs[kk][tx * 4 + j];
#pragma unroll
            for (int i = 0; i < 4; i++)
#pragma unroll
                for (int j = 0; j < 4; j++) acc[i][j] = fmaf(a[i], b[j], acc[i][j]);
        }
        __syncthreads();
    }
#pragma unroll
    for (int i = 0; i < 4; i++)
#pragma unroll
        for (int j = 0; j < 4; j++)
            C[(size_t)(m0 + ty * 4 + i) * Nn + n0 + tx * 4 + j] = acc[i][j];
}

__global__ void k_zerodiag(float* __restrict__ C, int n) {
    int i = blockIdx.x * 256 + threadIdx.x;
    if (i < n) C[(size_t)i * n + i] = 0.f;
}

__global__ void k_score(const float* __restrict__ X, const float* __restrict__ w,
                        int n, int c, float* __restrict__ score) {
    int row = blockIdx.x;
    __shared__ float sh[128];
    const float* xr = X + (size_t)row * c;
    float wsq = 0.f, dot = 0.f;
    for (int k = threadIdx.x; k < c; k += 128) {
        float wv = w[k];
        wsq += wv * wv;
        dot += xr[k] * wv;
    }
    sh[threadIdx.x] = wsq;
    __syncthreads();
    for (int o = 64; o > 0; o >>= 1) {
        if (threadIdx.x < o) sh[threadIdx.x] += sh[threadIdx.x + o];
        __syncthreads();
    }
    float wn = sh[0];
    __syncthreads();
    sh[threadIdx.x] = dot;
    __syncthreads();
    for (int o = 64; o > 0; o >>= 1) {
        if (threadIdx.x < o) sh[threadIdx.x] += sh[threadIdx.x + o];
        __syncthreads();
    }
    if (threadIdx.x == 0) score[row] = tanhf(sh[0] / sqrtf(wn));
}

__global__ void k_rank(const float* __restrict__ score, int n, int k,
                       int* __restrict__ perm, float* __restrict__ vals) {
    int i = blockIdx.x * 256 + threadIdx.x;
    if (i >= n) return;
    float si = score[i];
    int rank = 0;
    for (int j = 0; j < n; j++) {
        float sj = score[j];
        rank += (sj > si) || (sj == si && j < i);
    }
    if (rank < k) {
        perm[rank] = i;
        vals[rank] = si;
    }
}

__global__ void k_gatherx(const float* __restrict__ X, int c,
                          const int* __restrict__ perm, const float* __restrict__ vals,
                          int k, float* __restrict__ O) {
    int t = blockIdx.x * 256 + threadIdx.x;
    if (t >= k * c) return;
    int r = t / c, j = t % c;
    O[t] = X[(size_t)perm[r] * c + j] * vals[r];
}

__global__ void k_concat(const float* __restrict__ R, int n, int c, float* __restrict__ O) {
    int t = blockIdx.x * 256 + threadIdx.x;
    int tot = n * 2 * c;
    if (t >= tot) return;
    int i = t / (2 * c), j = t % (2 * c);
    O[t] = (j < c) ? R[(size_t)i * c + j] : 0.f;
}

__global__ void k_scatter(float* __restrict__ O, int ostride, int off,
                          const int* __restrict__ perm, int k,
                          const float* __restrict__ S, int sstride, int nc) {
    int t = blockIdx.x * 256 + threadIdx.x;
    if (t >= k * nc) return;
    int r = t / nc, j = t % nc;
    O[(size_t)perm[r] * ostride + off + j] = S[(size_t)r * sstride + j];
}

__global__ void k_softmax(const float* __restrict__ X, float* __restrict__ O, int n, int c) {
    int i = blockIdx.x * 256 + threadIdx.x;
    if (i >= n) return;
    const float* xr = X + (size_t)i * c;
    float m = -1e30f;
    for (int j = 0; j < c; j++) m = fmaxf(m, xr[j]);
    float s = 0.f;
    for (int j = 0; j < c; j++) s += expf(xr[j] - m);
    float inv = 1.0f / s;
    for (int j = 0; j < c; j++) O[(size_t)i * c + j] = expf(xr[j] - m) * inv;
}

// ---------------- host orchestration ----------------

struct Bufs {
    float *dinv, *selfc, *y, *z, *P;
};

static void gcn_call(const float* A, int n, const float* xin, int cin,
                     const float* W, const float* b, int cout, bool relu, float* out,
                     const Bufs& B) {
    const int KS = 8;
    k_deg<<<n, 256>>>(A, n, B.dinv, B.selfc);
    dim3 bx(32, 8);
    dim3 gx((cout + 31) / 32, (n + 7) / 8);
    k_xw<<<gx, bx>>>(xin, W, B.dinv, B.y, B.z, n, cin, cout);
    dim3 g2((cout + 31) / 32, n / 64, KS);
    k_gcnmm_sp<<<g2, 256>>>(A, B.z, B.P, n, cout, KS);
    k_gcn_epi<<<(n * cout + 255) / 256, 256>>>(B.P, B.y, B.dinv, B.selfc, b, out,
                                               n, cout, KS, relu ? 1 : 0);
}

extern "C" void kernel_launch(void* const* d_in, const int* in_sizes, int n_in,
                              void* d_out, int out_size) {
    const float* x = (const float*)d_in[0];
    const int* ei = (const int*)d_in[1];
    const float *Wd[5], *bd[5], *p[4], *Wu[4], *bu[4];
    for (int i = 0; i < 5; i++) { Wd[i] = (const float*)d_in[2 + 2 * i]; bd[i] = (const float*)d_in[3 + 2 * i]; }
    for (int i = 0; i < 4; i++) p[i] = (const float*)d_in[12 + i];
    for (int i = 0; i < 4; i++) { Wu[i] = (const float*)d_in[16 + 2 * i]; bu[i] = (const float*)d_in[17 + 2 * i]; }
    const float* Wo = (const float*)d_in[24];
    const float* bo = (const float*)d_in[25];

    float *A0, *A1, *A2, *A3, *A4, *xs0, *xs1, *xs2, *xs3, *xa, *xb;
    float *Brf, *Bcf, *score, *vals;
    __nv_bfloat16 *Br, *Bc;
    int *pm0, *pm1, *pm2, *pm3;
    Bufs B;
    cudaGetSymbolAddress((void**)&A0, dA0);
    cudaGetSymbolAddress((void**)&A1, dA1);
    cudaGetSymbolAddress((void**)&A2, dA2);
    cudaGetSymbolAddress((void**)&A3, dA3);
    cudaGetSymbolAddress((void**)&A4, dA4);
    cudaGetSymbolAddress((void**)&Br, dBr);
    cudaGetSymbolAddress((void**)&Bc, dBc);
    cudaGetSymbolAddress((void**)&Brf, dBrf);
    cudaGetSymbolAddress((void**)&Bcf, dBcf);
    cudaGetSymbolAddress((void**)&B.P, dP);
    cudaGetSymbolAddress((void**)&xs0, dxs0);
    cudaGetSymbolAddress((void**)&xs1, dxs1);
    cudaGetSymbolAddress((void**)&xs2, dxs2);
    cudaGetSymbolAddress((void**)&xs3, dxs3);
    cudaGetSymbolAddress((void**)&xa, dxa);
    cudaGetSymbolAddress((void**)&xb, dxb);
    cudaGetSymbolAddress((void**)&B.y, dybuf);
    cudaGetSymbolAddress((void**)&B.z, dzbuf);
    cudaGetSymbolAddress((void**)&B.dinv, ddinv);
    cudaGetSymbolAddress((void**)&B.selfc, dselfc);
    cudaGetSymbolAddress((void**)&score, dscorev);
    cudaGetSymbolAddress((void**)&vals, dvalsv);
    cudaGetSymbolAddress((void**)&pm0, dperm0);
    cudaGetSymbolAddress((void**)&pm1, dperm1);
    cudaGetSymbolAddress((void**)&pm2, dperm2);
    cudaGetSymbolAddress((void**)&pm3, dperm3);

    // build adjacency
    cudaMemsetAsync(A0, 0, (size_t)N0 * N0 * sizeof(float));
    k_edges<<<EDG / 256, 256>>>(ei, A0);

    // GCN0: [4096,128] -> [4096,32], relu
    gcn_call(A0, 4096, x, 128, Wd[0], bd[0], 32, true, xs0, B);

    // ---- level 1 (bf16 TC, exact: integer entries) ----
    k_score<<<4096, 128>>>(xs0, p[0], 4096, 32, score);
    k_rank<<<16, 256>>>(score, 4096, 2048, pm0, vals);
    k_gatherx<<<(2048 * 32 + 255) / 256, 256>>>(xs0, 32, pm0, vals, 2048, xa);
    k_grow_bf16<<<(2048 * 1024 + 255) / 256, 256>>>(A0, 4096, pm0, 2048, Br);
    k_gcol_bf16<<<(4096 * 2048 + 255) / 256, 256>>>(A0, 4096, pm0, 2048, Bc);
    k_wmma<<<dim3(16, 16), 256>>>(Br, Bc, A1, 4096, 2048);
    k_zerodiag<<<8, 256>>>(A1, 2048);
    gcn_call(A1, 2048, xa, 32, Wd[1], bd[1], 64, true, xs1, B);

    // ---- level 2 (bf16 TC) ----
    k_score<<<2048, 128>>>(xs1, p[1], 2048, 64, score);
    k_rank<<<8, 256>>>(score, 2048, 1024, pm1, vals);
    k_gatherx<<<(1024 * 64 + 255) / 256, 256>>>(xs1, 64, pm1, vals, 1024, xa);
    k_grow_bf16<<<(1024 * 512 + 255) / 256, 256>>>(A1, 2048, pm1, 1024, Br);
    k_gcol_bf16<<<(2048 * 1024 + 255) / 256, 256>>>(A1, 2048, pm1, 1024, Bc);
    k_wmma<<<dim3(8, 8), 256>>>(Br, Bc, A2, 2048, 1024);
    k_zerodiag<<<4, 256>>>(A2, 1024);
    gcn_call(A2, 1024, xa, 64, Wd[2], bd[2], 128, true, xs2, B);

    // ---- level 3 (fp32) ----
    k_score<<<1024, 128>>>(xs2, p[2], 1024, 128, score);
    k_rank<<<4, 256>>>(score, 1024, 512, pm2, vals);
    k_gatherx<<<(512 * 128 + 255) / 256, 256>>>(xs2, 128, pm2, vals, 512, xa);
    k_grow_f32<<<(512 * 1024 + 255) / 256, 256>>>(A2, 1024, pm2, 512, Brf);
    k_gcol_f32<<<(1024 * 512 + 255) / 256, 256>>>(A2, 1024, pm2, 512, Bcf);
    k_gemm64<<<dim3(8, 8), 256>>>(Brf, Bcf, A3, 1024, 512);
    k_zerodiag<<<2, 256>>>(A3, 512);
    gcn_call(A3, 512, xa, 128, Wd[3], bd[3], 256, true, xs3, B);

    // ---- level 4 (fp32) ----
    k_score<<<512, 128>>>(xs3, p[3], 512, 256, score);
    k_rank<<<2, 256>>>(score, 512, 256, pm3, vals);
    k_gatherx<<<(256 * 256 + 255) / 256, 256>>>(xs3, 256, pm3, vals, 256, xa);
    k_grow_f32<<<(256 * 512 + 255) / 256, 256>>>(A3, 512, pm3, 256, Brf);
    k_gcol_f32<<<(512 * 256 + 255) / 256, 256>>>(A3, 512, pm3, 256, Bcf);
    k_gemm64<<<dim3(4, 4), 256>>>(Brf, Bcf, A4, 512, 256);
    k_zerodiag<<<1, 256>>>(A4, 256);
    gcn_call(A4, 256, xa, 256, Wd[4], bd[4], 512, true, xb, B);

    // ---- up 0 : res = xs3 [512,256], perm3 ----
    k_concat<<<(512 * 512 + 255) / 256, 256>>>(xs3, 512, 256, xa);
    k_scatter<<<(256 * 256 + 255) / 256, 256>>>(xa, 512, 256, pm3, 256, xb, 512, 256);
    gcn_call(A3, 512, xa, 512, Wu[0], bu[0], 256, true, xb, B);

    // ---- up 1 : res = xs2 [1024,128], perm2 ----
    k_concat<<<(1024 * 256 + 255) / 256, 256>>>(xs2, 1024, 128, xa);
    k_scatter<<<(512 * 128 + 255) / 256, 256>>>(xa, 256, 128, pm2, 512, xb, 256, 128);
    gcn_call(A2, 1024, xa, 256, Wu[1], bu[1], 128, true, xb, B);

    // ---- up 2 : res = xs1 [2048,64], perm1 ----
    k_concat<<<(2048 * 128 + 255) / 256, 256>>>(xs1, 2048, 64, xa);
    k_scatter<<<(1024 * 64 + 255) / 256, 256>>>(xa, 128, 64, pm1, 1024, xb, 128, 64);
    gcn_call(A1, 2048, xa, 128, Wu[2], bu[2], 64, true, xb, B);

    // ---- up 3 : res = xs0 [4096,32], perm0, NO relu ----
    k_concat<<<(4096 * 64 + 255) / 256, 256>>>(xs0, 4096, 32, xa);
    k_scatter<<<(2048 * 32 + 255) / 256, 256>>>(xa, 64, 32, pm0, 2048, xb, 64, 32);
    gcn_call(A0, 4096, xa, 64, Wu[3], bu[3], 32, false, xb, B);

    // ---- final GCN + softmax ----
    gcn_call(A0, 4096, xb, 32, Wo, bo, 37, false, xa, B);
    k_softmax<<<16, 256>>>(xa, (float*)d_out, 4096, 37);
}

// round 3
// speedup vs baseline: 6.3207x; 1.4156x over previous
#include <cuda_runtime.h>
#include <cuda_bf16.h>
#include <mma.h>
#include <math.h>

using namespace nvcuda;

#define N0 4096
#define EDG 131072

// ---------------- device scratch ----------------
__device__ int dA0i[(size_t)N0 * N0];
__device__ __nv_bfloat16 dA0b[(size_t)N0 * N0];
__device__ __nv_bfloat16 dA0tb[(size_t)N0 * N0];
__device__ __nv_bfloat16 dA1b[2048 * 2048];
__device__ __nv_bfloat16 dA1tb[2048 * 2048];
__device__ float dCbuf[2048 * 2048];
__device__ float dA2[1024 * 1024];
__device__ float dA3[512 * 512];
__device__ float dA4[256 * 256];
__device__ __nv_bfloat16 dBr[2048 * 4096];
__device__ __nv_bfloat16 dBct[2048 * 4096];
__device__ float dBrf[512 * 1024];
__device__ float dBcf[1024 * 512];
__device__ float dP[4 * 4096 * 128];
__device__ float dxs0[4096 * 32];
__device__ float dxs1[2048 * 64];
__device__ float dxs2[1024 * 128];
__device__ float dxs3[512 * 256];
__device__ float dxa[4096 * 512];
__device__ float dxb[4096 * 512];
__device__ float dybuf[4096 * 512];
__device__ float dzbuf[4096 * 512];
__device__ float dinv0[4096], dself0[4096];
__device__ float dinv1[2048], dself1[2048];
__device__ float dinv2[1024], dself2[1024];
__device__ float dinv3[512], dself3[512];
__device__ float dinv4[256], dself4[256];
__device__ float dscorev[4096];
__device__ float dvalsv[2048];
__device__ int dperm0[2048];
__device__ int dperm1[1024];
__device__ int dperm2[512];
__device__ int dperm3[256];

// ---------------- cp.async helpers ----------------
__device__ __forceinline__ void cpa16(void* s, const void* g) {
    unsigned sa = (unsigned)__cvta_generic_to_shared(s);
    asm volatile("cp.async.cg.shared.global [%0], [%1], 16;\n" ::"r"(sa), "l"(g));
}
__device__ __forceinline__ void cpcommit() { asm volatile("cp.async.commit_group;\n"); }
__device__ __forceinline__ void cpwait1() { asm volatile("cp.async.wait_group 1;\n"); }

// ---------------- kernels ----------------

__global__ void k_edges(const int* __restrict__ ei, int* __restrict__ A) {
    int e = blockIdx.x * blockDim.x + threadIdx.x;
    if (e < EDG) {
        int s = ei[e];
        int d = ei[EDG + e];
        atomicAdd(&A[(size_t)d * N0 + s], 1);
    }
}

// int A -> bf16 A and bf16 A^T (tiled transpose)
__global__ void k_cvt0(const int* __restrict__ Ai, __nv_bfloat16* __restrict__ Ab,
                       __nv_bfloat16* __restrict__ AbT, int n) {
    __shared__ __nv_bfloat16 tile[32][33];
    int bx = blockIdx.x * 32, by = blockIdx.y * 32;
    int tx = threadIdx.x, ty = threadIdx.y;
    for (int r = ty; r < 32; r += 8) {
        int v = Ai[(size_t)(by + r) * n + bx + tx];
        __nv_bfloat16 b = __float2bfloat16((float)v);
        Ab[(size_t)(by + r) * n + bx + tx] = b;
        tile[r][tx] = b;
    }
    __syncthreads();
    for (int r = ty; r < 32; r += 8)
        AbT[(size_t)(bx + r) * n + by + tx] = tile[tx][r];
}

// fp32 C -> bf16 A1 and bf16 A1^T with diag zero
__global__ void k_cvt1(const float* __restrict__ C, __nv_bfloat16* __restrict__ Ab,
                       __nv_bfloat16* __restrict__ AbT, int n) {
    __shared__ __nv_bfloat16 tile[32][33];
    int bx = blockIdx.x * 32, by = blockIdx.y * 32;
    int tx = threadIdx.x, ty = threadIdx.y;
    for (int r = ty; r < 32; r += 8) {
        int gi = by + r, gj = bx + tx;
        float v = (gi == gj) ? 0.f : C[(size_t)gi * n + gj];
        __nv_bfloat16 b = __float2bfloat16(v);
        Ab[(size_t)gi * n + gj] = b;
        tile[r][tx] = b;
    }
    __syncthreads();
    for (int r = ty; r < 32; r += 8)
        AbT[(size_t)(bx + r) * n + by + tx] = tile[tx][r];
}

// deg from bf16 A
__global__ void k_deg_bf(const __nv_bfloat16* __restrict__ A, int n,
                         float* __restrict__ dinv, float* __restrict__ selfc) {
    int row = blockIdx.x;
    __shared__ float sh[256];
    const __nv_bfloat16* ar = A + (size_t)row * n;
    float s = 0.f;
    for (int j = threadIdx.x; j < n; j += 256) s += __bfloat162float(ar[j]);
    sh[threadIdx.x] = s;
    __syncthreads();
    for (int o = 128; o > 0; o >>= 1) {
        if (threadIdx.x < o) sh[threadIdx.x] += sh[threadIdx.x + o];
        __syncthreads();
    }
    if (threadIdx.x == 0) {
        float diag = __bfloat162float(ar[row]);
        float fill = (diag == 0.0f) ? 2.0f : 0.0f;
        float deg = sh[0] + fill;
        float di = (deg > 0.f) ? (1.0f / sqrtf(deg)) : 0.f;
        dinv[row] = di;
        selfc[row] = di * di * fill;
    }
}

__global__ void k_deg(const float* __restrict__ A, int n,
                      float* __restrict__ dinv, float* __restrict__ selfc) {
    int row = blockIdx.x;
    __shared__ float sh[256];
    const float* ar = A + (size_t)row * n;
    float s = 0.f;
    for (int j = threadIdx.x; j < n; j += 256) s += ar[j];
    sh[threadIdx.x] = s;
    __syncthreads();
    for (int o = 128; o > 0; o >>= 1) {
        if (threadIdx.x < o) sh[threadIdx.x] += sh[threadIdx.x + o];
        __syncthreads();
    }
    if (threadIdx.x == 0) {
        float diag = ar[row];
        float fill = (diag == 0.0f) ? 2.0f : 0.0f;
        float deg = sh[0] + fill;
        float di = (deg > 0.f) ? (1.0f / sqrtf(deg)) : 0.f;
        dinv[row] = di;
        selfc[row] = di * di * fill;
    }
}

// Y = X@W (fp32) ; Zcat[i][0..c) = bf16(dinv*Y) hi, Zcat[i][64..64+c) = lo, rest 0
// c <= 64. 256 threads = 64 cols x 4 rows
__global__ void k_xw_cat(const float* __restrict__ X, const float* __restrict__ W,
                         const float* __restrict__ dinv, float* __restrict__ Y,
                         __nv_bfloat16* __restrict__ Zc, int n, int cin, int c) {
    int j = threadIdx.x & 63;
    int i = blockIdx.x * 4 + (threadIdx.x >> 6);
    if (i >= n) return;
    __nv_bfloat16 hb = __float2bfloat16(0.f), lb = hb;
    if (j < c) {
        const float* xr = X + (size_t)i * cin;
        float acc = 0.f;
        for (int k = 0; k < cin; k++) acc = fmaf(xr[k], W[(size_t)k * c + j], acc);
        Y[(size_t)i * c + j] = acc;
        float z = acc * dinv[i];
        hb = __float2bfloat16(z);
        lb = __float2bfloat16(z - __bfloat162float(hb));
    }
    Zc[(size_t)i * 128 + j] = hb;
    Zc[(size_t)i * 128 + 64 + j] = lb;
}

// P[ks] += A(bf16)[n][n] @ Zcat[n][128], split-K. BM=64, BN=128, BK=64, 8 warps.
__global__ __launch_bounds__(256) void k_prop(const __nv_bfloat16* __restrict__ A,
                                              const __nv_bfloat16* __restrict__ Zc,
                                              float* __restrict__ P, int n, int KS) {
    __shared__ __nv_bfloat16 As[64][72];
    __shared__ __nv_bfloat16 Zs[64][136];
    int tid = threadIdx.x;
    int warp = tid >> 5;
    int wm = warp >> 2, wn = warp & 3;
    int m0 = blockIdx.x * 64;
    int ks = blockIdx.y;
    int chunk = n / KS;
    int kbeg = ks * chunk, kend = kbeg + chunk;

    wmma::fragment<wmma::accumulator, 16, 16, 16, float> acc[2][2];
#pragma unroll
    for (int i = 0; i < 2; i++)
#pragma unroll
        for (int j = 0; j < 2; j++) wmma::fill_fragment(acc[i][j], 0.f);

    for (int k0 = kbeg; k0 < kend; k0 += 64) {
#pragma unroll
        for (int l = 0; l < 2; l++) {
            int e = tid + 256 * l;
            int r = e >> 3, cg = (e & 7) * 8;
            *reinterpret_cast<uint4*>(&As[r][cg]) =
                *reinterpret_cast<const uint4*>(A + (size_t)(m0 + r) * n + k0 + cg);
        }
#pragma unroll
        for (int l = 0; l < 4; l++) {
            int e = tid + 256 * l;
            int r = e >> 4, cg = (e & 15) * 8;
            *reinterpret_cast<uint4*>(&Zs[r][cg]) =
                *reinterpret_cast<const uint4*>(Zc + (size_t)(k0 + r) * 128 + cg);
        }
        __syncthreads();
#pragma unroll
        for (int kk = 0; kk < 64; kk += 16) {
            wmma::fragment<wmma::matrix_a, 16, 16, 16, __nv_bfloat16, wmma::row_major> af[2];
            wmma::fragment<wmma::matrix_b, 16, 16, 16, __nv_bfloat16, wmma::row_major> bf[2];
#pragma unroll
            for (int i = 0; i < 2; i++)
                wmma::load_matrix_sync(af[i], &As[wm * 32 + 16 * i][kk], 72);
#pragma unroll
            for (int j = 0; j < 2; j++)
                wmma::load_matrix_sync(bf[j], &Zs[kk][wn * 32 + 16 * j], 136);
#pragma unroll
            for (int i = 0; i < 2; i++)
#pragma unroll
                for (int j = 0; j < 2; j++)
                    wmma::mma_sync(acc[i][j], af[i], bf[j], acc[i][j]);
        }
        __syncthreads();
    }
#pragma unroll
    for (int i = 0; i < 2; i++)
#pragma unroll
        for (int j = 0; j < 2; j++)
            wmma::store_matrix_sync(P + ((size_t)ks * n + m0 + wm * 32 + 16 * i) * 128 +
                                        wn * 32 + 16 * j,
                                    acc[i][j], 128, wmma::mem_row_major);
}

// out = relu?( dinv_i*(sum_ks P_hi+P_lo) + selfc_i*Y + b )
__global__ void k_prop_epi(const float* __restrict__ P, const float* __restrict__ Y,
                           const float* __restrict__ dinv, const float* __restrict__ selfc,
                           const float* __restrict__ bias, float* __restrict__ O,
                           int n, int c, int KS, int dorelu) {
    int t = blockIdx.x * 256 + threadIdx.x;
    if (t >= n * c) return;
    int i = t / c, j = t % c;
    float s = 0.f;
    for (int ks = 0; ks < KS; ks++) {
        const float* pr = P + ((size_t)ks * n + i) * 128;
        s += pr[j] + pr[64 + j];
    }
    float o = dinv[i] * s + selfc[i] * Y[t] + bias[j];
    if (dorelu) o = fmaxf(o, 0.f);
    O[t] = o;
}

// ---- old fp32 SIMT path for small levels ----
__global__ void k_xw(const float* __restrict__ X, const float* __restrict__ W,
                     const float* __restrict__ dinv,
                     float* __restrict__ Y, float* __restrict__ Z,
                     int n, int cin, int cout) {
    int j = blockIdx.x * 32 + threadIdx.x;
    int i = blockIdx.y * 8 + threadIdx.y;
    if (i >= n || j >= cout) return;
    const float* xr = X + (size_t)i * cin;
    float acc = 0.f;
    for (int k = 0; k < cin; k++) acc = fmaf(xr[k], W[(size_t)k * cout + j], acc);
    Y[(size_t)i * cout + j] = acc;
    Z[(size_t)i * cout + j] = acc * dinv[i];
}

__global__ __launch_bounds__(256) void k_gcnmm_sp(
    const float* __restrict__ A, const float* __restrict__ Z,
    float* __restrict__ P, int n, int c, int KS) {
    __shared__ float As[32][65];
    __shared__ float Zs[32][32];
    int tid = threadIdx.x;
    int m0 = blockIdx.y * 64;
    int n0c = blockIdx.x * 32;
    int ks = blockIdx.z;
    int chunk = n / KS;
    int kbeg = ks * chunk, kend = kbeg + chunk;
    int r0 = tid >> 5, colt = tid & 31;
    float acc[8] = {0, 0, 0, 0, 0, 0, 0, 0};
    for (int k0 = kbeg; k0 < kend; k0 += 32) {
#pragma unroll
        for (int l = 0; l < 2; l++) {
            int e = tid + 256 * l;
            int row = e >> 3, qc = (e & 7) * 4;
            float4 v = *reinterpret_cast<const float4*>(A + (size_t)(m0 + row) * n + k0 + qc);
            As[qc + 0][row] = v.x; As[qc + 1][row] = v.y;
            As[qc + 2][row] = v.z; As[qc + 3][row] = v.w;
        }
        {
            int row = tid >> 3, qc = (tid & 7) * 4;
            int gk = k0 + row;
#pragma unroll
            for (int u = 0; u < 4; u++) {
                int gc = n0c + qc + u;
                Zs[row][qc + u] = (gc < c) ? Z[(size_t)gk * c + gc] : 0.f;
            }
        }
        __syncthreads();
#pragma unroll
        for (int k = 0; k < 32; k++) {
            float zv = Zs[k][colt];
#pragma unroll
            for (int u = 0; u < 8; u++) acc[u] = fmaf(As[k][r0 + 8 * u], zv, acc[u]);
        }
        __syncthreads();
    }
    int gc = n0c + colt;
    if (gc < c) {
#pragma unroll
        for (int u = 0; u < 8; u++) {
            int gi = m0 + r0 + 8 * u;
            P[((size_t)ks * n + gi) * c + gc] = acc[u];
        }
    }
}

__global__ void k_gcn_epi(const float* __restrict__ P, const float* __restrict__ Y,
                          const float* __restrict__ dinv, const float* __restrict__ selfc,
                          const float* __restrict__ bias, float* __restrict__ O,
                          int n, int c, int KS, int dorelu) {
    int t = blockIdx.x * 256 + threadIdx.x;
    if (t >= n * c) return;
    int i = t / c, j = t % c;
    float s = 0.f;
    size_t stride = (size_t)n * c;
    for (int ks = 0; ks < KS; ks++) s += P[ks * stride + t];
    float o = dinv[i] * s + selfc[i] * Y[t] + bias[j];
    if (dorelu) o = fmaxf(o, 0.f);
    O[t] = o;
}

// row gather with diag->1: Out[r][k] = (k==perm_r)?1:Src[perm_r][k]
__global__ void k_growb(const __nv_bfloat16* __restrict__ Src, int n,
                        const int* __restrict__ perm, int ksel,
                        __nv_bfloat16* __restrict__ Out) {
    size_t t = (size_t)blockIdx.x * 256 + threadIdx.x;
    size_t tot = (size_t)ksel * (n / 8);
    if (t >= tot) return;
    int r = t / (n / 8);
    int kc = (t % (n / 8)) * 8;
    int pr = perm[r];
    uint4 v = *reinterpret_cast<const uint4*>(Src + (size_t)pr * n + kc);
    if (pr >= kc && pr < kc + 8) {
        __nv_bfloat16 tmp[8];
        *reinterpret_cast<uint4*>(tmp) = v;
        tmp[pr - kc] = __float2bfloat16(1.0f);
        v = *reinterpret_cast<uint4*>(tmp);
    }
    *reinterpret_cast<uint4*>(Out + (size_t)r * n + kc) = v;
}

__global__ void k_grow_f32(const float* __restrict__ A, int n,
                           const int* __restrict__ perm, int ksel,
                           float* __restrict__ Br) {
    size_t t = (size_t)blockIdx.x * 256 + threadIdx.x;
    if (t >= (size_t)ksel * n) return;
    int r = t / n, k = t % n;
    int pr = perm[r];
    Br[t] = (k == pr) ? 1.0f : A[(size_t)pr * n + k];
}

__global__ void k_gcol_f32(const float* __restrict__ A, int n,
                           const int* __restrict__ perm, int ksel,
                           float* __restrict__ Bc) {
    size_t t = (size_t)blockIdx.x * 256 + threadIdx.x;
    if (t >= (size_t)n * ksel) return;
    int k = t / ksel, c = t % ksel;
    int pc = perm[c];
    Bc[t] = (k == pc) ? 1.0f : A[(size_t)k * n + pc];
}

// augment GEMM: C[M][Nn] = Br[M][K] @ BcT[Nn][K]^T  (B col-major), cp.async 2-stage
__global__ __launch_bounds__(256) void k_aug(const __nv_bfloat16* __restrict__ Br,
                                             const __nv_bfloat16* __restrict__ BcT,
                                             float* __restrict__ C, int K, int Nn) {
    __shared__ __nv_bfloat16 As[2][128][40];
    __shared__ __nv_bfloat16 Bs[2][128][40];
    int tid = threadIdx.x;
    int warp = tid >> 5;
    int wm = warp >> 1, wn = warp & 1;
    int m0 = blockIdx.y * 128, n0 = blockIdx.x * 128;

    wmma::fragment<wmma::accumulator, 16, 16, 16, float> acc[2][4];
#pragma unroll
    for (int i = 0; i < 2; i++)
#pragma unroll
        for (int j = 0; j < 4; j++) wmma::fill_fragment(acc[i][j], 0.f);

    auto load_tiles = [&](int buf, int k0) {
#pragma unroll
        for (int l = 0; l < 2; l++) {
            int e = tid + 256 * l;
            int r = e >> 2, cg = (e & 3) * 8;
            cpa16(&As[buf][r][cg], Br + (size_t)(m0 + r) * K + k0 + cg);
            cpa16(&Bs[buf][r][cg], BcT + (size_t)(n0 + r) * K + k0 + cg);
        }
    };

    load_tiles(0, 0);
    cpcommit();
    int nIter = K / 32;
    for (int it = 0; it < nIter; it++) {
        int cur = it & 1;
        if (it + 1 < nIter) load_tiles(cur ^ 1, (it + 1) * 32);
        cpcommit();
        cpwait1();
        __syncthreads();
#pragma unroll
        for (int kk = 0; kk < 32; kk += 16) {
            wmma::fragment<wmma::matrix_a, 16, 16, 16, __nv_bfloat16, wmma::row_major> af[2];
            wmma::fragment<wmma::matrix_b, 16, 16, 16, __nv_bfloat16, wmma::col_major> bf[4];
#pragma unroll
            for (int i = 0; i < 2; i++)
                wmma::load_matrix_sync(af[i], &As[cur][wm * 32 + 16 * i][kk], 40);
#pragma unroll
            for (int j = 0; j < 4; j++)
                wmma::load_matrix_sync(bf[j], &Bs[cur][wn * 64 + 16 * j][kk], 40);
#pragma unroll
            for (int i = 0; i < 2; i++)
#pragma unroll
                for (int j = 0; j < 4; j++)
                    wmma::mma_sync(acc[i][j], af[i], bf[j], acc[i][j]);
        }
        __syncthreads();
    }
#pragma unroll
    for (int i = 0; i < 2; i++)
#pragma unroll
        for (int j = 0; j < 4; j++)
            wmma::store_matrix_sync(C + (size_t)(m0 + wm * 32 + 16 * i) * Nn + n0 + wn * 64 + 16 * j,
                                    acc[i][j], Nn, wmma::mem_row_major);
}

__global__ __launch_bounds__(256) void k_gemm64(const float* __restrict__ Br,
                                                const float* __restrict__ Bc,
                                                float* __restrict__ C, int K, int Nn) {
    __shared__ float As[16][65];
    __shared__ float Bs[16][65];
    int tid = threadIdx.x;
    int m0 = blockIdx.y * 64, n0 = blockIdx.x * 64;
    int ty = tid >> 4, tx = tid & 15;
    float acc[4][4] = {};
    for (int k0 = 0; k0 < K; k0 += 16) {
#pragma unroll
        for (int l = 0; l < 4; l++) {
            int e = tid + 256 * l;
            int row = e >> 4, kk = e & 15;
            As[kk][row] = Br[(size_t)(m0 + row) * K + k0 + kk];
        }
#pragma unroll
        for (int l = 0; l < 4; l++) {
            int e = tid + 256 * l;
            int row = e >> 6, col = e & 63;
            Bs[row][col] = Bc[(size_t)(k0 + row) * Nn + n0 + col];
        }
        __syncthreads();
#pragma unroll
        for (int kk = 0; kk < 16; kk++) {
            float a[4], b[4];
#pragma unroll
            for (int i = 0; i < 4; i++) a[i] = As[kk][ty * 4 + i];
#pragma unroll
            for (int j = 0; j < 4; j++) b[j] = Bs[kk][tx * 4 + j];
#pragma unroll
            for (int i = 0; i < 4; i++)
#pragma unroll
                for (int j = 0; j < 4; j++) acc[i][j] = fmaf(a[i], b[j], acc[i][j]);
        }
        __syncthreads();
    }
#pragma unroll
    for (int i = 0; i < 4; i++)
#pragma unroll
        for (int j = 0; j < 4; j++)
            C[(size_t)(m0 + ty * 4 + i) * Nn + n0 + tx * 4 + j] = acc[i][j];
}

__global__ void k_zerodiag(float* __restrict__ C, int n) {
    int i = blockIdx.x * 256 + threadIdx.x;
    if (i < n) C[(size_t)i * n + i] = 0.f;
}

__global__ void k_score(const float* __restrict__ X, const float* __restrict__ w,
                        int n, int c, float* __restrict__ score) {
    int row = blockIdx.x;
    __shared__ float sh[128];
    const float* xr = X + (size_t)row * c;
    float wsq = 0.f, dot = 0.f;
    for (int k = threadIdx.x; k < c; k += 128) {
        float wv = w[k];
        wsq += wv * wv;
        dot += xr[k] * wv;
    }
    sh[threadIdx.x] = wsq;
    __syncthreads();
    for (int o = 64; o > 0; o >>= 1) {
        if (threadIdx.x < o) sh[threadIdx.x] += sh[threadIdx.x + o];
        __syncthreads();
    }
    float wn = sh[0];
    __syncthreads();
    sh[threadIdx.x] = dot;
    __syncthreads();
    for (int o = 64; o > 0; o >>= 1) {
        if (threadIdx.x < o) sh[threadIdx.x] += sh[threadIdx.x + o];
        __syncthreads();
    }
    if (threadIdx.x == 0) score[row] = tanhf(sh[0] / sqrtf(wn));
}

__global__ void k_rank(const float* __restrict__ score, int n, int k,
                       int* __restrict__ perm, float* __restrict__ vals) {
    int i = blockIdx.x * 256 + threadIdx.x;
    if (i >= n) return;
    float si = score[i];
    int rank = 0;
    for (int j = 0; j < n; j++) {
        float sj = score[j];
        rank += (sj > si) || (sj == si && j < i);
    }
    if (rank < k) {
        perm[rank] = i;
        vals[rank] = si;
    }
}

__global__ void k_gatherx(const float* __restrict__ X, int c,
                          const int* __restrict__ perm, const float* __restrict__ vals,
                          int k, float* __restrict__ O) {
    int t = blockIdx.x * 256 + threadIdx.x;
    if (t >= k * c) return;
    int r = t / c, j = t % c;
    O[t] = X[(size_t)perm[r] * c + j] * vals[r];
}

__global__ void k_concat(const float* __restrict__ R, int n, int c, float* __restrict__ O) {
    int t = blockIdx.x * 256 + threadIdx.x;
    int tot = n * 2 * c;
    if (t >= tot) return;
    int i = t / (2 * c), j = t % (2 * c);
    O[t] = (j < c) ? R[(size_t)i * c + j] : 0.f;
}

__global__ void k_scatter(float* __restrict__ O, int ostride, int off,
                          const int* __restrict__ perm, int k,
                          const float* __restrict__ S, int sstride, int nc) {
    int t = blockIdx.x * 256 + threadIdx.x;
    if (t >= k * nc) return;
    int r = t / nc, j = t % nc;
    O[(size_t)perm[r] * ostride + off + j] = S[(size_t)r * sstride + j];
}

__global__ void k_softmax(const float* __restrict__ X, float* __restrict__ O, int n, int c) {
    int i = blockIdx.x * 256 + threadIdx.x;
    if (i >= n) return;
    const float* xr = X + (size_t)i * c;
    float m = -1e30f;
    for (int j = 0; j < c; j++) m = fmaxf(m, xr[j]);
    float s = 0.f;
    for (int j = 0; j < c; j++) s += expf(xr[j] - m);
    float inv = 1.0f / s;
    for (int j = 0; j < c; j++) O[(size_t)i * c + j] = expf(xr[j] - m) * inv;
}

// ---------------- host orchestration ----------------

struct Ptrs {
    float *y, *z, *P;
    __nv_bfloat16* zc;
};

// tensor-core GCN (n in {4096,2048}, c<=64)
static void gcn_tc(const __nv_bfloat16* Ab, int n, const float* xin, int cin,
                   const float* W, const float* b, int c, bool relu, float* out,
                   const float* dinv, const float* selfc, const Ptrs& q) {
    const int KS = 4;
    k_xw_cat<<<n / 4, 256>>>(xin, W, dinv, q.y, q.zc, n, cin, c);
    k_prop<<<dim3(n / 64, KS), 256>>>(Ab, q.zc, q.P, n, KS);
    k_prop_epi<<<(n * c + 255) / 256, 256>>>(q.P, q.y, dinv, selfc, b, out, n, c, KS, relu ? 1 : 0);
}

// fp32 SIMT GCN for small levels
static void gcn_f32(const float* A, int n, const float* xin, int cin,
                    const float* W, const float* b, int cout, bool relu, float* out,
                    const float* dinv, const float* selfc, const Ptrs& q) {
    const int KS = 8;
    dim3 bx(32, 8);
    dim3 gx((cout + 31) / 32, (n + 7) / 8);
    k_xw<<<gx, bx>>>(xin, W, dinv, q.y, q.z, n, cin, cout);
    dim3 g2((cout + 31) / 32, n / 64, KS);
    k_gcnmm_sp<<<g2, 256>>>(A, q.z, q.P, n, cout, KS);
    k_gcn_epi<<<(n * cout + 255) / 256, 256>>>(q.P, q.y, dinv, selfc, b, out, n, cout, KS, relu ? 1 : 0);
}

extern "C" void kernel_launch(void* const* d_in, const int* in_sizes, int n_in,
                              void* d_out, int out_size) {
    const float* x = (const float*)d_in[0];
    const int* ei = (const int*)d_in[1];
    const float *Wd[5], *bd[5], *p[4], *Wu[4], *bu[4];
    for (int i = 0; i < 5; i++) { Wd[i] = (const float*)d_in[2 + 2 * i]; bd[i] = (const float*)d_in[3 + 2 * i]; }
    for (int i = 0; i < 4; i++) p[i] = (const float*)d_in[12 + i];
    for (int i = 0; i < 4; i++) { Wu[i] = (const float*)d_in[16 + 2 * i]; bu[i] = (const float*)d_in[17 + 2 * i]; }
    const float* Wo = (const float*)d_in[24];
    const float* bo = (const float*)d_in[25];

    int* A0i;
    __nv_bfloat16 *A0b, *A0tb, *A1b, *A1tb, *Br, *BcT;
    float *C, *A2, *A3, *A4, *xs0, *xs1, *xs2, *xs3, *xa, *xb;
    float *Brf, *Bcf, *score, *vals;
    float *di0, *sf0, *di1, *sf1, *di2, *sf2, *di3, *sf3, *di4, *sf4;
    int *pm0, *pm1, *pm2, *pm3;
    Ptrs q;
    cudaGetSymbolAddress((void**)&A0i, dA0i);
    cudaGetSymbolAddress((void**)&A0b, dA0b);
    cudaGetSymbolAddress((void**)&A0tb, dA0tb);
    cudaGetSymbolAddress((void**)&A1b, dA1b);
    cudaGetSymbolAddress((void**)&A1tb, dA1tb);
    cudaGetSymbolAddress((void**)&C, dCbuf);
    cudaGetSymbolAddress((void**)&A2, dA2);
    cudaGetSymbolAddress((void**)&A3, dA3);
    cudaGetSymbolAddress((void**)&A4, dA4);
    cudaGetSymbolAddress((void**)&Br, dBr);
    cudaGetSymbolAddress((void**)&BcT, dBct);
    cudaGetSymbolAddress((void**)&Brf, dBrf);
    cudaGetSymbolAddress((void**)&Bcf, dBcf);
    cudaGetSymbolAddress((void**)&q.P, dP);
    cudaGetSymbolAddress((void**)&xs0, dxs0);
    cudaGetSymbolAddress((void**)&xs1, dxs1);
    cudaGetSymbolAddress((void**)&xs2, dxs2);
    cudaGetSymbolAddress((void**)&xs3, dxs3);
    cudaGetSymbolAddress((void**)&xa, dxa);
    cudaGetSymbolAddress((void**)&xb, dxb);
    cudaGetSymbolAddress((void**)&q.y, dybuf);
    cudaGetSymbolAddress((void**)&q.z, dzbuf);
    q.zc = (__nv_bfloat16*)q.z;
    cudaGetSymbolAddress((void**)&di0, dinv0); cudaGetSymbolAddress((void**)&sf0, dself0);
    cudaGetSymbolAddress((void**)&di1, dinv1); cudaGetSymbolAddress((void**)&sf1, dself1);
    cudaGetSymbolAddress((void**)&di2, dinv2); cudaGetSymbolAddress((void**)&sf2, dself2);
    cudaGetSymbolAddress((void**)&di3, dinv3); cudaGetSymbolAddress((void**)&sf3, dself3);
    cudaGetSymbolAddress((void**)&di4, dinv4); cudaGetSymbolAddress((void**)&sf4, dself4);
    cudaGetSymbolAddress((void**)&score, dscorev);
    cudaGetSymbolAddress((void**)&vals, dvalsv);
    cudaGetSymbolAddress((void**)&pm0, dperm0);
    cudaGetSymbolAddress((void**)&pm1, dperm1);
    cudaGetSymbolAddress((void**)&pm2, dperm2);
    cudaGetSymbolAddress((void**)&pm3, dperm3);

    // build adjacency (int), convert to bf16 + bf16 transpose
    cudaMemsetAsync(A0i, 0, (size_t)N0 * N0 * sizeof(int));
    k_edges<<<EDG / 256, 256>>>(ei, A0i);
    k_cvt0<<<dim3(N0 / 32, N0 / 32), dim3(32, 8)>>>(A0i, A0b, A0tb, N0);
    k_deg_bf<<<N0, 256>>>(A0b, N0, di0, sf0);

    // GCN0: [4096,128] -> [4096,32], relu
    gcn_tc(A0b, 4096, x, 128, Wd[0], bd[0], 32, true, xs0, di0, sf0, q);

    // ---- level 1 ----
    k_score<<<4096, 128>>>(xs0, p[0], 4096, 32, score);
    k_rank<<<16, 256>>>(score, 4096, 2048, pm0, vals);
    k_gatherx<<<(2048 * 32 + 255) / 256, 256>>>(xs0, 32, pm0, vals, 2048, xa);
    k_growb<<<(2048 * (4096 / 8) + 255) / 256, 256>>>(A0b, 4096, pm0, 2048, Br);
    k_growb<<<(2048 * (4096 / 8) + 255) / 256, 256>>>(A0tb, 4096, pm0, 2048, BcT);
    k_aug<<<dim3(16, 16), 256>>>(Br, BcT, C, 4096, 2048);
    k_cvt1<<<dim3(2048 / 32, 2048 / 32), dim3(32, 8)>>>(C, A1b, A1tb, 2048);
    k_deg_bf<<<2048, 256>>>(A1b, 2048, di1, sf1);
    gcn_tc(A1b, 2048, xa, 32, Wd[1], bd[1], 64, true, xs1, di1, sf1, q);

    // ---- level 2 ----
    k_score<<<2048, 128>>>(xs1, p[1], 2048, 64, score);
    k_rank<<<8, 256>>>(score, 2048, 1024, pm1, vals);
    k_gatherx<<<(1024 * 64 + 255) / 256, 256>>>(xs1, 64, pm1, vals, 1024, xa);
    k_growb<<<(1024 * (2048 / 8) + 255) / 256, 256>>>(A1b, 2048, pm1, 1024, Br);
    k_growb<<<(1024 * (2048 / 8) + 255) / 256, 256>>>(A1tb, 2048, pm1, 1024, BcT);
    k_aug<<<dim3(8, 8), 256>>>(Br, BcT, A2, 2048, 1024);
    k_zerodiag<<<4, 256>>>(A2, 1024);
    k_deg<<<1024, 256>>>(A2, 1024, di2, sf2);
    gcn_f32(A2, 1024, xa, 64, Wd[2], bd[2], 128, true, xs2, di2, sf2, q);

    // ---- level 3 (fp32) ----
    k_score<<<1024, 128>>>(xs2, p[2], 1024, 128, score);
    k_rank<<<4, 256>>>(score, 1024, 512, pm2, vals);
    k_gatherx<<<(512 * 128 + 255) / 256, 256>>>(xs2, 128, pm2, vals, 512, xa);
    k_grow_f32<<<(512 * 1024 + 255) / 256, 256>>>(A2, 1024, pm2, 512, Brf);
    k_gcol_f32<<<(1024 * 512 + 255) / 256, 256>>>(A2, 1024, pm2, 512, Bcf);
    k_gemm64<<<dim3(8, 8), 256>>>(Brf, Bcf, A3, 1024, 512);
    k_zerodiag<<<2, 256>>>(A3, 512);
    k_deg<<<512, 256>>>(A3, 512, di3, sf3);
    gcn_f32(A3, 512, xa, 128, Wd[3], bd[3], 256, true, xs3, di3, sf3, q);

    // ---- level 4 (fp32) ----
    k_score<<<512, 128>>>(xs3, p[3], 512, 256, score);
    k_rank<<<2, 256>>>(score, 512, 256, pm3, vals);
    k_gatherx<<<(256 * 256 + 255) / 256, 256>>>(xs3, 256, pm3, vals, 256, xa);
    k_grow_f32<<<(256 * 512 + 255) / 256, 256>>>(A3, 512, pm3, 256, Brf);
    k_gcol_f32<<<(512 * 256 + 255) / 256, 256>>>(A3, 512, pm3, 256, Bcf);
    k_gemm64<<<dim3(4, 4), 256>>>(Brf, Bcf, A4, 512, 256);
    k_zerodiag<<<1, 256>>>(A4, 256);
    k_deg<<<256, 256>>>(A4, 256, di4, sf4);
    gcn_f32(A4, 256, xa, 256, Wd[4], bd[4], 512, true, xb, di4, sf4, q);

    // ---- up 0 : res = xs3 [512,256], perm3 ----
    k_concat<<<(512 * 512 + 255) / 256, 256>>>(xs3, 512, 256, xa);
    k_scatter<<<(256 * 256 + 255) / 256, 256>>>(xa, 512, 256, pm3, 256, xb, 512, 256);
    gcn_f32(A3, 512, xa, 512, Wu[0], bu[0], 256, true, xb, di3, sf3, q);

    // ---- up 1 : res = xs2 [1024,128], perm2 ----
    k_concat<<<(1024 * 256 + 255) / 256, 256>>>(xs2, 1024, 128, xa);
    k_scatter<<<(512 * 128 + 255) / 256, 256>>>(xa, 256, 128, pm2, 512, xb, 256, 128);
    gcn_f32(A2, 1024, xa, 256, Wu[1], bu[1], 128, true, xb, di2, sf2, q);

    // ---- up 2 : res = xs1 [2048,64], perm1 ----
    k_concat<<<(2048 * 128 + 255) / 256, 256>>>(xs1, 2048, 64, xa);
    k_scatter<<<(1024 * 64 + 255) / 256, 256>>>(xa, 128, 64, pm1, 1024, xb, 128, 64);
    gcn_tc(A1b, 2048, xa, 128, Wu[2], bu[2], 64, true, xb, di1, sf1, q);

    // ---- up 3 : res = xs0 [4096,32], perm0, NO relu ----
    k_concat<<<(4096 * 64 + 255) / 256, 256>>>(xs0, 4096, 32, xa);
    k_scatter<<<(2048 * 32 + 255) / 256, 256>>>(xa, 64, 32, pm0, 2048, xb, 64, 32);
    gcn_tc(A0b, 4096, xa, 64, Wu[3], bu[3], 32, false, xb, di0, sf0, q);

    // ---- final GCN + softmax ----
    gcn_tc(A0b, 4096, xb, 32, Wo, bo, 37, false, xa, di0, sf0, q);
    k_softmax<<<16, 256>>>(xa, (float*)d_out, 4096, 37);
}

// round 4
// speedup vs baseline: 6.8106x; 1.0775x over previous
#include <cuda_runtime.h>
#include <cuda_bf16.h>
#include <mma.h>
#include <math.h>

using namespace nvcuda;

#define N0 4096
#define EDG 131072

// ---------------- device scratch ----------------
__device__ __nv_bfloat16 dA0b[(size_t)N0 * N0];
__device__ __nv_bfloat16 dA0tb[(size_t)N0 * N0];
__device__ __nv_bfloat16 dA1b[2048 * 2048];
__device__ __nv_bfloat16 dA1tb[2048 * 2048];
__device__ float dA2[1024 * 1024];
__device__ float dA3[512 * 512];
__device__ float dA4[256 * 256];
__device__ float dBrf[512 * 1024];
__device__ float dBcf[1024 * 512];
__device__ float dP[4 * 4096 * 128];
__device__ float dxs0[4096 * 32];
__device__ float dxs1[2048 * 64];
__device__ float dxs2[1024 * 128];
__device__ float dxs3[512 * 256];
__device__ float dxa[4096 * 512];
__device__ float dxb[4096 * 512];
__device__ float dybuf[4096 * 512];
__device__ float dzbuf[4096 * 512];
__device__ float ddeg0[4096], ddeg1[2048];
__device__ float dinv0[4096], dself0[4096];
__device__ float dinv1[2048], dself1[2048];
__device__ float dinv2[1024], dself2[1024];
__device__ float dinv3[512], dself3[512];
__device__ float dinv4[256], dself4[256];
__device__ float dscorev[4096];
__device__ float dvalsv[2048];
__device__ int dperm0[2048];
__device__ int dperm1[1024];
__device__ int dperm2[512];
__device__ int dperm3[256];

// ---------------- helpers ----------------
__device__ __forceinline__ void cpa16(void* s, const void* g) {
    unsigned sa = (unsigned)__cvta_generic_to_shared(s);
    asm volatile("cp.async.cg.shared.global [%0], [%1], 16;\n" ::"r"(sa), "l"(g));
}
__device__ __forceinline__ void cpcommit() { asm volatile("cp.async.commit_group;\n"); }
__device__ __forceinline__ void cpwait1() { asm volatile("cp.async.wait_group 1;\n"); }

__device__ __forceinline__ void bf16AtomicInc(__nv_bfloat16* addr) {
    unsigned short* p = (unsigned short*)addr;
    unsigned short old = *p;
    while (true) {
        __nv_bfloat16_raw r;
        r.x = old;
        float f = __bfloat162float(__nv_bfloat16(r)) + 1.0f;
        __nv_bfloat16 nb = __float2bfloat16(f);
        __nv_bfloat16_raw nr = (__nv_bfloat16_raw)nb;
        unsigned short prev = atomicCAS(p, old, nr.x);
        if (prev == old) break;
        old = prev;
    }
}

// ---------------- kernels ----------------

__global__ void k_edges(const int* __restrict__ ei, __nv_bfloat16* __restrict__ A) {
    int e = blockIdx.x * blockDim.x + threadIdx.x;
    if (e < EDG) {
        int s = ei[e];
        int d = ei[EDG + e];
        bf16AtomicInc(&A[(size_t)d * N0 + s]);
    }
}

// bf16 transpose (32x32 tiles) + per-row degree partial sums
__global__ void k_trans_deg(const __nv_bfloat16* __restrict__ Ab,
                            __nv_bfloat16* __restrict__ AbT,
                            float* __restrict__ deg, int n) {
    __shared__ __nv_bfloat16 tile[32][33];
    int bx = blockIdx.x * 32, by = blockIdx.y * 32;
    int tx = threadIdx.x, ty = threadIdx.y;
    for (int r = ty; r < 32; r += 8)
        tile[r][tx] = Ab[(size_t)(by + r) * n + bx + tx];
    __syncthreads();
    for (int r = ty; r < 32; r += 8)
        AbT[(size_t)(bx + r) * n + by + tx] = tile[tx][r];
    if (ty == 0) {
        float s = 0.f;
        for (int c = 0; c < 32; c++) s += __bfloat162float(tile[tx][c]);
        atomicAdd(&deg[by + tx], s);
    }
}

// finalize dinv/selfc from accumulated deg + diag of bf16 matrix
__global__ void k_degfin(const __nv_bfloat16* __restrict__ Ab, const float* __restrict__ deg,
                         int n, float* __restrict__ dinv, float* __restrict__ selfc) {
    int i = blockIdx.x * 256 + threadIdx.x;
    if (i >= n) return;
    float diag = __bfloat162float(Ab[(size_t)i * n + i]);
    float fill = (diag == 0.0f) ? 2.0f : 0.0f;
    float d = deg[i] + fill;
    float di = (d > 0.f) ? (1.0f / sqrtf(d)) : 0.f;
    dinv[i] = di;
    selfc[i] = di * di * fill;
}

__global__ void k_deg(const float* __restrict__ A, int n,
                      float* __restrict__ dinv, float* __restrict__ selfc) {
    int row = blockIdx.x;
    __shared__ float sh[256];
    const float* ar = A + (size_t)row * n;
    float s = 0.f;
    for (int j = threadIdx.x; j < n; j += 256) s += ar[j];
    sh[threadIdx.x] = s;
    __syncthreads();
    for (int o = 128; o > 0; o >>= 1) {
        if (threadIdx.x < o) sh[threadIdx.x] += sh[threadIdx.x + o];
        __syncthreads();
    }
    if (threadIdx.x == 0) {
        float diag = ar[row];
        float fill = (diag == 0.0f) ? 2.0f : 0.0f;
        float deg = sh[0] + fill;
        float di = (deg > 0.f) ? (1.0f / sqrtf(deg)) : 0.f;
        dinv[row] = di;
        selfc[row] = di * di * fill;
    }
}

// Y = X@W ; Zcat = [bf16 hi | bf16 lo] of dinv*Y, 128 wide. 16 rows/block, shared W.
__global__ __launch_bounds__(256) void k_xw_cat(const float* __restrict__ X,
                                                const float* __restrict__ W,
                                                const float* __restrict__ dinv,
                                                float* __restrict__ Y,
                                                __nv_bfloat16* __restrict__ Zc,
                                                int n, int cin, int c) {
    __shared__ float Ws[8192];
    int tid = threadIdx.x;
    int tot = cin * c;
    for (int e = tid; e < tot; e += 256) Ws[e] = W[e];
    __syncthreads();
    int j = tid & 63;
    int rg = tid >> 6;
    __nv_bfloat16 zb = __float2bfloat16(0.f);
#pragma unroll
    for (int sub = 0; sub < 4; sub++) {
        int i = blockIdx.x * 16 + rg * 4 + sub;
        if (i >= n) break;
        __nv_bfloat16 hb = zb, lb = zb;
        if (j < c) {
            const float* xr = X + (size_t)i * cin;
            float acc = 0.f;
            for (int k = 0; k < cin; k += 4) {
                float4 xv = *reinterpret_cast<const float4*>(xr + k);
                acc = fmaf(xv.x, Ws[k * c + j], acc);
                acc = fmaf(xv.y, Ws[(k + 1) * c + j], acc);
                acc = fmaf(xv.z, Ws[(k + 2) * c + j], acc);
                acc = fmaf(xv.w, Ws[(k + 3) * c + j], acc);
            }
            Y[(size_t)i * c + j] = acc;
            float z = acc * dinv[i];
            hb = __float2bfloat16(z);
            lb = __float2bfloat16(z - __bfloat162float(hb));
        }
        Zc[(size_t)i * 128 + j] = hb;
        Zc[(size_t)i * 128 + 64 + j] = lb;
    }
}

// P[ks] = A(bf16)[n][n] @ Zcat[n][128], split-K
__global__ __launch_bounds__(256) void k_prop(const __nv_bfloat16* __restrict__ A,
                                              const __nv_bfloat16* __restrict__ Zc,
                                              float* __restrict__ P, int n, int KS) {
    __shared__ __nv_bfloat16 As[64][72];
    __shared__ __nv_bfloat16 Zs[64][136];
    int tid = threadIdx.x;
    int warp = tid >> 5;
    int wm = warp >> 2, wn = warp & 3;
    int m0 = blockIdx.x * 64;
    int ks = blockIdx.y;
    int chunk = n / KS;
    int kbeg = ks * chunk, kend = kbeg + chunk;

    wmma::fragment<wmma::accumulator, 16, 16, 16, float> acc[2][2];
#pragma unroll
    for (int i = 0; i < 2; i++)
#pragma unroll
        for (int j = 0; j < 2; j++) wmma::fill_fragment(acc[i][j], 0.f);

    for (int k0 = kbeg; k0 < kend; k0 += 64) {
#pragma unroll
        for (int l = 0; l < 2; l++) {
            int e = tid + 256 * l;
            int r = e >> 3, cg = (e & 7) * 8;
            *reinterpret_cast<uint4*>(&As[r][cg]) =
                *reinterpret_cast<const uint4*>(A + (size_t)(m0 + r) * n + k0 + cg);
        }
#pragma unroll
        for (int l = 0; l < 4; l++) {
            int e = tid + 256 * l;
            int r = e >> 4, cg = (e & 15) * 8;
            *reinterpret_cast<uint4*>(&Zs[r][cg]) =
                *reinterpret_cast<const uint4*>(Zc + (size_t)(k0 + r) * 128 + cg);
        }
        __syncthreads();
#pragma unroll
        for (int kk = 0; kk < 64; kk += 16) {
            wmma::fragment<wmma::matrix_a, 16, 16, 16, __nv_bfloat16, wmma::row_major> af[2];
            wmma::fragment<wmma::matrix_b, 16, 16, 16, __nv_bfloat16, wmma::row_major> bf[2];
#pragma unroll
            for (int i = 0; i < 2; i++)
                wmma::load_matrix_sync(af[i], &As[wm * 32 + 16 * i][kk], 72);
#pragma unroll
            for (int j = 0; j < 2; j++)
                wmma::load_matrix_sync(bf[j], &Zs[kk][wn * 32 + 16 * j], 136);
#pragma unroll
            for (int i = 0; i < 2; i++)
#pragma unroll
                for (int j = 0; j < 2; j++)
                    wmma::mma_sync(acc[i][j], af[i], bf[j], acc[i][j]);
        }
        __syncthreads();
    }
#pragma unroll
    for (int i = 0; i < 2; i++)
#pragma unroll
        for (int j = 0; j < 2; j++)
            wmma::store_matrix_sync(P + ((size_t)ks * n + m0 + wm * 32 + 16 * i) * 128 +
                                        wn * 32 + 16 * j,
                                    acc[i][j], 128, wmma::mem_row_major);
}

__global__ void k_prop_epi(const float* __restrict__ P, const float* __restrict__ Y,
                           const float* __restrict__ dinv, const float* __restrict__ selfc,
                           const float* __restrict__ bias, float* __restrict__ O,
                           int n, int c, int KS, int dorelu) {
    int t = blockIdx.x * 256 + threadIdx.x;
    if (t >= n * c) return;
    int i = t / c, j = t % c;
    float s = 0.f;
    for (int ks = 0; ks < KS; ks++) {
        const float* pr = P + ((size_t)ks * n + i) * 128;
        s += pr[j] + pr[64 + j];
    }
    float o = dinv[i] * s + selfc[i] * Y[t] + bias[j];
    if (dorelu) o = fmaxf(o, 0.f);
    O[t] = o;
}

// ---- fused gather + augment GEMM ----
// C'[r][c] = sum_k B[perm_r][k] * B[k][perm_c], B = A with diag->1, diag(C')=0.
// A row-major bf16, AT = A^T row-major bf16. BM=BN=128, BK=64, 3-stage cp.async.
// mode 0: write fp32 C. mode 1: write bf16 Ob + ObT + deg row sums (atomic).
#define AUG_SMEM (3 * 2 * 128 * 72 * 2)
__global__ __launch_bounds__(256) void k_aug(const __nv_bfloat16* __restrict__ A,
                                             const __nv_bfloat16* __restrict__ AT,
                                             const int* __restrict__ permv,
                                             int K, int Nn, float* __restrict__ C,
                                             __nv_bfloat16* __restrict__ Ob,
                                             __nv_bfloat16* __restrict__ ObT,
                                             float* __restrict__ deg, int mode) {
    extern __shared__ char smraw[];
    __nv_bfloat16* AsB = reinterpret_cast<__nv_bfloat16*>(smraw);
    __nv_bfloat16* BsB = AsB + 3 * 128 * 72;
    __shared__ int spa[128], spb[128];
    const int LDK = 72;
    int tid = threadIdx.x;
    int warp = tid >> 5;
    int wm = warp >> 2, wn = warp & 3;  // 2 x 4 warps, warp tile 64x32
    int m0 = blockIdx.y * 128, n0 = blockIdx.x * 128;

    if (tid < 128) spa[tid] = permv[m0 + tid];
    else spb[tid - 128] = permv[n0 + tid - 128];
    __syncthreads();

    auto load_tiles = [&](int st, int k0) {
        __nv_bfloat16* as = AsB + st * 128 * LDK;
        __nv_bfloat16* bs = BsB + st * 128 * LDK;
#pragma unroll
        for (int l = 0; l < 4; l++) {
            int e = tid + 256 * l;
            int r = e >> 3, cg = (e & 7) * 8;
            cpa16(as + r * LDK + cg, A + (size_t)spa[r] * K + k0 + cg);
            cpa16(bs + r * LDK + cg, AT + (size_t)spb[r] * K + k0 + cg);
        }
        cpcommit();
    };

    wmma::fragment<wmma::accumulator, 16, 16, 16, float> acc[4][2];
#pragma unroll
    for (int i = 0; i < 4; i++)
#pragma unroll
        for (int j = 0; j < 2; j++) wmma::fill_fragment(acc[i][j], 0.f);

    int nIter = K / 64;
    load_tiles(0, 0);
    load_tiles(1, 64);
    for (int it = 0; it < nIter; it++) {
        int st = it % 3;
        cpwait1();
        __syncthreads();
        // diag fix: element (global k == perm) -> 1
        int k0 = it * 64;
        if (tid < 128) {
            int d = spa[tid] - k0;
            if (d >= 0 && d < 64) AsB[st * 128 * LDK + tid * LDK + d] = __float2bfloat16(1.f);
        } else {
            int r = tid - 128;
            int d = spb[r] - k0;
            if (d >= 0 && d < 64) BsB[st * 128 * LDK + r * LDK + d] = __float2bfloat16(1.f);
        }
        __syncthreads();
        if (it + 2 < nIter) load_tiles((it + 2) % 3, (it + 2) * 64);
        __nv_bfloat16* as = AsB + st * 128 * LDK;
        __nv_bfloat16* bs = BsB + st * 128 * LDK;
#pragma unroll
        for (int kk = 0; kk < 64; kk += 16) {
            wmma::fragment<wmma::matrix_a, 16, 16, 16, __nv_bfloat16, wmma::row_major> af[4];
            wmma::fragment<wmma::matrix_b, 16, 16, 16, __nv_bfloat16, wmma::col_major> bf[2];
#pragma unroll
            for (int i = 0; i < 4; i++)
                wmma::load_matrix_sync(af[i], as + (wm * 64 + 16 * i) * LDK + kk, LDK);
#pragma unroll
            for (int j = 0; j < 2; j++)
                wmma::load_matrix_sync(bf[j], bs + (wn * 32 + 16 * j) * LDK + kk, LDK);
#pragma unroll
            for (int i = 0; i < 4; i++)
#pragma unroll
                for (int j = 0; j < 2; j++)
                    wmma::mma_sync(acc[i][j], af[i], bf[j], acc[i][j]);
        }
    }
    __syncthreads();
    // stage C tile in smem
    float* Cs = reinterpret_cast<float*>(smraw);
    const int LDC = 132;
#pragma unroll
    for (int i = 0; i < 4; i++)
#pragma unroll
        for (int j = 0; j < 2; j++)
            wmma::store_matrix_sync(Cs + (wm * 64 + 16 * i) * LDC + wn * 32 + 16 * j,
                                    acc[i][j], LDC, wmma::mem_row_major);
    __syncthreads();
    if (m0 == n0 && tid < 128) Cs[tid * LDC + tid] = 0.f;
    __syncthreads();
    if (mode == 0) {
#pragma unroll
        for (int l = 0; l < 16; l++) {
            int e = tid + 256 * l;
            int r = e >> 5, cq = (e & 31) * 4;
            float4 v;
            v.x = Cs[r * LDC + cq];
            v.y = Cs[r * LDC + cq + 1];
            v.z = Cs[r * LDC + cq + 2];
            v.w = Cs[r * LDC + cq + 3];
            *reinterpret_cast<float4*>(C + (size_t)(m0 + r) * Nn + n0 + cq) = v;
        }
    } else {
#pragma unroll
        for (int l = 0; l < 32; l++) {
            int e = tid + 256 * l;
            int r = e >> 6, c2 = (e & 63) * 2;
            *reinterpret_cast<__nv_bfloat162*>(Ob + (size_t)(m0 + r) * Nn + n0 + c2) =
                __floats2bfloat162_rn(Cs[r * LDC + c2], Cs[r * LDC + c2 + 1]);
        }
#pragma unroll
        for (int l = 0; l < 32; l++) {
            int e = tid + 256 * l;
            int c = e >> 6, r2 = (e & 63) * 2;
            *reinterpret_cast<__nv_bfloat162*>(ObT + (size_t)(n0 + c) * Nn + m0 + r2) =
                __floats2bfloat162_rn(Cs[r2 * LDC + c], Cs[(r2 + 1) * LDC + c]);
        }
        if (tid < 128) {
            float s = 0.f;
            for (int c = 0; c < 128; c++) s += Cs[tid * LDC + c];
            atomicAdd(&deg[m0 + tid], s);
        }
    }
}

// ---- fp32 SIMT path for small levels ----
__global__ void k_xw(const float* __restrict__ X, const float* __restrict__ W,
                     const float* __restrict__ dinv,
                     float* __restrict__ Y, float* __restrict__ Z,
                     int n, int cin, int cout) {
    int j = blockIdx.x * 32 + threadIdx.x;
    int i = blockIdx.y * 8 + threadIdx.y;
    if (i >= n || j >= cout) return;
    const float* xr = X + (size_t)i * cin;
    float acc = 0.f;
    for (int k = 0; k < cin; k++) acc = fmaf(xr[k], W[(size_t)k * cout + j], acc);
    Y[(size_t)i * cout + j] = acc;
    Z[(size_t)i * cout + j] = acc * dinv[i];
}

__global__ __launch_bounds__(256) void k_gcnmm_sp(
    const float* __restrict__ A, const float* __restrict__ Z,
    float* __restrict__ P, int n, int c, int KS) {
    __shared__ float As[32][65];
    __shared__ float Zs[32][32];
    int tid = threadIdx.x;
    int m0 = blockIdx.y * 64;
    int n0c = blockIdx.x * 32;
    int ks = blockIdx.z;
    int chunk = n / KS;
    int kbeg = ks * chunk, kend = kbeg + chunk;
    int r0 = tid >> 5, colt = tid & 31;
    float acc[8] = {0, 0, 0, 0, 0, 0, 0, 0};
    for (int k0 = kbeg; k0 < kend; k0 += 32) {
#pragma unroll
        for (int l = 0; l < 2; l++) {
            int e = tid + 256 * l;
            int row = e >> 3, qc = (e & 7) * 4;
            float4 v = *reinterpret_cast<const float4*>(A + (size_t)(m0 + row) * n + k0 + qc);
            As[qc + 0][row] = v.x; As[qc + 1][row] = v.y;
            As[qc + 2][row] = v.z; As[qc + 3][row] = v.w;
        }
        {
            int row = tid >> 3, qc = (tid & 7) * 4;
            int gk = k0 + row;
#pragma unroll
            for (int u = 0; u < 4; u++) {
                int gc = n0c + qc + u;
                Zs[row][qc + u] = (gc < c) ? Z[(size_t)gk * c + gc] : 0.f;
            }
        }
        __syncthreads();
#pragma unroll
        for (int k = 0; k < 32; k++) {
            float zv = Zs[k][colt];
#pragma unroll
            for (int u = 0; u < 8; u++) acc[u] = fmaf(As[k][r0 + 8 * u], zv, acc[u]);
        }
        __syncthreads();
    }
    int gc = n0c + colt;
    if (gc < c) {
#pragma unroll
        for (int u = 0; u < 8; u++) {
            int gi = m0 + r0 + 8 * u;
            P[((size_t)ks * n + gi) * c + gc] = acc[u];
        }
    }
}

__global__ void k_gcn_epi(const float* __restrict__ P, const float* __restrict__ Y,
                          const float* __restrict__ dinv, const float* __restrict__ selfc,
                          const float* __restrict__ bias, float* __restrict__ O,
                          int n, int c, int KS, int dorelu) {
    int t = blockIdx.x * 256 + threadIdx.x;
    if (t >= n * c) return;
    int i = t / c, j = t % c;
    float s = 0.f;
    size_t stride = (size_t)n * c;
    for (int ks = 0; ks < KS; ks++) s += P[ks * stride + t];
    float o = dinv[i] * s + selfc[i] * Y[t] + bias[j];
    if (dorelu) o = fmaxf(o, 0.f);
    O[t] = o;
}

__global__ void k_grow_f32(const float* __restrict__ A, int n,
                           const int* __restrict__ perm, int ksel,
                           float* __restrict__ Br) {
    size_t t = (size_t)blockIdx.x * 256 + threadIdx.x;
    if (t >= (size_t)ksel * n) return;
    int r = t / n, k = t % n;
    int pr = perm[r];
    Br[t] = (k == pr) ? 1.0f : A[(size_t)pr * n + k];
}

__global__ void k_gcol_f32(const float* __restrict__ A, int n,
                           const int* __restrict__ perm, int ksel,
                           float* __restrict__ Bc) {
    size_t t = (size_t)blockIdx.x * 256 + threadIdx.x;
    if (t >= (size_t)n * ksel) return;
    int k = t / ksel, c = t % ksel;
    int pc = perm[c];
    Bc[t] = (k == pc) ? 1.0f : A[(size_t)k * n + pc];
}

__global__ __launch_bounds__(256) void k_gemm64(const float* __restrict__ Br,
                                                const float* __restrict__ Bc,
                                                float* __restrict__ C, int K, int Nn) {
    __shared__ float As[16][65];
    __shared__ float Bs[16][65];
    int tid = threadIdx.x;
    int m0 = blockIdx.y * 64, n0 = blockIdx.x * 64;
    int ty = tid >> 4, tx = tid & 15;
    float acc[4][4] = {};
    for (int k0 = 0; k0 < K; k0 += 16) {
#pragma unroll
        for (int l = 0; l < 4; l++) {
            int e = tid + 256 * l;
            int row = e >> 4, kk = e & 15;
            As[kk][row] = Br[(size_t)(m0 + row) * K + k0 + kk];
        }
#pragma unroll
        for (int l = 0; l < 4; l++) {
            int e = tid + 256 * l;
            int row = e >> 6, col = e & 63;
            Bs[row][col] = Bc[(size_t)(k0 + row) * Nn + n0 + col];
        }
        __syncthreads();
#pragma unroll
        for (int kk = 0; kk < 16; kk++) {
            float a[4], b[4];
#pragma unroll
            for (int i = 0; i < 4; i++) a[i] = As[kk][ty * 4 + i];
#pragma unroll
            for (int j = 0; j < 4; j++) b[j] = Bs[kk][tx * 4 + j];
#pragma unroll
            for (int i = 0; i < 4; i++)
#pragma unroll
                for (int j = 0; j < 4; j++) acc[i][j] = fmaf(a[i], b[j], acc[i][j]);
        }
        __syncthreads();
    }
#pragma unroll
    for (int i = 0; i < 4; i++)
#pragma unroll
        for (int j = 0; j < 4; j++)
            C[(size_t)(m0 + ty * 4 + i) * Nn + n0 + tx * 4 + j] = acc[i][j];
}

__global__ void k_zerodiag(float* __restrict__ C, int n) {
    int i = blockIdx.x * 256 + threadIdx.x;
    if (i < n) C[(size_t)i * n + i] = 0.f;
}

__global__ void k_score(const float* __restrict__ X, const float* __restrict__ w,
                        int n, int c, float* __restrict__ score) {
    int row = blockIdx.x;
    __shared__ float sh[128];
    const float* xr = X + (size_t)row * c;
    float wsq = 0.f, dot = 0.f;
    for (int k = threadIdx.x; k < c; k += 128) {
        float wv = w[k];
        wsq += wv * wv;
        dot += xr[k] * wv;
    }
    sh[threadIdx.x] = wsq;
    __syncthreads();
    for (int o = 64; o > 0; o >>= 1) {
        if (threadIdx.x < o) sh[threadIdx.x] += sh[threadIdx.x + o];
        __syncthreads();
    }
    float wn = sh[0];
    __syncthreads();
    sh[threadIdx.x] = dot;
    __syncthreads();
    for (int o = 64; o > 0; o >>= 1) {
        if (threadIdx.x < o) sh[threadIdx.x] += sh[threadIdx.x + o];
        __syncthreads();
    }
    if (threadIdx.x == 0) score[row] = tanhf(sh[0] / sqrtf(wn));
}

__global__ void k_rank(const float* __restrict__ score, int n, int k,
                       int* __restrict__ perm, float* __restrict__ vals) {
    int i = blockIdx.x * 256 + threadIdx.x;
    if (i >= n) return;
    float si = score[i];
    const float4* s4 = reinterpret_cast<const float4*>(score);
    int rank = 0;
    for (int j4 = 0; j4 < n / 4; j4++) {
        float4 s = s4[j4];
        int j = j4 * 4;
        rank += (s.x > si) || (s.x == si && j < i);
        rank += (s.y > si) || (s.y == si && j + 1 < i);
        rank += (s.z > si) || (s.z == si && j + 2 < i);
        rank += (s.w > si) || (s.w == si && j + 3 < i);
    }
    if (rank < k) {
        perm[rank] = i;
        vals[rank] = si;
    }
}

__global__ void k_gatherx(const float* __restrict__ X, int c,
                          const int* __restrict__ perm, const float* __restrict__ vals,
                          int k, float* __restrict__ O) {
    int t = blockIdx.x * 256 + threadIdx.x;
    if (t >= k * c) return;
    int r = t / c, j = t % c;
    O[t] = X[(size_t)perm[r] * c + j] * vals[r];
}

__global__ void k_concat(const float* __restrict__ R, int n, int c, float* __restrict__ O) {
    int t = blockIdx.x * 256 + threadIdx.x;
    int tot = n * 2 * c;
    if (t >= tot) return;
    int i = t / (2 * c), j = t % (2 * c);
    O[t] = (j < c) ? R[(size_t)i * c + j] : 0.f;
}

__global__ void k_scatter(float* __restrict__ O, int ostride, int off,
                          const int* __restrict__ perm, int k,
                          const float* __restrict__ S, int sstride, int nc) {
    int t = blockIdx.x * 256 + threadIdx.x;
    if (t >= k * nc) return;
    int r = t / nc, j = t % nc;
    O[(size_t)perm[r] * ostride + off + j] = S[(size_t)r * sstride + j];
}

__global__ void k_softmax(const float* __restrict__ X, float* __restrict__ O, int n, int c) {
    int i = blockIdx.x * 256 + threadIdx.x;
    if (i >= n) return;
    const float* xr = X + (size_t)i * c;
    float m = -1e30f;
    for (int j = 0; j < c; j++) m = fmaxf(m, xr[j]);
    float s = 0.f;
    for (int j = 0; j < c; j++) s += expf(xr[j] - m);
    float inv = 1.0f / s;
    for (int j = 0; j < c; j++) O[(size_t)i * c + j] = expf(xr[j] - m) * inv;
}

// ---------------- host orchestration ----------------

struct Ptrs {
    float *y, *z, *P;
    __nv_bfloat16* zc;
};

static void gcn_tc(const __nv_bfloat16* Ab, int n, const float* xin, int cin,
                   const float* W, const float* b, int c, bool relu, float* out,
                   const float* dinv, const float* selfc, const Ptrs& q) {
    const int KS = 4;
    k_xw_cat<<<(n + 15) / 16, 256>>>(xin, W, dinv, q.y, q.zc, n, cin, c);
    k_prop<<<dim3(n / 64, KS), 256>>>(Ab, q.zc, q.P, n, KS);
    k_prop_epi<<<(n * c + 255) / 256, 256>>>(q.P, q.y, dinv, selfc, b, out, n, c, KS, relu ? 1 : 0);
}

static void gcn_f32(const float* A, int n, const float* xin, int cin,
                    const float* W, const float* b, int cout, bool relu, float* out,
                    const float* dinv, const float* selfc, const Ptrs& q) {
    const int KS = 8;
    dim3 bx(32, 8);
    dim3 gx((cout + 31) / 32, (n + 7) / 8);
    k_xw<<<gx, bx>>>(xin, W, dinv, q.y, q.z, n, cin, cout);
    dim3 g2((cout + 31) / 32, n / 64, KS);
    k_gcnmm_sp<<<g2, 256>>>(A, q.z, q.P, n, cout, KS);
    k_gcn_epi<<<(n * cout + 255) / 256, 256>>>(q.P, q.y, dinv, selfc, b, out, n, cout, KS, relu ? 1 : 0);
}

extern "C" void kernel_launch(void* const* d_in, const int* in_sizes, int n_in,
                              void* d_out, int out_size) {
    const float* x = (const float*)d_in[0];
    const int* ei = (const int*)d_in[1];
    const float *Wd[5], *bd[5], *p[4], *Wu[4], *bu[4];
    for (int i = 0; i < 5; i++) { Wd[i] = (const float*)d_in[2 + 2 * i]; bd[i] = (const float*)d_in[3 + 2 * i]; }
    for (int i = 0; i < 4; i++) p[i] = (const float*)d_in[12 + i];
    for (int i = 0; i < 4; i++) { Wu[i] = (const float*)d_in[16 + 2 * i]; bu[i] = (const float*)d_in[17 + 2 * i]; }
    const float* Wo = (const float*)d_in[24];
    const float* bo = (const float*)d_in[25];

    static bool attrset = false;
    if (!attrset) {
        cudaFuncSetAttribute(k_aug, cudaFuncAttributeMaxDynamicSharedMemorySize, AUG_SMEM);
        attrset = true;
    }

    __nv_bfloat16 *A0b, *A0tb, *A1b, *A1tb;
    float *A2, *A3, *A4, *xs0, *xs1, *xs2, *xs3, *xa, *xb;
    float *Brf, *Bcf, *score, *vals, *deg0, *deg1;
    float *di0, *sf0, *di1, *sf1, *di2, *sf2, *di3, *sf3, *di4, *sf4;
    int *pm0, *pm1, *pm2, *pm3;
    Ptrs q;
    cudaGetSymbolAddress((void**)&A0b, dA0b);
    cudaGetSymbolAddress((void**)&A0tb, dA0tb);
    cudaGetSymbolAddress((void**)&A1b, dA1b);
    cudaGetSymbolAddress((void**)&A1tb, dA1tb);
    cudaGetSymbolAddress((void**)&A2, dA2);
    cudaGetSymbolAddress((void**)&A3, dA3);
    cudaGetSymbolAddress((void**)&A4, dA4);
    cudaGetSymbolAddress((void**)&Brf, dBrf);
    cudaGetSymbolAddress((void**)&Bcf, dBcf);
    cudaGetSymbolAddress((void**)&q.P, dP);
    cudaGetSymbolAddress((void**)&xs0, dxs0);
    cudaGetSymbolAddress((void**)&xs1, dxs1);
    cudaGetSymbolAddress((void**)&xs2, dxs2);
    cudaGetSymbolAddress((void**)&xs3, dxs3);
    cudaGetSymbolAddress((void**)&xa, dxa);
    cudaGetSymbolAddress((void**)&xb, dxb);
    cudaGetSymbolAddress((void**)&q.y, dybuf);
    cudaGetSymbolAddress((void**)&q.z, dzbuf);
    q.zc = (__nv_bfloat16*)q.z;
    cudaGetSymbolAddress((void**)&deg0, ddeg0);
    cudaGetSymbolAddress((void**)&deg1, ddeg1);
    cudaGetSymbolAddress((void**)&di0, dinv0); cudaGetSymbolAddress((void**)&sf0, dself0);
    cudaGetSymbolAddress((void**)&di1, dinv1); cudaGetSymbolAddress((void**)&sf1, dself1);
    cudaGetSymbolAddress((void**)&di2, dinv2); cudaGetSymbolAddress((void**)&sf2, dself2);
    cudaGetSymbolAddress((void**)&di3, dinv3); cudaGetSymbolAddress((void**)&sf3, dself3);
    cudaGetSymbolAddress((void**)&di4, dinv4); cudaGetSymbolAddress((void**)&sf4, dself4);
    cudaGetSymbolAddress((void**)&score, dscorev);
    cudaGetSymbolAddress((void**)&vals, dvalsv);
    cudaGetSymbolAddress((void**)&pm0, dperm0);
    cudaGetSymbolAddress((void**)&pm1, dperm1);
    cudaGetSymbolAddress((void**)&pm2, dperm2);
    cudaGetSymbolAddress((void**)&pm3, dperm3);

    // build adjacency directly in bf16; transpose + degree fused
    cudaMemsetAsync(A0b, 0, (size_t)N0 * N0 * sizeof(__nv_bfloat16));
    cudaMemsetAsync(deg0, 0, N0 * sizeof(float));
    cudaMemsetAsync(deg1, 0, 2048 * sizeof(float));
    k_edges<<<EDG / 256, 256>>>(ei, A0b);
    k_trans_deg<<<dim3(N0 / 32, N0 / 32), dim3(32, 8)>>>(A0b, A0tb, deg0, N0);
    k_degfin<<<N0 / 256, 256>>>(A0b, deg0, N0, di0, sf0);

    // GCN0
    gcn_tc(A0b, 4096, x, 128, Wd[0], bd[0], 32, true, xs0, di0, sf0, q);

    // ---- level 1: fused gather+augment -> bf16 A1 + A1^T + deg ----
    k_score<<<4096, 128>>>(xs0, p[0], 4096, 32, score);
    k_rank<<<16, 256>>>(score, 4096, 2048, pm0, vals);
    k_gatherx<<<(2048 * 32 + 255) / 256, 256>>>(xs0, 32, pm0, vals, 2048, xa);
    k_aug<<<dim3(16, 16), 256, AUG_SMEM>>>(A0b, A0tb, pm0, 4096, 2048,
                                           nullptr, A1b, A1tb, deg1, 1);
    k_degfin<<<2048 / 256, 256>>>(A1b, deg1, 2048, di1, sf1);
    gcn_tc(A1b, 2048, xa, 32, Wd[1], bd[1], 64, true, xs1, di1, sf1, q);

    // ---- level 2: fused gather+augment -> fp32 A2 ----
    k_score<<<2048, 128>>>(xs1, p[1], 2048, 64, score);
    k_rank<<<8, 256>>>(score, 2048, 1024, pm1, vals);
    k_gatherx<<<(1024 * 64 + 255) / 256, 256>>>(xs1, 64, pm1, vals, 1024, xa);
    k_aug<<<dim3(8, 8), 256, AUG_SMEM>>>(A1b, A1tb, pm1, 2048, 1024,
                                         A2, nullptr, nullptr, nullptr, 0);
    k_deg<<<1024, 256>>>(A2, 1024, di2, sf2);
    gcn_f32(A2, 1024, xa, 64, Wd[2], bd[2], 128, true, xs2, di2, sf2, q);

    // ---- level 3 (fp32) ----
    k_score<<<1024, 128>>>(xs2, p[2], 1024, 128, score);
    k_rank<<<4, 256>>>(score, 1024, 512, pm2, vals);
    k_gatherx<<<(512 * 128 + 255) / 256, 256>>>(xs2, 128, pm2, vals, 512, xa);
    k_grow_f32<<<(512 * 1024 + 255) / 256, 256>>>(A2, 1024, pm2, 512, Brf);
    k_gcol_f32<<<(1024 * 512 + 255) / 256, 256>>>(A2, 1024, pm2, 512, Bcf);
    k_gemm64<<<dim3(8, 8), 256>>>(Brf, Bcf, A3, 1024, 512);
    k_zerodiag<<<2, 256>>>(A3, 512);
    k_deg<<<512, 256>>>(A3, 512, di3, sf3);
    gcn_f32(A3, 512, xa, 128, Wd[3], bd[3], 256, true, xs3, di3, sf3, q);

    // ---- level 4 (fp32) ----
    k_score<<<512, 128>>>(xs3, p[3], 512, 256, score);
    k_rank<<<2, 256>>>(score, 512, 256, pm3, vals);
    k_gatherx<<<(256 * 256 + 255) / 256, 256>>>(xs3, 256, pm3, vals, 256, xa);
    k_grow_f32<<<(256 * 512 + 255) / 256, 256>>>(A3, 512, pm3, 256, Brf);
    k_gcol_f32<<<(512 * 256 + 255) / 256, 256>>>(A3, 512, pm3, 256, Bcf);
    k_gemm64<<<dim3(4, 4), 256>>>(Brf, Bcf, A4, 512, 256);
    k_zerodiag<<<1, 256>>>(A4, 256);
    k_deg<<<256, 256>>>(A4, 256, di4, sf4);
    gcn_f32(A4, 256, xa, 256, Wd[4], bd[4], 512, true, xb, di4, sf4, q);

    // ---- up path ----
    k_concat<<<(512 * 512 + 255) / 256, 256>>>(xs3, 512, 256, xa);
    k_scatter<<<(256 * 256 + 255) / 256, 256>>>(xa, 512, 256, pm3, 256, xb, 512, 256);
    gcn_f32(A3, 512, xa, 512, Wu[0], bu[0], 256, true, xb, di3, sf3, q);

    k_concat<<<(1024 * 256 + 255) / 256, 256>>>(xs2, 1024, 128, xa);
    k_scatter<<<(512 * 128 + 255) / 256, 256>>>(xa, 256, 128, pm2, 512, xb, 256, 128);
    gcn_f32(A2, 1024, xa, 256, Wu[1], bu[1], 128, true, xb, di2, sf2, q);

    k_concat<<<(2048 * 128 + 255) / 256, 256>>>(xs1, 2048, 64, xa);
    k_scatter<<<(1024 * 64 + 255) / 256, 256>>>(xa, 128, 64, pm1, 1024, xb, 128, 64);
    gcn_tc(A1b, 2048, xa, 128, Wu[2], bu[2], 64, true, xb, di1, sf1, q);

    k_concat<<<(4096 * 64 + 255) / 256, 256>>>(xs0, 4096, 32, xa);
    k_scatter<<<(2048 * 32 + 255) / 256, 256>>>(xa, 64, 32, pm0, 2048, xb, 64, 32);
    gcn_tc(A0b, 4096, xa, 64, Wu[3], bu[3], 32, false, xb, di0, sf0, q);

    // ---- final GCN + softmax ----
    gcn_tc(A0b, 4096, xb, 32, Wo, bo, 37, false, xa, di0, sf0, q);
    k_softmax<<<16, 256>>>(xa, (float*)d_out, 4096, 37);
}

// round 8
// speedup vs baseline: 6.9584x; 1.0217x over previous
#include <cuda_runtime.h>
#include <cuda_bf16.h>
#include <mma.h>
#include <math.h>

using namespace nvcuda;

#define N0 4096
#define EDG 131072

// ---------------- device scratch ----------------
__device__ __nv_bfloat16 dA0b[(size_t)N0 * N0];
__device__ __nv_bfloat16 dA0tb[(size_t)N0 * N0];
__device__ __nv_bfloat16 dA1b[2048 * 2048];
__device__ __nv_bfloat16 dA1tb[2048 * 2048];
__device__ float dA2[1024 * 1024];
__device__ float dA3[512 * 512];
__device__ float dA4[256 * 256];
__device__ float dBrf[512 * 1024];
__device__ float dBcf[1024 * 512];
__device__ float dP[8 * 4096 * 128];
__device__ float dxs0[4096 * 32];
__device__ float dxs1[2048 * 64];
__device__ float dxs2[1024 * 128];
__device__ float dxs3[512 * 256];
__device__ float dxa[4096 * 512];
__device__ float dxb[4096 * 512];
__device__ float dybuf[4096 * 512];
__device__ float dzbuf[4096 * 512];
__device__ float ddeg0[4096], ddeg1[2048];
__device__ float dinv0[4096], dself0[4096];
__device__ float dinv1[2048], dself1[2048];
__device__ float dinv2[1024], dself2[1024];
__device__ float dinv3[512], dself3[512];
__device__ float dinv4[256], dself4[256];
__device__ float dscorev[4096];
__device__ float dvalsv[2048];
__device__ int dperm0[2048];
__device__ int dperm1[1024];
__device__ int dperm2[512];
__device__ int dperm3[256];
__device__ int dinvi0[4096];
__device__ int dinvi1[2048];
__device__ int dinvi2[1024];
__device__ int dinvi3[512];

// ---------------- helpers ----------------
__device__ __forceinline__ void cpa16(void* s, const void* g) {
    unsigned sa = (unsigned)__cvta_generic_to_shared(s);
    asm volatile("cp.async.cg.shared.global [%0], [%1], 16;\n" ::"r"(sa), "l"(g));
}
__device__ __forceinline__ void cpcommit() { asm volatile("cp.async.commit_group;\n"); }
__device__ __forceinline__ void cpwait1() { asm volatile("cp.async.wait_group 1;\n"); }

__device__ __forceinline__ void bf16AtomicInc(__nv_bfloat16* addr) {
    unsigned short* p = (unsigned short*)addr;
    unsigned short old = *p;
    while (true) {
        __nv_bfloat16_raw r;
        r.x = old;
        float f = __bfloat162float(__nv_bfloat16(r)) + 1.0f;
        __nv_bfloat16 nb = __float2bfloat16(f);
        __nv_bfloat16_raw nr = (__nv_bfloat16_raw)nb;
        unsigned short prev = atomicCAS(p, old, nr.x);
        if (prev == old) break;
        old = prev;
    }
}

// ---------------- kernels ----------------

__global__ void k_edges(const int* __restrict__ ei, __nv_bfloat16* __restrict__ A) {
    int e = blockIdx.x * blockDim.x + threadIdx.x;
    if (e < EDG) {
        int s = ei[e];
        int d = ei[EDG + e];
        bf16AtomicInc(&A[(size_t)d * N0 + s]);
    }
}

__global__ void k_trans_deg(const __nv_bfloat16* __restrict__ Ab,
                            __nv_bfloat16* __restrict__ AbT,
                            float* __restrict__ deg, int n) {
    __shared__ __nv_bfloat16 tile[32][33];
    int bx = blockIdx.x * 32, by = blockIdx.y * 32;
    int tx = threadIdx.x, ty = threadIdx.y;
    for (int r = ty; r < 32; r += 8)
        tile[r][tx] = Ab[(size_t)(by + r) * n + bx + tx];
    __syncthreads();
    for (int r = ty; r < 32; r += 8)
        AbT[(size_t)(bx + r) * n + by + tx] = tile[tx][r];
    if (ty == 0) {
        float s = 0.f;
        for (int c = 0; c < 32; c++) s += __bfloat162float(tile[tx][c]);
        atomicAdd(&deg[by + tx], s);
    }
}

__global__ void k_degfin(const __nv_bfloat16* __restrict__ Ab, const float* __restrict__ deg,
                         int n, float* __restrict__ dinv, float* __restrict__ selfc) {
    int i = blockIdx.x * 256 + threadIdx.x;
    if (i >= n) return;
    float diag = __bfloat162float(Ab[(size_t)i * n + i]);
    float fill = (diag == 0.0f) ? 2.0f : 0.0f;
    float d = deg[i] + fill;
    float di = (d > 0.f) ? (1.0f / sqrtf(d)) : 0.f;
    dinv[i] = di;
    selfc[i] = di * di * fill;
}

__global__ void k_deg(const float* __restrict__ A, int n,
                      float* __restrict__ dinv, float* __restrict__ selfc) {
    int row = blockIdx.x;
    __shared__ float sh[256];
    const float* ar = A + (size_t)row * n;
    float s = 0.f;
    for (int j = threadIdx.x; j < n; j += 256) s += ar[j];
    sh[threadIdx.x] = s;
    __syncthreads();
    for (int o = 128; o > 0; o >>= 1) {
        if (threadIdx.x < o) sh[threadIdx.x] += sh[threadIdx.x + o];
        __syncthreads();
    }
    if (threadIdx.x == 0) {
        float diag = ar[row];
        float fill = (diag == 0.0f) ? 2.0f : 0.0f;
        float deg = sh[0] + fill;
        float di = (deg > 0.f) ? (1.0f / sqrtf(deg)) : 0.f;
        dinv[row] = di;
        selfc[row] = di * di * fill;
    }
}

// Y = X@W ; Zcat = [bf16 hi | bf16 lo] of dinv*Y, 128 wide. 4 rows/block.
__global__ void k_xw_cat(const float* __restrict__ X, const float* __restrict__ W,
                         const float* __restrict__ dinv, float* __restrict__ Y,
                         __nv_bfloat16* __restrict__ Zc, int n, int cin, int c) {
    int j = threadIdx.x & 63;
    int i = blockIdx.x * 4 + (threadIdx.x >> 6);
    if (i >= n) return;
    __nv_bfloat16 hb = __float2bfloat16(0.f), lb = hb;
    if (j < c) {
        const float* xr = X + (size_t)i * cin;
        float acc = 0.f;
        for (int k = 0; k < cin; k += 4) {
            float4 xv = *reinterpret_cast<const float4*>(xr + k);
            acc = fmaf(xv.x, W[(size_t)k * c + j], acc);
            acc = fmaf(xv.y, W[(size_t)(k + 1) * c + j], acc);
            acc = fmaf(xv.z, W[(size_t)(k + 2) * c + j], acc);
            acc = fmaf(xv.w, W[(size_t)(k + 3) * c + j], acc);
        }
        Y[(size_t)i * c + j] = acc;
        float z = acc * dinv[i];
        hb = __float2bfloat16(z);
        lb = __float2bfloat16(z - __bfloat162float(hb));
    }
    Zc[(size_t)i * 128 + j] = hb;
    Zc[(size_t)i * 128 + 64 + j] = lb;
}

// P[ks] = A(bf16)[n][n] @ Zcat[n][128], split-K
__global__ __launch_bounds__(256) void k_prop(const __nv_bfloat16* __restrict__ A,
                                              const __nv_bfloat16* __restrict__ Zc,
                                              float* __restrict__ P, int n, int KS) {
    __shared__ __nv_bfloat16 As[64][72];
    __shared__ __nv_bfloat16 Zs[64][136];
    int tid = threadIdx.x;
    int warp = tid >> 5;
    int wm = warp >> 2, wn = warp & 3;
    int m0 = blockIdx.x * 64;
    int ks = blockIdx.y;
    int chunk = n / KS;
    int kbeg = ks * chunk, kend = kbeg + chunk;

    wmma::fragment<wmma::accumulator, 16, 16, 16, float> acc[2][2];
#pragma unroll
    for (int i = 0; i < 2; i++)
#pragma unroll
        for (int j = 0; j < 2; j++) wmma::fill_fragment(acc[i][j], 0.f);

    for (int k0 = kbeg; k0 < kend; k0 += 64) {
#pragma unroll
        for (int l = 0; l < 2; l++) {
            int e = tid + 256 * l;
            int r = e >> 3, cg = (e & 7) * 8;
            *reinterpret_cast<uint4*>(&As[r][cg]) =
                *reinterpret_cast<const uint4*>(A + (size_t)(m0 + r) * n + k0 + cg);
        }
#pragma unroll
        for (int l = 0; l < 4; l++) {
            int e = tid + 256 * l;
            int r = e >> 4, cg = (e & 15) * 8;
            *reinterpret_cast<uint4*>(&Zs[r][cg]) =
                *reinterpret_cast<const uint4*>(Zc + (size_t)(k0 + r) * 128 + cg);
        }
        __syncthreads();
#pragma unroll
        for (int kk = 0; kk < 64; kk += 16) {
            wmma::fragment<wmma::matrix_a, 16, 16, 16, __nv_bfloat16, wmma::row_major> af[2];
            wmma::fragment<wmma::matrix_b, 16, 16, 16, __nv_bfloat16, wmma::row_major> bf[2];
#pragma unroll
            for (int i = 0; i < 2; i++)
                wmma::load_matrix_sync(af[i], &As[wm * 32 + 16 * i][kk], 72);
#pragma unroll
            for (int j = 0; j < 2; j++)
                wmma::load_matrix_sync(bf[j], &Zs[kk][wn * 32 + 16 * j], 136);
#pragma unroll
            for (int i = 0; i < 2; i++)
#pragma unroll
                for (int j = 0; j < 2; j++)
                    wmma::mma_sync(acc[i][j], af[i], bf[j], acc[i][j]);
        }
        __syncthreads();
    }
#pragma unroll
    for (int i = 0; i < 2; i++)
#pragma unroll
        for (int j = 0; j < 2; j++)
            wmma::store_matrix_sync(P + ((size_t)ks * n + m0 + wm * 32 + 16 * i) * 128 +
                                        wn * 32 + 16 * j,
                                    acc[i][j], 128, wmma::mem_row_major);
}

__global__ void k_prop_epi(const float* __restrict__ P, const float* __restrict__ Y,
                           const float* __restrict__ dinv, const float* __restrict__ selfc,
                           const float* __restrict__ bias, float* __restrict__ O,
                           int n, int c, int KS, int dorelu) {
    int t = blockIdx.x * 256 + threadIdx.x;
    if (t >= n * c) return;
    int i = t / c, j = t % c;
    float s = 0.f;
    for (int ks = 0; ks < KS; ks++) {
        const float* pr = P + ((size_t)ks * n + i) * 128;
        s += pr[j] + pr[64 + j];
    }
    float o = dinv[i] * s + selfc[i] * Y[t] + bias[j];
    if (dorelu) o = fmaxf(o, 0.f);
    O[t] = o;
}

// ---- fused gather + augment GEMM (WMMA, 3-stage cp.async) ----
// C'[r][c] = sum_k B[perm_r][k] * B[k][perm_c], B = A with diag->1, diag(C')=0.
// mode 0: write fp32 C. mode 1: write bf16 Ob + ObT + deg row sums (atomic).
#define AUG_SMEM (3 * 2 * 128 * 72 * 2)
__global__ __launch_bounds__(256) void k_aug(const __nv_bfloat16* __restrict__ A,
                                             const __nv_bfloat16* __restrict__ AT,
                                             const int* __restrict__ permv,
                                             int K, int Nn, float* __restrict__ C,
                                             __nv_bfloat16* __restrict__ Ob,
                                             __nv_bfloat16* __restrict__ ObT,
                                             float* __restrict__ deg, int mode) {
    extern __shared__ char smraw[];
    __nv_bfloat16* AsB = reinterpret_cast<__nv_bfloat16*>(smraw);
    __nv_bfloat16* BsB = AsB + 3 * 128 * 72;
    __shared__ int spa[128], spb[128];
    const int LDK = 72;
    int tid = threadIdx.x;
    int warp = tid >> 5;
    int wm = warp >> 2, wn = warp & 3;
    int m0 = blockIdx.y * 128, n0 = blockIdx.x * 128;

    if (tid < 128) spa[tid] = permv[m0 + tid];
    else spb[tid - 128] = permv[n0 + tid - 128];
    __syncthreads();

    auto load_tiles = [&](int st, int k0) {
        __nv_bfloat16* as = AsB + st * 128 * LDK;
        __nv_bfloat16* bs = BsB + st * 128 * LDK;
#pragma unroll
        for (int l = 0; l < 4; l++) {
            int e = tid + 256 * l;
            int r = e >> 3, cg = (e & 7) * 8;
            cpa16(as + r * LDK + cg, A + (size_t)spa[r] * K + k0 + cg);
            cpa16(bs + r * LDK + cg, AT + (size_t)spb[r] * K + k0 + cg);
        }
        cpcommit();
    };

    wmma::fragment<wmma::accumulator, 16, 16, 16, float> acc[4][2];
#pragma unroll
    for (int i = 0; i < 4; i++)
#pragma unroll
        for (int j = 0; j < 2; j++) wmma::fill_fragment(acc[i][j], 0.f);

    int nIter = K / 64;
    load_tiles(0, 0);
    load_tiles(1, 64);
    for (int it = 0; it < nIter; it++) {
        int st = it % 3;
        cpwait1();
        __syncthreads();
        int k0 = it * 64;
        if (tid < 128) {
            int d = spa[tid] - k0;
            if (d >= 0 && d < 64) AsB[st * 128 * LDK + tid * LDK + d] = __float2bfloat16(1.f);
        } else {
            int r = tid - 128;
            int d = spb[r] - k0;
            if (d >= 0 && d < 64) BsB[st * 128 * LDK + r * LDK + d] = __float2bfloat16(1.f);
        }
        __syncthreads();
        if (it + 2 < nIter) load_tiles((it + 2) % 3, (it + 2) * 64);
        __nv_bfloat16* as = AsB + st * 128 * LDK;
        __nv_bfloat16* bs = BsB + st * 128 * LDK;
#pragma unroll
        for (int kk = 0; kk < 64; kk += 16) {
            wmma::fragment<wmma::matrix_a, 16, 16, 16, __nv_bfloat16, wmma::row_major> af[4];
            wmma::fragment<wmma::matrix_b, 16, 16, 16, __nv_bfloat16, wmma::col_major> bf[2];
#pragma unroll
            for (int i = 0; i < 4; i++)
                wmma::load_matrix_sync(af[i], as + (wm * 64 + 16 * i) * LDK + kk, LDK);
#pragma unroll
            for (int j = 0; j < 2; j++)
                wmma::load_matrix_sync(bf[j], bs + (wn * 32 + 16 * j) * LDK + kk, LDK);
#pragma unroll
            for (int i = 0; i < 4; i++)
#pragma unroll
                for (int j = 0; j < 2; j++)
                    wmma::mma_sync(acc[i][j], af[i], bf[j], acc[i][j]);
        }
    }
    __syncthreads();
    float* Cs = reinterpret_cast<float*>(smraw);
    const int LDC = 132;
#pragma unroll
    for (int i = 0; i < 4; i++)
#pragma unroll
        for (int j = 0; j < 2; j++)
            wmma::store_matrix_sync(Cs + (wm * 64 + 16 * i) * LDC + wn * 32 + 16 * j,
                                    acc[i][j], LDC, wmma::mem_row_major);
    __syncthreads();
    if (m0 == n0 && tid < 128) Cs[tid * LDC + tid] = 0.f;
    __syncthreads();
    if (mode == 0) {
#pragma unroll
        for (int l = 0; l < 16; l++) {
            int e = tid + 256 * l;
            int r = e >> 5, cq = (e & 31) * 4;
            float4 v;
            v.x = Cs[r * LDC + cq];
            v.y = Cs[r * LDC + cq + 1];
            v.z = Cs[r * LDC + cq + 2];
            v.w = Cs[r * LDC + cq + 3];
            *reinterpret_cast<float4*>(C + (size_t)(m0 + r) * Nn + n0 + cq) = v;
        }
    } else {
#pragma unroll
        for (int l = 0; l < 32; l++) {
            int e = tid + 256 * l;
            int r = e >> 6, c2 = (e & 63) * 2;
            *reinterpret_cast<__nv_bfloat162*>(Ob + (size_t)(m0 + r) * Nn + n0 + c2) =
                __floats2bfloat162_rn(Cs[r * LDC + c2], Cs[r * LDC + c2 + 1]);
        }
#pragma unroll
        for (int l = 0; l < 32; l++) {
            int e = tid + 256 * l;
            int c = e >> 6, r2 = (e & 63) * 2;
            *reinterpret_cast<__nv_bfloat162*>(ObT + (size_t)(n0 + c) * Nn + m0 + r2) =
                __floats2bfloat162_rn(Cs[r2 * LDC + c], Cs[(r2 + 1) * LDC + c]);
        }
        if (tid < 128) {
            float s = 0.f;
            for (int c = 0; c < 128; c++) s += Cs[tid * LDC + c];
            atomicAdd(&deg[m0 + tid], s);
        }
    }
}

// ---- fp32 SIMT path for small levels ----
__global__ void k_xw(const float* __restrict__ X, const float* __restrict__ W,
                     const float* __restrict__ dinv,
                     float* __restrict__ Y, float* __restrict__ Z,
                     int n, int cin, int cout) {
    int j = blockIdx.x * 32 + threadIdx.x;
    int i = blockIdx.y * 8 + threadIdx.y;
    if (i >= n || j >= cout) return;
    const float* xr = X + (size_t)i * cin;
    float acc = 0.f;
    for (int k = 0; k < cin; k++) acc = fmaf(xr[k], W[(size_t)k * cout + j], acc);
    Y[(size_t)i * cout + j] = acc;
    Z[(size_t)i * cout + j] = acc * dinv[i];
}

__global__ __launch_bounds__(256) void k_gcnmm_sp(
    const float* __restrict__ A, const float* __restrict__ Z,
    float* __restrict__ P, int n, int c, int KS) {
    __shared__ float As[32][65];
    __shared__ float Zs[32][32];
    int tid = threadIdx.x;
    int m0 = blockIdx.y * 64;
    int n0c = blockIdx.x * 32;
    int ks = blockIdx.z;
    int chunk = n / KS;
    int kbeg = ks * chunk, kend = kbeg + chunk;
    int r0 = tid >> 5, colt = tid & 31;
    float acc[8] = {0, 0, 0, 0, 0, 0, 0, 0};
    for (int k0 = kbeg; k0 < kend; k0 += 32) {
#pragma unroll
        for (int l = 0; l < 2; l++) {
            int e = tid + 256 * l;
            int row = e >> 3, qc = (e & 7) * 4;
            float4 v = *reinterpret_cast<const float4*>(A + (size_t)(m0 + row) * n + k0 + qc);
            As[qc + 0][row] = v.x; As[qc + 1][row] = v.y;
            As[qc + 2][row] = v.z; As[qc + 3][row] = v.w;
        }
        {
            int row = tid >> 3, qc = (tid & 7) * 4;
            int gk = k0 + row;
#pragma unroll
            for (int u = 0; u < 4; u++) {
                int gc = n0c + qc + u;
                Zs[row][qc + u] = (gc < c) ? Z[(size_t)gk * c + gc] : 0.f;
            }
        }
        __syncthreads();
#pragma unroll
        for (int k = 0; k < 32; k++) {
            float zv = Zs[k][colt];
#pragma unroll
            for (int u = 0; u < 8; u++) acc[u] = fmaf(As[k][r0 + 8 * u], zv, acc[u]);
        }
        __syncthreads();
    }
    int gc = n0c + colt;
    if (gc < c) {
#pragma unroll
        for (int u = 0; u < 8; u++) {
            int gi = m0 + r0 + 8 * u;
            P[((size_t)ks * n + gi) * c + gc] = acc[u];
        }
    }
}

__global__ void k_gcn_epi(const float* __restrict__ P, const float* __restrict__ Y,
                          const float* __restrict__ dinv, const float* __restrict__ selfc,
                          const float* __restrict__ bias, float* __restrict__ O,
                          int n, int c, int KS, int dorelu) {
    int t = blockIdx.x * 256 + threadIdx.x;
    if (t >= n * c) return;
    int i = t / c, j = t % c;
    float s = 0.f;
    size_t stride = (size_t)n * c;
    for (int ks = 0; ks < KS; ks++) s += P[ks * stride + t];
    float o = dinv[i] * s + selfc[i] * Y[t] + bias[j];
    if (dorelu) o = fmaxf(o, 0.f);
    O[t] = o;
}

__global__ void k_grow_f32(const float* __restrict__ A, int n,
                           const int* __restrict__ perm, int ksel,
                           float* __restrict__ Br) {
    size_t t = (size_t)blockIdx.x * 256 + threadIdx.x;
    if (t >= (size_t)ksel * n) return;
    int r = t / n, k = t % n;
    int pr = perm[r];
    Br[t] = (k == pr) ? 1.0f : A[(size_t)pr * n + k];
}

__global__ void k_gcol_f32(const float* __restrict__ A, int n,
                           const int* __restrict__ perm, int ksel,
                           float* __restrict__ Bc) {
    size_t t = (size_t)blockIdx.x * 256 + threadIdx.x;
    if (t >= (size_t)n * ksel) return;
    int k = t / ksel, c = t % ksel;
    int pc = perm[c];
    Bc[t] = (k == pc) ? 1.0f : A[(size_t)k * n + pc];
}

__global__ __launch_bounds__(256) void k_gemm64(const float* __restrict__ Br,
                                                const float* __restrict__ Bc,
                                                float* __restrict__ C, int K, int Nn) {
    __shared__ float As[16][65];
    __shared__ float Bs[16][65];
    int tid = threadIdx.x;
    int m0 = blockIdx.y * 64, n0 = blockIdx.x * 64;
    int ty = tid >> 4, tx = tid & 15;
    float acc[4][4] = {};
    for (int k0 = 0; k0 < K; k0 += 16) {
#pragma unroll
        for (int l = 0; l < 4; l++) {
            int e = tid + 256 * l;
            int row = e >> 4, kk = e & 15;
            As[kk][row] = Br[(size_t)(m0 + row) * K + k0 + kk];
        }
#pragma unroll
        for (int l = 0; l < 4; l++) {
            int e = tid + 256 * l;
            int row = e >> 6, col = e & 63;
            Bs[row][col] = Bc[(size_t)(k0 + row) * Nn + n0 + col];
        }
        __syncthreads();
#pragma unroll
        for (int kk = 0; kk < 16; kk++) {
            float a[4], b[4];
#pragma unroll
            for (int i = 0; i < 4; i++) a[i] = As[kk][ty * 4 + i];
#pragma unroll
            for (int j = 0; j < 4; j++) b[j] = Bs[kk][tx * 4 + j];
#pragma unroll
            for (int i = 0; i < 4; i++)
#pragma unroll
                for (int j = 0; j < 4; j++) acc[i][j] = fmaf(a[i], b[j], acc[i][j]);
        }
        __syncthreads();
    }
#pragma unroll
    for (int i = 0; i < 4; i++)
#pragma unroll
        for (int j = 0; j < 4; j++)
            C[(size_t)(m0 + ty * 4 + i) * Nn + n0 + tx * 4 + j] = acc[i][j];
}

__global__ void k_zerodiag(float* __restrict__ C, int n) {
    int i = blockIdx.x * 256 + threadIdx.x;
    if (i < n) C[(size_t)i * n + i] = 0.f;
}

__global__ void k_score(const float* __restrict__ X, const float* __restrict__ w,
                        int n, int c, float* __restrict__ score) {
    int row = blockIdx.x;
    __shared__ float sh[128];
    const float* xr = X + (size_t)row * c;
    float wsq = 0.f, dot = 0.f;
    for (int k = threadIdx.x; k < c; k += 128) {
        float wv = w[k];
        wsq += wv * wv;
        dot += xr[k] * wv;
    }
    sh[threadIdx.x] = wsq;
    __syncthreads();
    for (int o = 64; o > 0; o >>= 1) {
        if (threadIdx.x < o) sh[threadIdx.x] += sh[threadIdx.x + o];
        __syncthreads();
    }
    float wn = sh[0];
    __syncthreads();
    sh[threadIdx.x] = dot;
    __syncthreads();
    for (int o = 64; o > 0; o >>= 1) {
        if (threadIdx.x < o) sh[threadIdx.x] += sh[threadIdx.x + o];
        __syncthreads();
    }
    if (threadIdx.x == 0) score[row] = tanhf(sh[0] / sqrtf(wn));
}

// rank + perm + vals + inverse index
__global__ void k_rank(const float* __restrict__ score, int n, int k,
                       int* __restrict__ perm, float* __restrict__ vals,
                       int* __restrict__ inv) {
    int i = blockIdx.x * 256 + threadIdx.x;
    if (i >= n) return;
    float si = score[i];
    const float4* s4 = reinterpret_cast<const float4*>(score);
    int rank = 0;
    for (int j4 = 0; j4 < n / 4; j4++) {
        float4 s = s4[j4];
        int j = j4 * 4;
        rank += (s.x > si) || (s.x == si && j < i);
        rank += (s.y > si) || (s.y == si && j + 1 < i);
        rank += (s.z > si) || (s.z == si && j + 2 < i);
        rank += (s.w > si) || (s.w == si && j + 3 < i);
    }
    if (rank < k) {
        perm[rank] = i;
        vals[rank] = si;
        inv[i] = rank;
    } else {
        inv[i] = -1;
    }
}

__global__ void k_gatherx(const float* __restrict__ X, int c,
                          const int* __restrict__ perm, const float* __restrict__ vals,
                          int k, float* __restrict__ O) {
    int t = blockIdx.x * 256 + threadIdx.x;
    if (t >= k * c) return;
    int r = t / c, j = t % c;
    O[t] = X[(size_t)perm[r] * c + j] * vals[r];
}

// fused unpool: O[n][2c]: first half = res, second half = X[inv[i]] or 0
__global__ void k_unpool(const float* __restrict__ R, int n, int c,
                         const float* __restrict__ X, int sx,
                         const int* __restrict__ inv, float* __restrict__ O) {
    int t = blockIdx.x * 256 + threadIdx.x;
    int tot = n * 2 * c;
    if (t >= tot) return;
    int i = t / (2 * c), j = t % (2 * c);
    float v;
    if (j < c) {
        v = R[(size_t)i * c + j];
    } else {
        int r = inv[i];
        v = (r >= 0) ? X[(size_t)r * sx + (j - c)] : 0.f;
    }
    O[t] = v;
}

__global__ void k_softmax(const float* __restrict__ X, float* __restrict__ O, int n, int c) {
    int i = blockIdx.x * 256 + threadIdx.x;
    if (i >= n) return;
    const float* xr = X + (size_t)i * c;
    float m = -1e30f;
    for (int j = 0; j < c; j++) m = fmaxf(m, xr[j]);
    float s = 0.f;
    for (int j = 0; j < c; j++) s += expf(xr[j] - m);
    float inv = 1.0f / s;
    for (int j = 0; j < c; j++) O[(size_t)i * c + j] = expf(xr[j] - m) * inv;
}

// ---------------- host orchestration ----------------

struct Ptrs {
    float *y, *z, *P;
    __nv_bfloat16* zc;
};

static void gcn_tc(const __nv_bfloat16* Ab, int n, const float* xin, int cin,
                   const float* W, const float* b, int c, bool relu, float* out,
                   const float* dinv, const float* selfc, const Ptrs& q) {
    const int KS = 8;
    k_xw_cat<<<(n + 3) / 4, 256>>>(xin, W, dinv, q.y, q.zc, n, cin, c);
    k_prop<<<dim3(n / 64, KS), 256>>>(Ab, q.zc, q.P, n, KS);
    k_prop_epi<<<(n * c + 255) / 256, 256>>>(q.P, q.y, dinv, selfc, b, out, n, c, KS, relu ? 1 : 0);
}

static void gcn_f32(const float* A, int n, const float* xin, int cin,
                    const float* W, const float* b, int cout, bool relu, float* out,
                    const float* dinv, const float* selfc, const Ptrs& q) {
    const int KS = 8;
    dim3 bx(32, 8);
    dim3 gx((cout + 31) / 32, (n + 7) / 8);
    k_xw<<<gx, bx>>>(xin, W, dinv, q.y, q.z, n, cin, cout);
    dim3 g2((cout + 31) / 32, n / 64, KS);
    k_gcnmm_sp<<<g2, 256>>>(A, q.z, q.P, n, cout, KS);
    k_gcn_epi<<<(n * cout + 255) / 256, 256>>>(q.P, q.y, dinv, selfc, b, out, n, cout, KS, relu ? 1 : 0);
}

extern "C" void kernel_launch(void* const* d_in, const int* in_sizes, int n_in,
                              void* d_out, int out_size) {
    const float* x = (const float*)d_in[0];
    const int* ei = (const int*)d_in[1];
    const float *Wd[5], *bd[5], *p[4], *Wu[4], *bu[4];
    for (int i = 0; i < 5; i++) { Wd[i] = (const float*)d_in[2 + 2 * i]; bd[i] = (const float*)d_in[3 + 2 * i]; }
    for (int i = 0; i < 4; i++) p[i] = (const float*)d_in[12 + i];
    for (int i = 0; i < 4; i++) { Wu[i] = (const float*)d_in[16 + 2 * i]; bu[i] = (const float*)d_in[17 + 2 * i]; }
    const float* Wo = (const float*)d_in[24];
    const float* bo = (const float*)d_in[25];

    static bool attrset = false;
    if (!attrset) {
        cudaFuncSetAttribute(k_aug, cudaFuncAttributeMaxDynamicSharedMemorySize, AUG_SMEM);
        attrset = true;
    }

    __nv_bfloat16 *A0b, *A0tb, *A1b, *A1tb;
    float *A2, *A3, *A4, *xs0, *xs1, *xs2, *xs3, *xa, *xb;
    float *Brf, *Bcf, *score, *vals, *deg0, *deg1;
    float *di0, *sf0, *di1, *sf1, *di2, *sf2, *di3, *sf3, *di4, *sf4;
    int *pm0, *pm1, *pm2, *pm3;
    int *iv0, *iv1, *iv2, *iv3;
    Ptrs q;
    cudaGetSymbolAddress((void**)&A0b, dA0b);
    cudaGetSymbolAddress((void**)&A0tb, dA0tb);
    cudaGetSymbolAddress((void**)&A1b, dA1b);
    cudaGetSymbolAddress((void**)&A1tb, dA1tb);
    cudaGetSymbolAddress((void**)&A2, dA2);
    cudaGetSymbolAddress((void**)&A3, dA3);
    cudaGetSymbolAddress((void**)&A4, dA4);
    cudaGetSymbolAddress((void**)&Brf, dBrf);
    cudaGetSymbolAddress((void**)&Bcf, dBcf);
    cudaGetSymbolAddress((void**)&q.P, dP);
    cudaGetSymbolAddress((void**)&xs0, dxs0);
    cudaGetSymbolAddress((void**)&xs1, dxs1);
    cudaGetSymbolAddress((void**)&xs2, dxs2);
    cudaGetSymbolAddress((void**)&xs3, dxs3);
    cudaGetSymbolAddress((void**)&xa, dxa);
    cudaGetSymbolAddress((void**)&xb, dxb);
    cudaGetSymbolAddress((void**)&q.y, dybuf);
    cudaGetSymbolAddress((void**)&q.z, dzbuf);
    q.zc = (__nv_bfloat16*)q.z;
    cudaGetSymbolAddress((void**)&deg0, ddeg0);
    cudaGetSymbolAddress((void**)&deg1, ddeg1);
    cudaGetSymbolAddress((void**)&di0, dinv0); cudaGetSymbolAddress((void**)&sf0, dself0);
    cudaGetSymbolAddress((void**)&di1, dinv1); cudaGetSymbolAddress((void**)&sf1, dself1);
    cudaGetSymbolAddress((void**)&di2, dinv2); cudaGetSymbolAddress((void**)&sf2, dself2);
    cudaGetSymbolAddress((void**)&di3, dinv3); cudaGetSymbolAddress((void**)&sf3, dself3);
    cudaGetSymbolAddress((void**)&di4, dinv4); cudaGetSymbolAddress((void**)&sf4, dself4);
    cudaGetSymbolAddress((void**)&score, dscorev);
    cudaGetSymbolAddress((void**)&vals, dvalsv);
    cudaGetSymbolAddress((void**)&pm0, dperm0);
    cudaGetSymbolAddress((void**)&pm1, dperm1);
    cudaGetSymbolAddress((void**)&pm2, dperm2);
    cudaGetSymbolAddress((void**)&pm3, dperm3);
    cudaGetSymbolAddress((void**)&iv0, dinvi0);
    cudaGetSymbolAddress((void**)&iv1, dinvi1);
    cudaGetSymbolAddress((void**)&iv2, dinvi2);
    cudaGetSymbolAddress((void**)&iv3, dinvi3);

    // build adjacency directly in bf16; transpose + degree fused
    cudaMemsetAsync(A0b, 0, (size_t)N0 * N0 * sizeof(__nv_bfloat16));
    cudaMemsetAsync(deg0, 0, N0 * sizeof(float));
    cudaMemsetAsync(deg1, 0, 2048 * sizeof(float));
    k_edges<<<EDG / 256, 256>>>(ei, A0b);
    k_trans_deg<<<dim3(N0 / 32, N0 / 32), dim3(32, 8)>>>(A0b, A0tb, deg0, N0);
    k_degfin<<<N0 / 256, 256>>>(A0b, deg0, N0, di0, sf0);

    // GCN0
    gcn_tc(A0b, 4096, x, 128, Wd[0], bd[0], 32, true, xs0, di0, sf0, q);

    // ---- level 1: fused gather+augment -> bf16 A1 + A1^T + deg ----
    k_score<<<4096, 128>>>(xs0, p[0], 4096, 32, score);
    k_rank<<<16, 256>>>(score, 4096, 2048, pm0, vals, iv0);
    k_gatherx<<<(2048 * 32 + 255) / 256, 256>>>(xs0, 32, pm0, vals, 2048, xa);
    k_aug<<<dim3(16, 16), 256, AUG_SMEM>>>(A0b, A0tb, pm0, 4096, 2048,
                                           nullptr, A1b, A1tb, deg1, 1);
    k_degfin<<<2048 / 256, 256>>>(A1b, deg1, 2048, di1, sf1);
    gcn_tc(A1b, 2048, xa, 32, Wd[1], bd[1], 64, true, xs1, di1, sf1, q);

    // ---- level 2: fused gather+augment -> fp32 A2 ----
    k_score<<<2048, 128>>>(xs1, p[1], 2048, 64, score);
    k_rank<<<8, 256>>>(score, 2048, 1024, pm1, vals, iv1);
    k_gatherx<<<(1024 * 64 + 255) / 256, 256>>>(xs1, 64, pm1, vals, 1024, xa);
    k_aug<<<dim3(8, 8), 256, AUG_SMEM>>>(A1b, A1tb, pm1, 2048, 1024,
                                         A2, nullptr, nullptr, nullptr, 0);
    k_deg<<<1024, 256>>>(A2, 1024, di2, sf2);
    gcn_f32(A2, 1024, xa, 64, Wd[2], bd[2], 128, true, xs2, di2, sf2, q);

    // ---- level 3 (fp32) ----
    k_score<<<1024, 128>>>(xs2, p[2], 1024, 128, score);
    k_rank<<<4, 256>>>(score, 1024, 512, pm2, vals, iv2);
    k_gatherx<<<(512 * 128 + 255) / 256, 256>>>(xs2, 128, pm2, vals, 512, xa);
    k_grow_f32<<<(512 * 1024 + 255) / 256, 256>>>(A2, 1024, pm2, 512, Brf);
    k_gcol_f32<<<(1024 * 512 + 255) / 256, 256>>>(A2, 1024, pm2, 512, Bcf);
    k_gemm64<<<dim3(8, 8), 256>>>(Brf, Bcf, A3, 1024, 512);
    k_zerodiag<<<2, 256>>>(A3, 512);
    k_deg<<<512, 256>>>(A3, 512, di3, sf3);
    gcn_f32(A3, 512, xa, 128, Wd[3], bd[3], 256, true, xs3, di3, sf3, q);

    // ---- level 4 (fp32) ----
    k_score<<<512, 128>>>(xs3, p[3], 512, 256, score);
    k_rank<<<2, 256>>>(score, 512, 256, pm3, vals, iv3);
    k_gatherx<<<(256 * 256 + 255) / 256, 256>>>(xs3, 256, pm3, vals, 256, xa);
    k_grow_f32<<<(256 * 512 + 255) / 256, 256>>>(A3, 512, pm3, 256, Brf);
    k_gcol_f32<<<(512 * 256 + 255) / 256, 256>>>(A3, 512, pm3, 256, Bcf);
    k_gemm64<<<dim3(4, 4), 256>>>(Brf, Bcf, A4, 512, 256);
    k_zerodiag<<<1, 256>>>(A4, 256);
    k_deg<<<256, 256>>>(A4, 256, di4, sf4);
    gcn_f32(A4, 256, xa, 256, Wd[4], bd[4], 512, true, xb, di4, sf4, q);

    // ---- up path (fused unpool) ----
    k_unpool<<<(512 * 512 + 255) / 256, 256>>>(xs3, 512, 256, xb, 512, iv3, xa);
    gcn_f32(A3, 512, xa, 512, Wu[0], bu[0], 256, true, xb, di3, sf3, q);

    k_unpool<<<(1024 * 256 + 255) / 256, 256>>>(xs2, 1024, 128, xb, 256, iv2, xa);
    gcn_f32(A2, 1024, xa, 256, Wu[1], bu[1], 128, true, xb, di2, sf2, q);

    k_unpool<<<(2048 * 128 + 255) / 256, 256>>>(xs1, 2048, 64, xb, 128, iv1, xa);
    gcn_tc(A1b, 2048, xa, 128, Wu[2], bu[2], 64, true, xb, di1, sf1, q);

    k_unpool<<<(4096 * 64 + 255) / 256, 256>>>(xs0, 4096, 32, xb, 64, iv0, xa);
    gcn_tc(A0b, 4096, xa, 64, Wu[3], bu[3], 32, false, xb, di0, sf0, q);

    // ---- final GCN + softmax ----
    gcn_tc(A0b, 4096, xb, 32, Wo, bo, 37, false, xa, di0, sf0, q);
    k_softmax<<<16, 256>>>(xa, (float*)d_out, 4096, 37);
}

// round 9
// speedup vs baseline: 10.2592x; 1.4744x over previous
#include <cuda_runtime.h>
#include <cuda_bf16.h>
#include <mma.h>
#include <math.h>

using namespace nvcuda;

#define N0 4096
#define EDG 131072

// ---------------- device scratch ----------------
__device__ __nv_bfloat16 dA1b[2048 * 2048];
__device__ __nv_bfloat16 dA1tb[2048 * 2048];
__device__ float dC1[2048 * 2048];
__device__ float dA2[1024 * 1024];
__device__ float dA3[512 * 512];
__device__ float dA4[256 * 256];
__device__ float dBrf[512 * 1024];
__device__ float dBcf[1024 * 512];
__device__ float dP[8 * 4096 * 128];
__device__ float dxs0[4096 * 32];
__device__ float dxs1[2048 * 64];
__device__ float dxs2[1024 * 128];
__device__ float dxs3[512 * 256];
__device__ float dxa[4096 * 512];
__device__ float dxb[4096 * 512];
__device__ float dybuf[4096 * 512];
__device__ float dzbuf[4096 * 512];
__device__ float ddeg1[2048];
__device__ float dinv0[4096], dself0[4096];
__device__ float dinv1[2048], dself1[2048];
__device__ float dinv2[1024], dself2[1024];
__device__ float dinv3[512], dself3[512];
__device__ float dinv4[256], dself4[256];
__device__ float dscorev[4096];
__device__ float dvalsv[2048];
__device__ int dperm0[2048];
__device__ int dperm1[1024];
__device__ int dperm2[512];
__device__ int dperm3[256];
__device__ int dinvi0[4096];
__device__ int dinvi1[2048];
__device__ int dinvi2[1024];
__device__ int dinvi3[512];
// sparse structures for A0
__device__ int dcall[4096], dselfn[4096], dcsrc[4096], dcdst[4096];
__device__ int doffS[4097], doffD[4097], dheadS[4096], dheadD[4096];
__device__ int doutl[EDG], dinl[EDG];

// ---------------- helpers ----------------
__device__ __forceinline__ void cpa16(void* s, const void* g) {
    unsigned sa = (unsigned)__cvta_generic_to_shared(s);
    asm volatile("cp.async.cg.shared.global [%0], [%1], 16;\n" ::"r"(sa), "l"(g));
}
__device__ __forceinline__ void cpcommit() { asm volatile("cp.async.commit_group;\n"); }
__device__ __forceinline__ void cpwait1() { asm volatile("cp.async.wait_group 1;\n"); }

// ---------------- sparse build kernels ----------------

__global__ void k_ecnt(const int* __restrict__ ei, int* __restrict__ call,
                       int* __restrict__ selfn, int* __restrict__ csrc,
                       int* __restrict__ cdst) {
    int e = blockIdx.x * 256 + threadIdx.x;
    if (e >= EDG) return;
    int s = ei[e], d = ei[EDG + e];
    atomicAdd(&call[d], 1);
    if (s == d) {
        atomicAdd(&selfn[d], 1);
    } else {
        atomicAdd(&csrc[s], 1);
        atomicAdd(&cdst[d], 1);
    }
}

// exclusive scan of 4096 ints; blockIdx 0 -> (c0,off0,head0), 1 -> (c1,off1,head1)
__global__ void k_scan(const int* __restrict__ c0, int* __restrict__ off0, int* __restrict__ head0,
                       const int* __restrict__ c1, int* __restrict__ off1, int* __restrict__ head1) {
    const int* c = blockIdx.x ? c1 : c0;
    int* off = blockIdx.x ? off1 : off0;
    int* head = blockIdx.x ? head1 : head0;
    __shared__ int sh[1024];
    int tid = threadIdx.x;
    int base = tid * 4;
    int v0 = c[base], v1 = c[base + 1], v2 = c[base + 2], v3 = c[base + 3];
    sh[tid] = v0 + v1 + v2 + v3;
    __syncthreads();
    for (int o = 1; o < 1024; o <<= 1) {
        int x = (tid >= o) ? sh[tid - o] : 0;
        __syncthreads();
        sh[tid] += x;
        __syncthreads();
    }
    int excl = tid ? sh[tid - 1] : 0;
    int p0 = excl, p1 = excl + v0, p2 = p1 + v1, p3 = p2 + v2;
    off[base] = p0; off[base + 1] = p1; off[base + 2] = p2; off[base + 3] = p3;
    head[base] = p0; head[base + 1] = p1; head[base + 2] = p2; head[base + 3] = p3;
    if (tid == 1023) off[4096] = sh[1023];
}

__global__ void k_fill(const int* __restrict__ ei, int* __restrict__ headS,
                       int* __restrict__ headD, int* __restrict__ outl,
                       int* __restrict__ inl) {
    int e = blockIdx.x * 256 + threadIdx.x;
    if (e >= EDG) return;
    int s = ei[e], d = ei[EDG + e];
    if (s == d) return;
    int p = atomicAdd(&headS[s], 1);
    outl[p] = d;
    int q = atomicAdd(&headD[d], 1);
    inl[q] = s;
}

__global__ void k_degfin0(const int* __restrict__ call, const int* __restrict__ selfn,
                          int n, float* __restrict__ dinv, float* __restrict__ selfc) {
    int i = blockIdx.x * 256 + threadIdx.x;
    if (i >= n) return;
    float fill = (selfn[i] == 0) ? 2.0f : 0.0f;
    float d = (float)call[i] + fill;
    float di = (d > 0.f) ? (1.0f / sqrtf(d)) : 0.f;
    dinv[i] = di;
    selfc[i] = di * di * fill;
}

// path-pair counting: for intermediate k, all (out i, in j) pairs with both selected
#define MAXD 192
__global__ void k_pairs(const int* __restrict__ offS, const int* __restrict__ outl,
                        const int* __restrict__ offD, const int* __restrict__ inl,
                        const int* __restrict__ inv, float* __restrict__ C1, int ld) {
    int k = blockIdx.x;
    __shared__ int so[MAXD], si[MAXD];
    __shared__ int cnto, cnti;
    int tid = threadIdx.x;
    if (tid == 0) { cnto = 0; cnti = 0; }
    __syncthreads();
    int b0 = offS[k], b1 = offS[k + 1];
    for (int t = b0 + tid; t < b1; t += 256) {
        int r = inv[outl[t]];
        if (r >= 0) { int p = atomicAdd(&cnto, 1); so[p] = r; }
    }
    int c0 = offD[k], c1 = offD[k + 1];
    for (int t = c0 + tid; t < c1; t += 256) {
        int r = inv[inl[t]];
        if (r >= 0) { int p = atomicAdd(&cnti, 1); si[p] = r; }
    }
    __syncthreads();
    int no = cnto, ni = cnti;
    int tot = no * ni;
    for (int t = tid; t < tot; t += 256) {
        int i = t / ni, j = t % ni;
        atomicAdd(&C1[(size_t)so[i] * ld + si[j]], 1.0f);
    }
}

// 2*Ahat term: each non-self edge (s,d) with both selected adds 2 at [inv d, inv s]
__global__ void k_addA(const int* __restrict__ ei, const int* __restrict__ inv,
                       float* __restrict__ C1, int ld) {
    int e = blockIdx.x * 256 + threadIdx.x;
    if (e >= EDG) return;
    int s = ei[e], d = ei[EDG + e];
    if (s == d) return;
    int rs = inv[s], rd = inv[d];
    if (rs >= 0 && rd >= 0) atomicAdd(&C1[(size_t)rd * ld + rs], 2.0f);
}

// finalize: C1 -> bf16 A1 + A1^T (diag 0) + deg row sums
__global__ void k_a1fin(const float* __restrict__ C1, __nv_bfloat16* __restrict__ Ab,
                        __nv_bfloat16* __restrict__ AbT, float* __restrict__ deg, int n) {
    __shared__ __nv_bfloat16 tile[32][33];
    int bx = blockIdx.x * 32, by = blockIdx.y * 32;
    int tx = threadIdx.x, ty = threadIdx.y;
    for (int r = ty; r < 32; r += 8) {
        int gi = by + r, gj = bx + tx;
        float v = (gi == gj) ? 0.f : C1[(size_t)gi * n + gj];
        __nv_bfloat16 b = __float2bfloat16(v);
        Ab[(size_t)gi * n + gj] = b;
        tile[r][tx] = b;
    }
    __syncthreads();
    for (int r = ty; r < 32; r += 8)
        AbT[(size_t)(bx + r) * n + by + tx] = tile[tx][r];
    if (ty == 0) {
        float s = 0.f;
        for (int c = 0; c < 32; c++) s += __bfloat162float(tile[tx][c]);
        atomicAdd(&deg[by + tx], s);
    }
}

// sparse GCN propagation: out[d] = relu?(dinv_d*(sum_in Z[src] + selfn_d*Z[d]) + selfc_d*Y[d] + b)
__global__ void k_sprop(const int* __restrict__ offD, const int* __restrict__ inl,
                        const int* __restrict__ selfn, const float* __restrict__ Z,
                        const float* __restrict__ Y, const float* __restrict__ dinv,
                        const float* __restrict__ selfc, const float* __restrict__ bias,
                        float* __restrict__ O, int c, int dorelu) {
    int d = blockIdx.x;
    int j = threadIdx.x;
    if (j >= c) return;
    int b0 = offD[d], b1 = offD[d + 1];
    float acc = 0.f;
    for (int t = b0; t < b1; t++) {
        int s = inl[t];
        acc += Z[(size_t)s * c + j];
    }
    int sn = selfn[d];
    if (sn) acc += (float)sn * Z[(size_t)d * c + j];
    float o = dinv[d] * acc + selfc[d] * Y[(size_t)d * c + j] + bias[j];
    if (dorelu) o = fmaxf(o, 0.f);
    O[(size_t)d * c + j] = o;
}

// ---------------- dense kernels (levels 1-4) ----------------

__global__ void k_degfin(const __nv_bfloat16* __restrict__ Ab, const float* __restrict__ deg,
                         int n, float* __restrict__ dinv, float* __restrict__ selfc) {
    int i = blockIdx.x * 256 + threadIdx.x;
    if (i >= n) return;
    float diag = __bfloat162float(Ab[(size_t)i * n + i]);
    float fill = (diag == 0.0f) ? 2.0f : 0.0f;
    float d = deg[i] + fill;
    float di = (d > 0.f) ? (1.0f / sqrtf(d)) : 0.f;
    dinv[i] = di;
    selfc[i] = di * di * fill;
}

__global__ void k_deg(const float* __restrict__ A, int n,
                      float* __restrict__ dinv, float* __restrict__ selfc) {
    int row = blockIdx.x;
    __shared__ float sh[256];
    const float* ar = A + (size_t)row * n;
    float s = 0.f;
    for (int j = threadIdx.x; j < n; j += 256) s += ar[j];
    sh[threadIdx.x] = s;
    __syncthreads();
    for (int o = 128; o > 0; o >>= 1) {
        if (threadIdx.x < o) sh[threadIdx.x] += sh[threadIdx.x + o];
        __syncthreads();
    }
    if (threadIdx.x == 0) {
        float diag = ar[row];
        float fill = (diag == 0.0f) ? 2.0f : 0.0f;
        float deg = sh[0] + fill;
        float di = (deg > 0.f) ? (1.0f / sqrtf(deg)) : 0.f;
        dinv[row] = di;
        selfc[row] = di * di * fill;
    }
}

// Y = X@W ; Zcat = [bf16 hi | bf16 lo] of dinv*Y, 128 wide. 4 rows/block.
__global__ void k_xw_cat(const float* __restrict__ X, const float* __restrict__ W,
                         const float* __restrict__ dinv, float* __restrict__ Y,
                         __nv_bfloat16* __restrict__ Zc, int n, int cin, int c) {
    int j = threadIdx.x & 63;
    int i = blockIdx.x * 4 + (threadIdx.x >> 6);
    if (i >= n) return;
    __nv_bfloat16 hb = __float2bfloat16(0.f), lb = hb;
    if (j < c) {
        const float* xr = X + (size_t)i * cin;
        float acc = 0.f;
        for (int k = 0; k < cin; k += 4) {
            float4 xv = *reinterpret_cast<const float4*>(xr + k);
            acc = fmaf(xv.x, W[(size_t)k * c + j], acc);
            acc = fmaf(xv.y, W[(size_t)(k + 1) * c + j], acc);
            acc = fmaf(xv.z, W[(size_t)(k + 2) * c + j], acc);
            acc = fmaf(xv.w, W[(size_t)(k + 3) * c + j], acc);
        }
        Y[(size_t)i * c + j] = acc;
        float z = acc * dinv[i];
        hb = __float2bfloat16(z);
        lb = __float2bfloat16(z - __bfloat162float(hb));
    }
    Zc[(size_t)i * 128 + j] = hb;
    Zc[(size_t)i * 128 + 64 + j] = lb;
}

__global__ __launch_bounds__(256) void k_prop(const __nv_bfloat16* __restrict__ A,
                                              const __nv_bfloat16* __restrict__ Zc,
                                              float* __restrict__ P, int n, int KS) {
    __shared__ __nv_bfloat16 As[64][72];
    __shared__ __nv_bfloat16 Zs[64][136];
    int tid = threadIdx.x;
    int warp = tid >> 5;
    int wm = warp >> 2, wn = warp & 3;
    int m0 = blockIdx.x * 64;
    int ks = blockIdx.y;
    int chunk = n / KS;
    int kbeg = ks * chunk, kend = kbeg + chunk;

    wmma::fragment<wmma::accumulator, 16, 16, 16, float> acc[2][2];
#pragma unroll
    for (int i = 0; i < 2; i++)
#pragma unroll
        for (int j = 0; j < 2; j++) wmma::fill_fragment(acc[i][j], 0.f);

    for (int k0 = kbeg; k0 < kend; k0 += 64) {
#pragma unroll
        for (int l = 0; l < 2; l++) {
            int e = tid + 256 * l;
            int r = e >> 3, cg = (e & 7) * 8;
            *reinterpret_cast<uint4*>(&As[r][cg]) =
                *reinterpret_cast<const uint4*>(A + (size_t)(m0 + r) * n + k0 + cg);
        }
#pragma unroll
        for (int l = 0; l < 4; l++) {
            int e = tid + 256 * l;
            int r = e >> 4, cg = (e & 15) * 8;
            *reinterpret_cast<uint4*>(&Zs[r][cg]) =
                *reinterpret_cast<const uint4*>(Zc + (size_t)(k0 + r) * 128 + cg);
        }
        __syncthreads();
#pragma unroll
        for (int kk = 0; kk < 64; kk += 16) {
            wmma::fragment<wmma::matrix_a, 16, 16, 16, __nv_bfloat16, wmma::row_major> af[2];
            wmma::fragment<wmma::matrix_b, 16, 16, 16, __nv_bfloat16, wmma::row_major> bf[2];
#pragma unroll
            for (int i = 0; i < 2; i++)
                wmma::load_matrix_sync(af[i], &As[wm * 32 + 16 * i][kk], 72);
#pragma unroll
            for (int j = 0; j < 2; j++)
                wmma::load_matrix_sync(bf[j], &Zs[kk][wn * 32 + 16 * j], 136);
#pragma unroll
            for (int i = 0; i < 2; i++)
#pragma unroll
                for (int j = 0; j < 2; j++)
                    wmma::mma_sync(acc[i][j], af[i], bf[j], acc[i][j]);
        }
        __syncthreads();
    }
#pragma unroll
    for (int i = 0; i < 2; i++)
#pragma unroll
        for (int j = 0; j < 2; j++)
            wmma::store_matrix_sync(P + ((size_t)ks * n + m0 + wm * 32 + 16 * i) * 128 +
                                        wn * 32 + 16 * j,
                                    acc[i][j], 128, wmma::mem_row_major);
}

__global__ void k_prop_epi(const float* __restrict__ P, const float* __restrict__ Y,
                           const float* __restrict__ dinv, const float* __restrict__ selfc,
                           const float* __restrict__ bias, float* __restrict__ O,
                           int n, int c, int KS, int dorelu) {
    int t = blockIdx.x * 256 + threadIdx.x;
    if (t >= n * c) return;
    int i = t / c, j = t % c;
    float s = 0.f;
    for (int ks = 0; ks < KS; ks++) {
        const float* pr = P + ((size_t)ks * n + i) * 128;
        s += pr[j] + pr[64 + j];
    }
    float o = dinv[i] * s + selfc[i] * Y[t] + bias[j];
    if (dorelu) o = fmaxf(o, 0.f);
    O[t] = o;
}

// ---- fused gather + augment GEMM (WMMA, 3-stage cp.async) — used at L2 only ----
#define AUG_SMEM (3 * 2 * 128 * 72 * 2)
__global__ __launch_bounds__(256) void k_aug(const __nv_bfloat16* __restrict__ A,
                                             const __nv_bfloat16* __restrict__ AT,
                                             const int* __restrict__ permv,
                                             int K, int Nn, float* __restrict__ C,
                                             __nv_bfloat16* __restrict__ Ob,
                                             __nv_bfloat16* __restrict__ ObT,
                                             float* __restrict__ deg, int mode) {
    extern __shared__ char smraw[];
    __nv_bfloat16* AsB = reinterpret_cast<__nv_bfloat16*>(smraw);
    __nv_bfloat16* BsB = AsB + 3 * 128 * 72;
    __shared__ int spa[128], spb[128];
    const int LDK = 72;
    int tid = threadIdx.x;
    int warp = tid >> 5;
    int wm = warp >> 2, wn = warp & 3;
    int m0 = blockIdx.y * 128, n0 = blockIdx.x * 128;

    if (tid < 128) spa[tid] = permv[m0 + tid];
    else spb[tid - 128] = permv[n0 + tid - 128];
    __syncthreads();

    auto load_tiles = [&](int st, int k0) {
        __nv_bfloat16* as = AsB + st * 128 * LDK;
        __nv_bfloat16* bs = BsB + st * 128 * LDK;
#pragma unroll
        for (int l = 0; l < 4; l++) {
            int e = tid + 256 * l;
            int r = e >> 3, cg = (e & 7) * 8;
            cpa16(as + r * LDK + cg, A + (size_t)spa[r] * K + k0 + cg);
            cpa16(bs + r * LDK + cg, AT + (size_t)spb[r] * K + k0 + cg);
        }
        cpcommit();
    };

    wmma::fragment<wmma::accumulator, 16, 16, 16, float> acc[4][2];
#pragma unroll
    for (int i = 0; i < 4; i++)
#pragma unroll
        for (int j = 0; j < 2; j++) wmma::fill_fragment(acc[i][j], 0.f);

    int nIter = K / 64;
    load_tiles(0, 0);
    load_tiles(1, 64);
    for (int it = 0; it < nIter; it++) {
        int st = it % 3;
        cpwait1();
        __syncthreads();
        int k0 = it * 64;
        if (tid < 128) {
            int d = spa[tid] - k0;
            if (d >= 0 && d < 64) AsB[st * 128 * LDK + tid * LDK + d] = __float2bfloat16(1.f);
        } else {
            int r = tid - 128;
            int d = spb[r] - k0;
            if (d >= 0 && d < 64) BsB[st * 128 * LDK + r * LDK + d] = __float2bfloat16(1.f);
        }
        __syncthreads();
        if (it + 2 < nIter) load_tiles((it + 2) % 3, (it + 2) * 64);
        __nv_bfloat16* as = AsB + st * 128 * LDK;
        __nv_bfloat16* bs = BsB + st * 128 * LDK;
#pragma unroll
        for (int kk = 0; kk < 64; kk += 16) {
            wmma::fragment<wmma::matrix_a, 16, 16, 16, __nv_bfloat16, wmma::row_major> af[4];
            wmma::fragment<wmma::matrix_b, 16, 16, 16, __nv_bfloat16, wmma::col_major> bf[2];
#pragma unroll
            for (int i = 0; i < 4; i++)
                wmma::load_matrix_sync(af[i], as + (wm * 64 + 16 * i) * LDK + kk, LDK);
#pragma unroll
            for (int j = 0; j < 2; j++)
                wmma::load_matrix_sync(bf[j], bs + (wn * 32 + 16 * j) * LDK + kk, LDK);
#pragma unroll
            for (int i = 0; i < 4; i++)
#pragma unroll
                for (int j = 0; j < 2; j++)
                    wmma::mma_sync(acc[i][j], af[i], bf[j], acc[i][j]);
        }
    }
    __syncthreads();
    float* Cs = reinterpret_cast<float*>(smraw);
    const int LDC = 132;
#pragma unroll
    for (int i = 0; i < 4; i++)
#pragma unroll
        for (int j = 0; j < 2; j++)
            wmma::store_matrix_sync(Cs + (wm * 64 + 16 * i) * LDC + wn * 32 + 16 * j,
                                    acc[i][j], LDC, wmma::mem_row_major);
    __syncthreads();
    if (m0 == n0 && tid < 128) Cs[tid * LDC + tid] = 0.f;
    __syncthreads();
    if (mode == 0) {
#pragma unroll
        for (int l = 0; l < 16; l++) {
            int e = tid + 256 * l;
            int r = e >> 5, cq = (e & 31) * 4;
            float4 v;
            v.x = Cs[r * LDC + cq];
            v.y = Cs[r * LDC + cq + 1];
            v.z = Cs[r * LDC + cq + 2];
            v.w = Cs[r * LDC + cq + 3];
            *reinterpret_cast<float4*>(C + (size_t)(m0 + r) * Nn + n0 + cq) = v;
        }
    } else {
#pragma unroll
        for (int l = 0; l < 32; l++) {
            int e = tid + 256 * l;
            int r = e >> 6, c2 = (e & 63) * 2;
            *reinterpret_cast<__nv_bfloat162*>(Ob + (size_t)(m0 + r) * Nn + n0 + c2) =
                __floats2bfloat162_rn(Cs[r * LDC + c2], Cs[r * LDC + c2 + 1]);
        }
#pragma unroll
        for (int l = 0; l < 32; l++) {
            int e = tid + 256 * l;
            int c = e >> 6, r2 = (e & 63) * 2;
            *reinterpret_cast<__nv_bfloat162*>(ObT + (size_t)(n0 + c) * Nn + m0 + r2) =
                __floats2bfloat162_rn(Cs[r2 * LDC + c], Cs[(r2 + 1) * LDC + c]);
        }
        if (tid < 128) {
            float s = 0.f;
            for (int c = 0; c < 128; c++) s += Cs[tid * LDC + c];
            atomicAdd(&deg[m0 + tid], s);
        }
    }
}

// ---- fp32 SIMT path ----
__global__ void k_xw(const float* __restrict__ X, const float* __restrict__ W,
                     const float* __restrict__ dinv,
                     float* __restrict__ Y, float* __restrict__ Z,
                     int n, int cin, int cout) {
    int j = blockIdx.x * 32 + threadIdx.x;
    int i = blockIdx.y * 8 + threadIdx.y;
    if (i >= n || j >= cout) return;
    const float* xr = X + (size_t)i * cin;
    float acc = 0.f;
    for (int k = 0; k < cin; k++) acc = fmaf(xr[k], W[(size_t)k * cout + j], acc);
    Y[(size_t)i * cout + j] = acc;
    Z[(size_t)i * cout + j] = acc * dinv[i];
}

__global__ __launch_bounds__(256) void k_gcnmm_sp(
    const float* __restrict__ A, const float* __restrict__ Z,
    float* __restrict__ P, int n, int c, int KS) {
    __shared__ float As[32][65];
    __shared__ float Zs[32][32];
    int tid = threadIdx.x;
    int m0 = blockIdx.y * 64;
    int n0c = blockIdx.x * 32;
    int ks = blockIdx.z;
    int chunk = n / KS;
    int kbeg = ks * chunk, kend = kbeg + chunk;
    int r0 = tid >> 5, colt = tid & 31;
    float acc[8] = {0, 0, 0, 0, 0, 0, 0, 0};
    for (int k0 = kbeg; k0 < kend; k0 += 32) {
#pragma unroll
        for (int l = 0; l < 2; l++) {
            int e = tid + 256 * l;
            int row = e >> 3, qc = (e & 7) * 4;
            float4 v = *reinterpret_cast<const float4*>(A + (size_t)(m0 + row) * n + k0 + qc);
            As[qc + 0][row] = v.x; As[qc + 1][row] = v.y;
            As[qc + 2][row] = v.z; As[qc + 3][row] = v.w;
        }
        {
            int row = tid >> 3, qc = (tid & 7) * 4;
            int gk = k0 + row;
#pragma unroll
            for (int u = 0; u < 4; u++) {
                int gc = n0c + qc + u;
                Zs[row][qc + u] = (gc < c) ? Z[(size_t)gk * c + gc] : 0.f;
            }
        }
        __syncthreads();
#pragma unroll
        for (int k = 0; k < 32; k++) {
            float zv = Zs[k][colt];
#pragma unroll
            for (int u = 0; u < 8; u++) acc[u] = fmaf(As[k][r0 + 8 * u], zv, acc[u]);
        }
        __syncthreads();
    }
    int gc = n0c + colt;
    if (gc < c) {
#pragma unroll
        for (int u = 0; u < 8; u++) {
            int gi = m0 + r0 + 8 * u;
            P[((size_t)ks * n + gi) * c + gc] = acc[u];
        }
    }
}

__global__ void k_gcn_epi(const float* __restrict__ P, const float* __restrict__ Y,
                          const float* __restrict__ dinv, const float* __restrict__ selfc,
                          const float* __restrict__ bias, float* __restrict__ O,
                          int n, int c, int KS, int dorelu) {
    int t = blockIdx.x * 256 + threadIdx.x;
    if (t >= n * c) return;
    int i = t / c, j = t % c;
    float s = 0.f;
    size_t stride = (size_t)n * c;
    for (int ks = 0; ks < KS; ks++) s += P[ks * stride + t];
    float o = dinv[i] * s + selfc[i] * Y[t] + bias[j];
    if (dorelu) o = fmaxf(o, 0.f);
    O[t] = o;
}

__global__ void k_grow_f32(const float* __restrict__ A, int n,
                           const int* __restrict__ perm, int ksel,
                           float* __restrict__ Br) {
    size_t t = (size_t)blockIdx.x * 256 + threadIdx.x;
    if (t >= (size_t)ksel * n) return;
    int r = t / n, k = t % n;
    int pr = perm[r];
    Br[t] = (k == pr) ? 1.0f : A[(size_t)pr * n + k];
}

__global__ void k_gcol_f32(const float* __restrict__ A, int n,
                           const int* __restrict__ perm, int ksel,
                           float* __restrict__ Bc) {
    size_t t = (size_t)blockIdx.x * 256 + threadIdx.x;
    if (t >= (size_t)n * ksel) return;
    int k = t / ksel, c = t % ksel;
    int pc = perm[c];
    Bc[t] = (k == pc) ? 1.0f : A[(size_t)k * n + pc];
}

__global__ __launch_bounds__(256) void k_gemm64(const float* __restrict__ Br,
                                                const float* __restrict__ Bc,
                                                float* __restrict__ C, int K, int Nn) {
    __shared__ float As[16][65];
    __shared__ float Bs[16][65];
    int tid = threadIdx.x;
    int m0 = blockIdx.y * 64, n0 = blockIdx.x * 64;
    int ty = tid >> 4, tx = tid & 15;
    float acc[4][4] = {};
    for (int k0 = 0; k0 < K; k0 += 16) {
#pragma unroll
        for (int l = 0; l < 4; l++) {
            int e = tid + 256 * l;
            int row = e >> 4, kk = e & 15;
            As[kk][row] = Br[(size_t)(m0 + row) * K + k0 + kk];
        }
#pragma unroll
        for (int l = 0; l < 4; l++) {
            int e = tid + 256 * l;
            int row = e >> 6, col = e & 63;
            Bs[row][col] = Bc[(size_t)(k0 + row) * Nn + n0 + col];
        }
        __syncthreads();
#pragma unroll
        for (int kk = 0; kk < 16; kk++) {
            float a[4], b[4];
#pragma unroll
            for (int i = 0; i < 4; i++) a[i] = As[kk][ty * 4 + i];
#pragma unroll
            for (int j = 0; j < 4; j++) b[j] = Bs[kk][tx * 4 + j];
#pragma unroll
            for (int i = 0; i < 4; i++)
#pragma unroll
                for (int j = 0; j < 4; j++) acc[i][j] = fmaf(a[i], b[j], acc[i][j]);
        }
        __syncthreads();
    }
#pragma unroll
    for (int i = 0; i < 4; i++)
#pragma unroll
        for (int j = 0; j < 4; j++)
            C[(size_t)(m0 + ty * 4 + i) * Nn + n0 + tx * 4 + j] = acc[i][j];
}

__global__ void k_zerodiag(float* __restrict__ C, int n) {
    int i = blockIdx.x * 256 + threadIdx.x;
    if (i < n) C[(size_t)i * n + i] = 0.f;
}

__global__ void k_score(const float* __restrict__ X, const float* __restrict__ w,
                        int n, int c, float* __restrict__ score) {
    int row = blockIdx.x;
    __shared__ float sh[128];
    const float* xr = X + (size_t)row * c;
    float wsq = 0.f, dot = 0.f;
    for (int k = threadIdx.x; k < c; k += 128) {
        float wv = w[k];
        wsq += wv * wv;
        dot += xr[k] * wv;
    }
    sh[threadIdx.x] = wsq;
    __syncthreads();
    for (int o = 64; o > 0; o >>= 1) {
        if (threadIdx.x < o) sh[threadIdx.x] += sh[threadIdx.x + o];
        __syncthreads();
    }
    float wn = sh[0];
    __syncthreads();
    sh[threadIdx.x] = dot;
    __syncthreads();
    for (int o = 64; o > 0; o >>= 1) {
        if (threadIdx.x < o) sh[threadIdx.x] += sh[threadIdx.x + o];
        __syncthreads();
    }
    if (threadIdx.x == 0) score[row] = tanhf(sh[0] / sqrtf(wn));
}

__global__ void k_rank(const float* __restrict__ score, int n, int k,
                       int* __restrict__ perm, float* __restrict__ vals,
                       int* __restrict__ inv) {
    int i = blockIdx.x * 256 + threadIdx.x;
    if (i >= n) return;
    float si = score[i];
    const float4* s4 = reinterpret_cast<const float4*>(score);
    int rank = 0;
    for (int j4 = 0; j4 < n / 4; j4++) {
        float4 s = s4[j4];
        int j = j4 * 4;
        rank += (s.x > si) || (s.x == si && j < i);
        rank += (s.y > si) || (s.y == si && j + 1 < i);
        rank += (s.z > si) || (s.z == si && j + 2 < i);
        rank += (s.w > si) || (s.w == si && j + 3 < i);
    }
    if (rank < k) {
        perm[rank] = i;
        vals[rank] = si;
        inv[i] = rank;
    } else {
        inv[i] = -1;
    }
}

__global__ void k_gatherx(const float* __restrict__ X, int c,
                          const int* __restrict__ perm, const float* __restrict__ vals,
                          int k, float* __restrict__ O) {
    int t = blockIdx.x * 256 + threadIdx.x;
    if (t >= k * c) return;
    int r = t / c, j = t % c;
    O[t] = X[(size_t)perm[r] * c + j] * vals[r];
}

__global__ void k_unpool(const float* __restrict__ R, int n, int c,
                         const float* __restrict__ X, int sx,
                         const int* __restrict__ inv, float* __restrict__ O) {
    int t = blockIdx.x * 256 + threadIdx.x;
    int tot = n * 2 * c;
    if (t >= tot) return;
    int i = t / (2 * c), j = t % (2 * c);
    float v;
    if (j < c) {
        v = R[(size_t)i * c + j];
    } else {
        int r = inv[i];
        v = (r >= 0) ? X[(size_t)r * sx + (j - c)] : 0.f;
    }
    O[t] = v;
}

__global__ void k_softmax(const float* __restrict__ X, float* __restrict__ O, int n, int c) {
    int i = blockIdx.x * 256 + threadIdx.x;
    if (i >= n) return;
    const float* xr = X + (size_t)i * c;
    float m = -1e30f;
    for (int j = 0; j < c; j++) m = fmaxf(m, xr[j]);
    float s = 0.f;
    for (int j = 0; j < c; j++) s += expf(xr[j] - m);
    float inv = 1.0f / s;
    for (int j = 0; j < c; j++) O[(size_t)i * c + j] = expf(xr[j] - m) * inv;
}

// ---------------- host orchestration ----------------

struct Ptrs {
    float *y, *z, *P;
    __nv_bfloat16* zc;
};

static void gcn_tc(const __nv_bfloat16* Ab, int n, const float* xin, int cin,
                   const float* W, const float* b, int c, bool relu, float* out,
                   const float* dinv, const float* selfc, const Ptrs& q) {
    const int KS = 8;
    k_xw_cat<<<(n + 3) / 4, 256>>>(xin, W, dinv, q.y, q.zc, n, cin, c);
    k_prop<<<dim3(n / 64, KS), 256>>>(Ab, q.zc, q.P, n, KS);
    k_prop_epi<<<(n * c + 255) / 256, 256>>>(q.P, q.y, dinv, selfc, b, out, n, c, KS, relu ? 1 : 0);
}

static void gcn_f32(const float* A, int n, const float* xin, int cin,
                    const float* W, const float* b, int cout, bool relu, float* out,
                    const float* dinv, const float* selfc, const Ptrs& q) {
    const int KS = 8;
    dim3 bx(32, 8);
    dim3 gx((cout + 31) / 32, (n + 7) / 8);
    k_xw<<<gx, bx>>>(xin, W, dinv, q.y, q.z, n, cin, cout);
    dim3 g2((cout + 31) / 32, n / 64, KS);
    k_gcnmm_sp<<<g2, 256>>>(A, q.z, q.P, n, cout, KS);
    k_gcn_epi<<<(n * cout + 255) / 256, 256>>>(q.P, q.y, dinv, selfc, b, out, n, cout, KS, relu ? 1 : 0);
}

// sparse GCN on original graph (n = 4096)
static void gcn_sparse(const int* offD, const int* inl, const int* selfn,
                       const float* xin, int cin, const float* W, const float* b,
                       int cout, bool relu, float* out,
                       const float* dinv, const float* selfc, const Ptrs& q) {
    dim3 bx(32, 8);
    dim3 gx((cout + 31) / 32, (N0 + 7) / 8);
    k_xw<<<gx, bx>>>(xin, W, dinv, q.y, q.z, N0, cin, cout);
    k_sprop<<<N0, 64>>>(offD, inl, selfn, q.z, q.y, dinv, selfc, b, out, cout, relu ? 1 : 0);
}

extern "C" void kernel_launch(void* const* d_in, const int* in_sizes, int n_in,
                              void* d_out, int out_size) {
    const float* x = (const float*)d_in[0];
    const int* ei = (const int*)d_in[1];
    const float *Wd[5], *bd[5], *p[4], *Wu[4], *bu[4];
    for (int i = 0; i < 5; i++) { Wd[i] = (const float*)d_in[2 + 2 * i]; bd[i] = (const float*)d_in[3 + 2 * i]; }
    for (int i = 0; i < 4; i++) p[i] = (const float*)d_in[12 + i];
    for (int i = 0; i < 4; i++) { Wu[i] = (const float*)d_in[16 + 2 * i]; bu[i] = (const float*)d_in[17 + 2 * i]; }
    const float* Wo = (const float*)d_in[24];
    const float* bo = (const float*)d_in[25];

    static bool attrset = false;
    if (!attrset) {
        cudaFuncSetAttribute(k_aug, cudaFuncAttributeMaxDynamicSharedMemorySize, AUG_SMEM);
        attrset = true;
    }

    __nv_bfloat16 *A1b, *A1tb;
    float *C1, *A2, *A3, *A4, *xs0, *xs1, *xs2, *xs3, *xa, *xb;
    float *Brf, *Bcf, *score, *vals, *deg1;
    float *di0, *sf0, *di1, *sf1, *di2, *sf2, *di3, *sf3, *di4, *sf4;
    int *pm0, *pm1, *pm2, *pm3;
    int *iv0, *iv1, *iv2, *iv3;
    int *call, *selfn, *csrc, *cdst, *offS, *offD, *headS, *headD, *outl, *inl;
    Ptrs q;
    cudaGetSymbolAddress((void**)&A1b, dA1b);
    cudaGetSymbolAddress((void**)&A1tb, dA1tb);
    cudaGetSymbolAddress((void**)&C1, dC1);
    cudaGetSymbolAddress((void**)&A2, dA2);
    cudaGetSymbolAddress((void**)&A3, dA3);
    cudaGetSymbolAddress((void**)&A4, dA4);
    cudaGetSymbolAddress((void**)&Brf, dBrf);
    cudaGetSymbolAddress((void**)&Bcf, dBcf);
    cudaGetSymbolAddress((void**)&q.P, dP);
    cudaGetSymbolAddress((void**)&xs0, dxs0);
    cudaGetSymbolAddress((void**)&xs1, dxs1);
    cudaGetSymbolAddress((void**)&xs2, dxs2);
    cudaGetSymbolAddress((void**)&xs3, dxs3);
    cudaGetSymbolAddress((void**)&xa, dxa);
    cudaGetSymbolAddress((void**)&xb, dxb);
    cudaGetSymbolAddress((void**)&q.y, dybuf);
    cudaGetSymbolAddress((void**)&q.z, dzbuf);
    q.zc = (__nv_bfloat16*)q.z;
    cudaGetSymbolAddress((void**)&deg1, ddeg1);
    cudaGetSymbolAddress((void**)&di0, dinv0); cudaGetSymbolAddress((void**)&sf0, dself0);
    cudaGetSymbolAddress((void**)&di1, dinv1); cudaGetSymbolAddress((void**)&sf1, dself1);
    cudaGetSymbolAddress((void**)&di2, dinv2); cudaGetSymbolAddress((void**)&sf2, dself2);
    cudaGetSymbolAddress((void**)&di3, dinv3); cudaGetSymbolAddress((void**)&sf3, dself3);
    cudaGetSymbolAddress((void**)&di4, dinv4); cudaGetSymbolAddress((void**)&sf4, dself4);
    cudaGetSymbolAddress((void**)&score, dscorev);
    cudaGetSymbolAddress((void**)&vals, dvalsv);
    cudaGetSymbolAddress((void**)&pm0, dperm0);
    cudaGetSymbolAddress((void**)&pm1, dperm1);
    cudaGetSymbolAddress((void**)&pm2, dperm2);
    cudaGetSymbolAddress((void**)&pm3, dperm3);
    cudaGetSymbolAddress((void**)&iv0, dinvi0);
    cudaGetSymbolAddress((void**)&iv1, dinvi1);
    cudaGetSymbolAddress((void**)&iv2, dinvi2);
    cudaGetSymbolAddress((void**)&iv3, dinvi3);
    cudaGetSymbolAddress((void**)&call, dcall);
    cudaGetSymbolAddress((void**)&selfn, dselfn);
    cudaGetSymbolAddress((void**)&csrc, dcsrc);
    cudaGetSymbolAddress((void**)&cdst, dcdst);
    cudaGetSymbolAddress((void**)&offS, doffS);
    cudaGetSymbolAddress((void**)&offD, doffD);
    cudaGetSymbolAddress((void**)&headS, dheadS);
    cudaGetSymbolAddress((void**)&headD, dheadD);
    cudaGetSymbolAddress((void**)&outl, doutl);
    cudaGetSymbolAddress((void**)&inl, dinl);

    // ---- build sparse adjacency structures ----
    cudaMemsetAsync(call, 0, 4096 * sizeof(int));
    cudaMemsetAsync(selfn, 0, 4096 * sizeof(int));
    cudaMemsetAsync(csrc, 0, 4096 * sizeof(int));
    cudaMemsetAsync(cdst, 0, 4096 * sizeof(int));
    cudaMemsetAsync(deg1, 0, 2048 * sizeof(float));
    cudaMemsetAsync(C1, 0, (size_t)2048 * 2048 * sizeof(float));
    k_ecnt<<<EDG / 256, 256>>>(ei, call, selfn, csrc, cdst);
    k_scan<<<2, 1024>>>(csrc, offS, headS, cdst, offD, headD);
    k_fill<<<EDG / 256, 256>>>(ei, headS, headD, outl, inl);
    k_degfin0<<<N0 / 256, 256>>>(call, selfn, N0, di0, sf0);

    // GCN0 (sparse): [4096,128] -> [4096,32], relu
    gcn_sparse(offD, inl, selfn, x, 128, Wd[0], bd[0], 32, true, xs0, di0, sf0, q);

    // ---- level 1: sparse path-pair augment -> C1 -> bf16 A1 + A1^T + deg ----
    k_score<<<4096, 128>>>(xs0, p[0], 4096, 32, score);
    k_rank<<<16, 256>>>(score, 4096, 2048, pm0, vals, iv0);
    k_gatherx<<<(2048 * 32 + 255) / 256, 256>>>(xs0, 32, pm0, vals, 2048, xa);
    k_pairs<<<4096, 256>>>(offS, outl, offD, inl, iv0, C1, 2048);
    k_addA<<<EDG / 256, 256>>>(ei, iv0, C1, 2048);
    k_a1fin<<<dim3(2048 / 32, 2048 / 32), dim3(32, 8)>>>(C1, A1b, A1tb, deg1, 2048);
    k_degfin<<<2048 / 256, 256>>>(A1b, deg1, 2048, di1, sf1);
    gcn_tc(A1b, 2048, xa, 32, Wd[1], bd[1], 64, true, xs1, di1, sf1, q);

    // ---- level 2: dense fused gather+augment -> fp32 A2 ----
    k_score<<<2048, 128>>>(xs1, p[1], 2048, 64, score);
    k_rank<<<8, 256>>>(score, 2048, 1024, pm1, vals, iv1);
    k_gatherx<<<(1024 * 64 + 255) / 256, 256>>>(xs1, 64, pm1, vals, 1024, xa);
    k_aug<<<dim3(8, 8), 256, AUG_SMEM>>>(A1b, A1tb, pm1, 2048, 1024,
                                         A2, nullptr, nullptr, nullptr, 0);
    k_deg<<<1024, 256>>>(A2, 1024, di2, sf2);
    gcn_f32(A2, 1024, xa, 64, Wd[2], bd[2], 128, true, xs2, di2, sf2, q);

    // ---- level 3 (fp32) ----
    k_score<<<1024, 128>>>(xs2, p[2], 1024, 128, score);
    k_rank<<<4, 256>>>(score, 1024, 512, pm2, vals, iv2);
    k_gatherx<<<(512 * 128 + 255) / 256, 256>>>(xs2, 128, pm2, vals, 512, xa);
    k_grow_f32<<<(512 * 1024 + 255) / 256, 256>>>(A2, 1024, pm2, 512, Brf);
    k_gcol_f32<<<(1024 * 512 + 255) / 256, 256>>>(A2, 1024, pm2, 512, Bcf);
    k_gemm64<<<dim3(8, 8), 256>>>(Brf, Bcf, A3, 1024, 512);
    k_zerodiag<<<2, 256>>>(A3, 512);
    k_deg<<<512, 256>>>(A3, 512, di3, sf3);
    gcn_f32(A3, 512, xa, 128, Wd[3], bd[3], 256, true, xs3, di3, sf3, q);

    // ---- level 4 (fp32) ----
    k_score<<<512, 128>>>(xs3, p[3], 512, 256, score);
    k_rank<<<2, 256>>>(score, 512, 256, pm3, vals, iv3);
    k_gatherx<<<(256 * 256 + 255) / 256, 256>>>(xs3, 256, pm3, vals, 256, xa);
    k_grow_f32<<<(256 * 512 + 255) / 256, 256>>>(A3, 512, pm3, 256, Brf);
    k_gcol_f32<<<(512 * 256 + 255) / 256, 256>>>(A3, 512, pm3, 256, Bcf);
    k_gemm64<<<dim3(4, 4), 256>>>(Brf, Bcf, A4, 512, 256);
    k_zerodiag<<<1, 256>>>(A4, 256);
    k_deg<<<256, 256>>>(A4, 256, di4, sf4);
    gcn_f32(A4, 256, xa, 256, Wd[4], bd[4], 512, true, xb, di4, sf4, q);

    // ---- up path (fused unpool) ----
    k_unpool<<<(512 * 512 + 255) / 256, 256>>>(xs3, 512, 256, xb, 512, iv3, xa);
    gcn_f32(A3, 512, xa, 512, Wu[0], bu[0], 256, true, xb, di3, sf3, q);

    k_unpool<<<(1024 * 256 + 255) / 256, 256>>>(xs2, 1024, 128, xb, 256, iv2, xa);
    gcn_f32(A2, 1024, xa, 256, Wu[1], bu[1], 128, true, xb, di2, sf2, q);

    k_unpool<<<(2048 * 128 + 255) / 256, 256>>>(xs1, 2048, 64, xb, 128, iv1, xa);
    gcn_tc(A1b, 2048, xa, 128, Wu[2], bu[2], 64, true, xb, di1, sf1, q);

    k_unpool<<<(4096 * 64 + 255) / 256, 256>>>(xs0, 4096, 32, xb, 64, iv0, xa);
    gcn_sparse(offD, inl, selfn, xa, 64, Wu[3], bu[3], 32, false, xb, di0, sf0, q);

    // ---- final GCN (sparse) + softmax ----
    gcn_sparse(offD, inl, selfn, xb, 32, Wo, bo, 37, false, xa, di0, sf0, q);
    k_softmax<<<16, 256>>>(xa, (float*)d_out, 4096, 37);
}